// round 10
// baseline (speedup 1.0000x reference)
#include <cuda_runtime.h>
#include <cuda_bf16.h>
#include <math.h>

#define S 512
#define B 64
#define H 512
#define D 512
#define G3 1536
#define NBLK 128

typedef unsigned u32;
typedef unsigned long long ull;
typedef __nv_bfloat16 bf16;

// ---------------- device-global scratch (allocation-free rule) ----------------
__device__ float g_gi0[(size_t)2 * S * B * G3];          // fp32 gi0 [dir][t][b][3H]
__device__ u32   g_xfrag[2][S][16384];                   // x in A-frag layout [plane][s]
__device__ u32   g_wfrag[2][2][393216];                  // Wih0 in B-frag layout [plane][dir]
__device__ float g_h0f[2][2][B * H];                     // [parity][dir]
__device__ float g_h1f[2][2][B * H];
// h planes in mma-frag layout: u32 idx = kblk*512 + mtile*128 + lane*4 + reg
__device__ u32   g_h0p[2][2][2][16384];                  // [parity][dir][plane]
__device__ u32   g_h1p[2][2][2][16384];
// two-level barrier state (padded 256B apart -> distinct L2 lines)
__device__ u32   g_grp[2][8][64];
__device__ u32   g_root[2][64];
__device__ u32   g_rel[2][64];

// ---------------- helpers ----------------
__device__ __forceinline__ void split_bf(float v, bf16& hi, bf16& lo) {
    hi = __float2bfloat16(v);
    lo = __float2bfloat16(v - __bfloat162float(hi));
}
__device__ __forceinline__ u32 pack2(bf16 a, bf16 b) {
    return (u32)__bfloat16_as_ushort(a) | ((u32)__bfloat16_as_ushort(b) << 16);
}
__device__ __forceinline__ float sigm(float x) { return 1.0f / (1.0f + expf(-x)); }

// byte offset of h value (batch b, hidden k) inside a frag-layout plane
__device__ __forceinline__ int frag_byte(int b, int k) {
    int kblk = k >> 4, c = k & 15, mt = b >> 4, r = b & 15;
    int lane = (r & 7) * 4 + ((c & 7) >> 1);
    int reg  = (r >> 3) + 2 * (c >> 3);
    return ((kblk * 512 + mt * 128 + lane * 4 + reg) << 2) + ((c & 1) << 1);
}

__device__ __forceinline__ void mma16816(float* d, const u32* a, u32 b0, u32 b1) {
    asm volatile("mma.sync.aligned.m16n8k16.row.col.f32.bf16.bf16.f32 "
                 "{%0,%1,%2,%3},{%4,%5,%6,%7},{%8,%9},{%0,%1,%2,%3};"
                 : "+f"(d[0]), "+f"(d[1]), "+f"(d[2]), "+f"(d[3])
                 : "r"(a[0]), "r"(a[1]), "r"(a[2]), "r"(a[3]), "r"(b0), "r"(b1));
}
__device__ __forceinline__ void cp16(void* smem_dst, const void* gsrc) {
    u32 s = (u32)__cvta_generic_to_shared(smem_dst);
    asm volatile("cp.async.cg.shared.global [%0], [%1], 16;" :: "r"(s), "l"(gsrc));
}

// ---------------- conv_xw: input -> A-frags, Wih0 -> B-frags ----------------
__global__ void conv_xw(const float* __restrict__ x,
                        const float* __restrict__ wf, const float* __restrict__ wb) {
    if (blockIdx.x < 16384) {
        size_t i = ((size_t)blockIdx.x * 256 + threadIdx.x) * 4;   // over B*S*D
        float4 v = *(const float4*)&x[i];
        int b  = (int)(i >> 18);
        int s  = (int)(i >> 9) & 511;
        int k0 = (int)i & 511;
        bf16 h0, l0, h1, l1, h2, l2, h3, l3;
        split_bf(v.x, h0, l0); split_bf(v.y, h1, l1);
        split_bf(v.z, h2, l2); split_bf(v.w, h3, l3);
        int kblk = k0 >> 4, c = k0 & 15, r = b & 15, mt = b >> 4;
        int lane = (r & 7) * 4 + ((c & 7) >> 1);
        int reg  = (r >> 3) + 2 * (c >> 3);
        int idx  = kblk * 512 + mt * 128 + lane * 4 + reg;
        g_xfrag[0][s][idx]     = pack2(h0, h1);
        g_xfrag[0][s][idx + 4] = pack2(h2, h3);
        g_xfrag[1][s][idx]     = pack2(l0, l1);
        g_xfrag[1][s][idx + 4] = pack2(l2, l3);
    } else {
        size_t j = ((size_t)(blockIdx.x - 16384) * 256 + threadIdx.x) * 4;  // over 2*G3*D
        int d = j >= (size_t)G3 * D;
        size_t off = d ? j - (size_t)G3 * D : j;
        const float* src = d ? wb : wf;
        float4 v = *(const float4*)&src[off];
        int n  = (int)(off >> 9);
        int k0 = (int)off & 511;
        bf16 h0, l0, h1, l1, h2, l2, h3, l3;
        split_bf(v.x, h0, l0); split_bf(v.y, h1, l1);
        split_bf(v.z, h2, l2); split_bf(v.w, h3, l3);
        int kblk = k0 >> 4;
        int lane = (n & 7) * 4 + ((k0 & 7) >> 1);
        int reg  = (k0 >> 3) & 1;
        int nblk = n >> 3;
        int base = ((kblk * 192 + nblk) * 32 + lane) * 2 + reg;
        g_wfrag[0][d][base]     = pack2(h0, h1);
        g_wfrag[0][d][base + 2] = pack2(h2, h3);
        g_wfrag[1][d][base]     = pack2(l0, l1);
        g_wfrag[1][d][base + 2] = pack2(l2, l3);
    }
}

// ---------------- init: hidden states (fp32 + frag planes) + barrier reset ----------------
__global__ void init_h(const float* __restrict__ enc) {
    if (blockIdx.x == 0) {
        if (threadIdx.x < 16) g_grp[threadIdx.x >> 3][threadIdx.x & 7][0] = 0;
        if (threadIdx.x < 2) { g_root[threadIdx.x][0] = 0; g_rel[threadIdx.x][0] = 0; }
    }
    int idx = blockIdx.x * blockDim.x + threadIdx.x;   // 131072
    int layer = idx >> 16;
    int rem = idx & 65535;
    int dir = rem >> 15;
    int rem2 = rem & 32767;
    int b = rem2 >> 9;
    int n = rem2 & 511;
    float v = enc[(layer * B + b) * (2 * H) + dir * H + n];
    bf16 hi, lo; split_bf(v, hi, lo);
    int off = frag_byte(b, n);
    if (layer == 0) {
        g_h0f[0][dir][b * H + n] = v;
        *(bf16*)((char*)g_h0p[0][dir][0] + off) = hi;
        *(bf16*)((char*)g_h0p[0][dir][1] + off) = lo;
    } else {
        g_h1f[0][dir][b * H + n] = v;
        *(bf16*)((char*)g_h1p[0][dir][0] + off) = hi;
        *(bf16*)((char*)g_h1p[0][dir][1] + off) = lo;
    }
}

// ---------------- gi0 = input @ Wih0^T + bih0: frag-direct, no smem ----------------
__global__ void __launch_bounds__(256, 2)
gemm_gi0(const float* __restrict__ bf_, const float* __restrict__ bb_) {
    int s  = blockIdx.x;
    int nb = blockIdx.y;
    int d  = blockIdx.z;
    const float* bias = d ? bb_ : bf_;

    int tid = threadIdx.x;
    int w = tid >> 5, l = tid & 31;
    int mtile = w & 3, m0 = mtile * 16, nh = w >> 2;
    int moff  = mtile * 128 + l * 4;
    int nbase = nb * 8 + nh * 4;

    const u32* Xh = g_xfrag[0][s];
    const u32* Xl = g_xfrag[1][s];
    const u32* Wh = g_wfrag[0][d];
    const u32* Wl = g_wfrag[1][d];

    float acc[4][4];
#pragma unroll
    for (int nt = 0; nt < 4; nt++) { acc[nt][0] = acc[nt][1] = acc[nt][2] = acc[nt][3] = 0.f; }

    u32 a[3][2][4];
    u32 b[3][2][4][2];

    auto loadK = [&](int c, int slot) {
        uint4 v;
        v = __ldcg((const uint4*)(Xh + c * 512 + moff));
        a[slot][0][0] = v.x; a[slot][0][1] = v.y; a[slot][0][2] = v.z; a[slot][0][3] = v.w;
        v = __ldcg((const uint4*)(Xl + c * 512 + moff));
        a[slot][1][0] = v.x; a[slot][1][1] = v.y; a[slot][1][2] = v.z; a[slot][1][3] = v.w;
#pragma unroll
        for (int nt = 0; nt < 4; nt++) {
            int idx = ((c * 192 + nbase + nt) * 32 + l) * 2;
            uint2 u = __ldcg((const uint2*)(Wh + idx));
            b[slot][0][nt][0] = u.x; b[slot][0][nt][1] = u.y;
            uint2 w2 = __ldcg((const uint2*)(Wl + idx));
            b[slot][1][nt][0] = w2.x; b[slot][1][nt][1] = w2.y;
        }
    };

    loadK(0, 0);
    loadK(1, 1);
#pragma unroll
    for (int c = 0; c < 32; c++) {
        int slot = c % 3;
        if (c < 30) loadK(c + 2, (c + 2) % 3);
#pragma unroll
        for (int nt = 0; nt < 4; nt++) {
            mma16816(acc[nt], a[slot][0], b[slot][0][nt][0], b[slot][0][nt][1]);
            mma16816(acc[nt], a[slot][1], b[slot][0][nt][0], b[slot][0][nt][1]);
            mma16816(acc[nt], a[slot][0], b[slot][1][nt][0], b[slot][1][nt][1]);
        }
    }

#pragma unroll
    for (int nt = 0; nt < 4; nt++) {
        int col = nb * 64 + nh * 32 + nt * 8 + 2 * (l & 3);
        float2 bi = *(const float2*)&bias[col];
        int b0 = m0 + (l >> 2);
        float2 v0 = make_float2(acc[nt][0] + bi.x, acc[nt][1] + bi.y);
        float2 v1 = make_float2(acc[nt][2] + bi.x, acc[nt][3] + bi.y);
        *(float2*)&g_gi0[(((size_t)d * S + s) * B + b0) * G3 + col] = v0;
        *(float2*)&g_gi0[(((size_t)d * S + s) * B + b0 + 8) * G3 + col] = v1;
    }
}

// ---------------- per-dir grid barrier: 2-level arrival, single-word spin ----------------
__device__ __forceinline__ void grid_bar(int dir, int grp, unsigned target) {
    __syncthreads();
    if (threadIdx.x == 0) {
        __threadfence();
        bool released = false;
        unsigned v = atomicAdd(&g_grp[dir][grp][0], 1u) + 1u;
        if (v == target * 8u) {
            unsigned r = atomicAdd(&g_root[dir][0], 1u) + 1u;
            if (r == target * 8u) {
                asm volatile("st.release.gpu.u32 [%0], %1;"
                             :: "l"(&g_rel[dir][0]), "r"(target) : "memory");
                released = true;
            }
        }
        if (!released) {
            unsigned r;
            do {
                asm volatile("ld.acquire.gpu.u32 %0, [%1];" : "=r"(r) : "l"(&g_rel[dir][0]) : "memory");
            } while (r < target);
        }
    }
    __syncthreads();
}

// ---------------- persistent recurrence kernel ----------------
// grid 128 (2 dir x 64 hgroups of 8), 512 thr = 16 warps (mtile x4, ksub x4).
// smem: WS 152064 | G0 19968 | G1 19968 | GI0S 6144 = 198144 B
__global__ void __launch_bounds__(512, 1)
gru_persist(const float* __restrict__ Wih_f, const float* __restrict__ Wih_b,
            const float* __restrict__ Whh_f, const float* __restrict__ Whh_b,
            const float* __restrict__ bih_f, const float* __restrict__ bih_b,
            const float* __restrict__ bhh_f, const float* __restrict__ bhh_b,
            float* __restrict__ out) {
    extern __shared__ char smem[];
    u32*  WS    = (u32*)smem;                    // [(mat*2+plane)*24 + n][264]
    float* G0   = (float*)(smem + 152064);       // partials ksub{0,1}: GA/GB/GC
    float* G1   = (float*)(smem + 172032);       // partials ksub{2,3}
    float* GI0S = (float*)(smem + 192000);       // [64][24]

    const int tid = threadIdx.x;
    const int bid = blockIdx.x;
    const int dir = bid >> 6;
    const int hb  = (bid & 63) * 8;
    const int w = tid >> 5, l = tid & 31;
    const int mtile = w & 3, m0 = mtile * 16, ksub = w >> 2;

    const float* Wih = dir ? Wih_b : Wih_f;
    const float* Whh = dir ? Whh_b : Whh_f;
    const float* bih = dir ? bih_b : bih_f;
    const float* bhh = dir ? bhh_b : bhh_f;
    const float* bhh0 = bhh;
    const float* bi1 = bih + G3;
    const float* bh1 = bhh + G3;

    // ---- one-time weight staging: bf16 hi/lo, (k,k+8)-interleaved u32 pairs ----
    {
        const float* Wmat[3] = { Whh, Wih + (size_t)G3 * D, Whh + (size_t)G3 * H };
#pragma unroll 4
        for (int i = 0; i < 36; i++) {
            int item = tid + 512 * i;            // < 18432
            int m3 = item / 6144;
            int rem = item - m3 * 6144;
            int n = rem >> 8;
            int k2 = rem & 255;
            int grow = (n >> 3) * H + hb + (n & 7);
            float2 v = *(const float2*)(Wmat[m3] + (size_t)grow * 512 + 2 * k2);
            bf16 h0, l0, h1, l1;
            split_bf(v.x, h0, l0); split_bf(v.y, h1, l1);
            int j = k2 & 7;
            int col = ((k2 >> 3) << 3) + ((j & 3) << 1) + (j >> 2);
            WS[((m3 * 2 + 0) * 24 + n) * 264 + col] = pack2(h0, h1);
            WS[((m3 * 2 + 1) * 24 + n) * 264 + col] = pack2(l0, l1);
        }
    }

    // ---- register-carried previous-h for this thread's (mm, j) element ----
    const int emm = tid & 63;       // batch
    const int ej  = tid >> 6;       // row within hidden slice
    const int erow = hb + ej;
    float hprev0 = g_h0f[0][dir][emm * H + erow];
    float hprev1 = g_h1f[0][dir][emm * H + erow];

    const int rowoff = (l >> 2) * 264 + 2 * (l & 3) + ksub * 8;
    const int fbase  = mtile * 128 + l * 4;

    for (int p = 0; p <= S; p++) {
        const u32* Apl[4] = { g_h0p[p & 1][dir][0], g_h0p[p & 1][dir][1],
                              g_h1p[(p + 1) & 1][dir][0], g_h1p[(p + 1) & 1][dir][1] };

        // gi0 prefetch (used in L0 epilogue)
        if (p < S) {
            int tt0 = dir ? (S - 1 - p) : p;
            const float* gi = &g_gi0[((size_t)dir * S + tt0) * B * G3];
            if (tid < 384) {
                int mm = tid / 6, r = tid % 6;
                int gate = r >> 1, half = r & 1;
                cp16(&GI0S[mm * 24 + gate * 8 + half * 4],
                     gi + mm * G3 + gate * H + hb + half * 4);
            }
            asm volatile("cp.async.commit_group;");
        }

        float acc[3][3][4];
#pragma unroll
        for (int m3 = 0; m3 < 3; m3++)
#pragma unroll
            for (int nt = 0; nt < 3; nt++)
                acc[m3][nt][0] = acc[m3][nt][1] = acc[m3][nt][2] = acc[m3][nt][3] = 0.f;

        u32 f[3][4][4];
        auto loadf = [&](int c, int slot) {
            int idx = (c * 4 + ksub) * 512 + fbase;
#pragma unroll
            for (int pl = 0; pl < 4; pl++) {
                uint4 v = __ldcg((const uint4*)(Apl[pl] + idx));
                f[slot][pl][0] = v.x; f[slot][pl][1] = v.y;
                f[slot][pl][2] = v.z; f[slot][pl][3] = v.w;
            }
        };
        loadf(0, 0);
        loadf(1, 1);

#pragma unroll
        for (int c = 0; c < 8; c++) {
            int slot = c % 3;
            if (c < 6) loadf(c + 2, (c + 2) % 3);
            const int cb = rowoff + c * 32;
#pragma unroll
            for (int m3 = 0; m3 < 3; m3++) {
                const u32* Ahi = (m3 == 2) ? f[slot][2] : f[slot][0];
                const u32* Alo = (m3 == 2) ? f[slot][3] : f[slot][1];
                const u32* WH = WS + (m3 * 2) * 24 * 264 + cb;
                const u32* WL = WH + 24 * 264;
#pragma unroll
                for (int nt = 0; nt < 3; nt++) {
                    ull wh64 = *(const ull*)(WH + nt * 8 * 264);
                    ull wl64 = *(const ull*)(WL + nt * 8 * 264);
                    u32 bh0 = (u32)wh64, bh1 = (u32)(wh64 >> 32);
                    u32 bl0 = (u32)wl64, bl1 = (u32)(wl64 >> 32);
                    mma16816(acc[m3][nt], Ahi, bh0, bh1);
                    mma16816(acc[m3][nt], Alo, bh0, bh1);
                    mma16816(acc[m3][nt], Ahi, bl0, bl1);
                }
            }
        }

        // ---- K-split pairwise reduction: ksub{0,2} write, ksub{1,3} accumulate ----
        __syncthreads();
        {
            float* Gb = (ksub & 2) ? G1 : G0;
            if ((ksub & 1) == 0) {
#pragma unroll
                for (int m3 = 0; m3 < 3; m3++) {
                    float* G = Gb + m3 * 1664;
#pragma unroll
                    for (int nt = 0; nt < 3; nt++) {
                        int col = nt * 8 + 2 * (l & 3);
                        int r0 = m0 + (l >> 2);
                        *(float2*)&G[r0 * 26 + col] =
                            make_float2(acc[m3][nt][0], acc[m3][nt][1]);
                        *(float2*)&G[(r0 + 8) * 26 + col] =
                            make_float2(acc[m3][nt][2], acc[m3][nt][3]);
                    }
                }
            }
            __syncthreads();
            if (ksub & 1) {
#pragma unroll
                for (int m3 = 0; m3 < 3; m3++) {
                    float* G = Gb + m3 * 1664;
#pragma unroll
                    for (int nt = 0; nt < 3; nt++) {
                        int col = nt * 8 + 2 * (l & 3);
                        int r0 = m0 + (l >> 2);
                        float2* p0 = (float2*)&G[r0 * 26 + col];
                        float2* p1 = (float2*)&G[(r0 + 8) * 26 + col];
                        float2 o0 = *p0, o1 = *p1;
                        *p0 = make_float2(o0.x + acc[m3][nt][0], o0.y + acc[m3][nt][1]);
                        *p1 = make_float2(o1.x + acc[m3][nt][2], o1.y + acc[m3][nt][3]);
                    }
                }
            }
            __syncthreads();
        }
        asm volatile("cp.async.wait_group 0;");

        // ---- L0 epilogue: t = p ----
        if (p < S) {
            float* Xnf = g_h0f[(p + 1) & 1][dir];
            char* Xnh = (char*)g_h0p[(p + 1) & 1][dir][0];
            char* Xnl = (char*)g_h0p[(p + 1) & 1][dir][1];
            float hr = G0[emm * 26 + ej]           + G1[emm * 26 + ej]           + bhh0[erow];
            float hz = G0[emm * 26 + 8 + ej]       + G1[emm * 26 + 8 + ej]       + bhh0[H + erow];
            float hn = G0[emm * 26 + 16 + ej]      + G1[emm * 26 + 16 + ej]      + bhh0[2 * H + erow];
            float rr = sigm(GI0S[emm * 24 + ej] + hr);
            float zz = sigm(GI0S[emm * 24 + 8 + ej] + hz);
            float nn = tanhf(GI0S[emm * 24 + 16 + ej] + rr * hn);
            float hnew = (1.0f - zz) * nn + zz * hprev0;
            hprev0 = hnew;
            Xnf[emm * H + erow] = hnew;
            bf16 hi, lo; split_bf(hnew, hi, lo);
            int off = frag_byte(emm, erow);
            *(bf16*)(Xnh + off) = hi;
            *(bf16*)(Xnl + off) = lo;
        }

        // ---- L1 epilogue: t = p-1 ----
        if (p >= 1) {
            int t1 = p - 1;
            int tt = dir ? (S - 1 - t1) : t1;
            float* Hnf = g_h1f[p & 1][dir];
            char* Hnh = (char*)g_h1p[p & 1][dir][0];
            char* Hnl = (char*)g_h1p[p & 1][dir][1];
            float ir  = G0[1664 + emm * 26 + ej]      + G1[1664 + emm * 26 + ej]      + bi1[erow];
            float iz  = G0[1664 + emm * 26 + 8 + ej]  + G1[1664 + emm * 26 + 8 + ej]  + bi1[H + erow];
            float inn = G0[1664 + emm * 26 + 16 + ej] + G1[1664 + emm * 26 + 16 + ej] + bi1[2 * H + erow];
            float hr  = G0[3328 + emm * 26 + ej]      + G1[3328 + emm * 26 + ej]      + bh1[erow];
            float hz  = G0[3328 + emm * 26 + 8 + ej]  + G1[3328 + emm * 26 + 8 + ej]  + bh1[H + erow];
            float hn  = G0[3328 + emm * 26 + 16 + ej] + G1[3328 + emm * 26 + 16 + ej] + bh1[2 * H + erow];
            float rr = sigm(ir + hr);
            float zz = sigm(iz + hz);
            float nn = tanhf(inn + rr * hn);
            float hnew = (1.0f - zz) * nn + zz * hprev1;
            hprev1 = hnew;
            Hnf[emm * H + erow] = hnew;
            bf16 hi, lo; split_bf(hnew, hi, lo);
            int off = frag_byte(emm, erow);
            *(bf16*)(Hnh + off) = hi;
            *(bf16*)(Hnl + off) = lo;
            out[(size_t)emm * (S * 2 * H) + (size_t)tt * (2 * H) + dir * H + erow] = hnew;
        }

        grid_bar(dir, (bid >> 3) & 7, (unsigned)(p + 1));
    }

    // ---- final hidden state copy (own dir; parity 0) ----
#pragma unroll
    for (int it = 0; it < 2; it++) {
        int local = (bid & 63) * 1024 + it * 512 + tid;   // < 65536 per dir
        int lyr = local >> 15;
        int rem = local & 32767;
        int b = rem >> 9;
        int n = rem & 511;
        float v = lyr ? __ldcg(&g_h1f[0][dir][b * H + n]) : __ldcg(&g_h0f[0][dir][b * H + n]);
        out[(size_t)B * S * 2 * H + ((size_t)lyr * B + b) * (2 * H) + dir * H + n] = v;
    }
}

// ---------------- launch ----------------
extern "C" void kernel_launch(void* const* d_in, const int* in_sizes, int n_in,
                              void* d_out, int out_size) {
    const float* input  = (const float*)d_in[0];
    const float* enc    = (const float*)d_in[1];
    const float* Wih_f  = (const float*)d_in[2];
    const float* Whh_f  = (const float*)d_in[3];
    const float* bih_f  = (const float*)d_in[4];
    const float* bhh_f  = (const float*)d_in[5];
    const float* Wih_b  = (const float*)d_in[6];
    const float* Whh_b  = (const float*)d_in[7];
    const float* bih_b  = (const float*)d_in[8];
    const float* bhh_b  = (const float*)d_in[9];
    float* out = (float*)d_out;

    const int SMEM_P = 198144;
    static int configured = 0;
    if (!configured) {
        cudaFuncSetAttribute(gru_persist, cudaFuncAttributeMaxDynamicSharedMemorySize, SMEM_P);
        configured = 1;
    }

    conv_xw<<<17920, 256>>>(input, Wih_f, Wih_b);
    init_h<<<512, 256>>>(enc);
    gemm_gi0<<<dim3(S, 24, 2), 256>>>(bih_f, bih_b);
    gru_persist<<<NBLK, 512, SMEM_P>>>(Wih_f, Wih_b, Whh_f, Whh_b,
                                       bih_f, bih_b, bhh_f, bhh_b, out);
}

// round 11
// speedup vs baseline: 1.4053x; 1.4053x over previous
#include <cuda_runtime.h>
#include <cuda_bf16.h>
#include <math.h>

#define S 512
#define B 64
#define H 512
#define D 512
#define G3 1536
#define NBLK 128

typedef unsigned u32;
typedef unsigned long long ull;
typedef __nv_bfloat16 bf16;

// ---------------- device-global scratch (allocation-free rule) ----------------
__device__ float g_gi0[(size_t)2 * S * B * G3];          // fp32 gi0 [dir][t][b][3H]
__device__ bf16  g_xp[2][(size_t)B * S * D];             // input hi/lo planes (planar)
__device__ bf16  g_wp[2][2][(size_t)G3 * D];             // Wih layer0 [dir][plane] (planar)
__device__ float g_h0f[2][2][B * H];                     // [parity][dir]
__device__ float g_h1f[2][2][B * H];
// h planes in mma-frag layout: u32 idx = kblk*512 + mtile*128 + lane*4 + reg
__device__ u32   g_h0p[2][2][2][16384];                  // [parity][dir][plane]
__device__ u32   g_h1p[2][2][2][16384];
__device__ unsigned g_arrive2[2];
__device__ unsigned g_release2[2];

// ---------------- helpers ----------------
__device__ __forceinline__ void split_bf(float v, bf16& hi, bf16& lo) {
    hi = __float2bfloat16(v);
    lo = __float2bfloat16(v - __bfloat162float(hi));
}
__device__ __forceinline__ u32 pack2(bf16 a, bf16 b) {
    return (u32)__bfloat16_as_ushort(a) | ((u32)__bfloat16_as_ushort(b) << 16);
}
__device__ __forceinline__ float sigm(float x) { return 1.0f / (1.0f + expf(-x)); }

// byte offset of h value (batch b, hidden k) inside a frag-layout plane
__device__ __forceinline__ int frag_byte(int b, int k) {
    int kblk = k >> 4, c = k & 15, mt = b >> 4, r = b & 15;
    int lane = (r & 7) * 4 + ((c & 7) >> 1);
    int reg  = (r >> 3) + 2 * (c >> 3);
    return ((kblk * 512 + mt * 128 + lane * 4 + reg) << 2) + ((c & 1) << 1);
}

__device__ __forceinline__ void mma16816(float* d, const u32* a, u32 b0, u32 b1) {
    asm volatile("mma.sync.aligned.m16n8k16.row.col.f32.bf16.bf16.f32 "
                 "{%0,%1,%2,%3},{%4,%5,%6,%7},{%8,%9},{%0,%1,%2,%3};"
                 : "+f"(d[0]), "+f"(d[1]), "+f"(d[2]), "+f"(d[3])
                 : "r"(a[0]), "r"(a[1]), "r"(a[2]), "r"(a[3]), "r"(b0), "r"(b1));
}
__device__ __forceinline__ void ldm4(u32* r, const void* p) {
    u32 s = (u32)__cvta_generic_to_shared(p);
    asm volatile("ldmatrix.sync.aligned.m8n8.x4.shared.b16 {%0,%1,%2,%3},[%4];"
                 : "=r"(r[0]), "=r"(r[1]), "=r"(r[2]), "=r"(r[3]) : "r"(s));
}
__device__ __forceinline__ void cp16(void* smem_dst, const void* gsrc) {
    u32 s = (u32)__cvta_generic_to_shared(smem_dst);
    asm volatile("cp.async.cg.shared.global [%0], [%1], 16;" :: "r"(s), "l"(gsrc));
}

// ---------------- conv_xw: input + Wih0 -> planar hi/lo bf16 planes ----------------
// blocks [0,16384): x; [16384,17920): W
__global__ void conv_xw(const float* __restrict__ x,
                        const float* __restrict__ wf, const float* __restrict__ wb) {
    if (blockIdx.x < 16384) {
        size_t i = ((size_t)blockIdx.x * 256 + threadIdx.x) * 4;
        float4 v = *(const float4*)&x[i];
        bf16 h0, l0, h1, l1, h2, l2, h3, l3;
        split_bf(v.x, h0, l0); split_bf(v.y, h1, l1);
        split_bf(v.z, h2, l2); split_bf(v.w, h3, l3);
        u32* ph = (u32*)&g_xp[0][i];
        u32* pl = (u32*)&g_xp[1][i];
        ph[0] = pack2(h0, h1); ph[1] = pack2(h2, h3);
        pl[0] = pack2(l0, l1); pl[1] = pack2(l2, l3);
    } else {
        size_t j = ((size_t)(blockIdx.x - 16384) * 256 + threadIdx.x) * 4;
        int d = j >= (size_t)G3 * D;
        size_t off = d ? j - (size_t)G3 * D : j;
        const float* src = d ? wb : wf;
        float4 v = *(const float4*)&src[off];
        bf16 h0, l0, h1, l1, h2, l2, h3, l3;
        split_bf(v.x, h0, l0); split_bf(v.y, h1, l1);
        split_bf(v.z, h2, l2); split_bf(v.w, h3, l3);
        u32* ph = (u32*)&g_wp[d][0][off];
        u32* pl = (u32*)&g_wp[d][1][off];
        ph[0] = pack2(h0, h1); ph[1] = pack2(h2, h3);
        pl[0] = pack2(l0, l1); pl[1] = pack2(l2, l3);
    }
}

// ---------------- init: hidden states (fp32 + frag planes) + barrier reset ----------------
__global__ void init_h(const float* __restrict__ enc) {
    if (blockIdx.x == 0 && threadIdx.x < 2) {
        g_arrive2[threadIdx.x] = 0;
        g_release2[threadIdx.x] = 0;
    }
    int idx = blockIdx.x * blockDim.x + threadIdx.x;   // 131072
    int layer = idx >> 16;
    int rem = idx & 65535;
    int dir = rem >> 15;
    int rem2 = rem & 32767;
    int b = rem2 >> 9;
    int n = rem2 & 511;
    float v = enc[(layer * B + b) * (2 * H) + dir * H + n];
    bf16 hi, lo; split_bf(v, hi, lo);
    int off = frag_byte(b, n);
    if (layer == 0) {
        g_h0f[0][dir][b * H + n] = v;
        *(bf16*)((char*)g_h0p[0][dir][0] + off) = hi;
        *(bf16*)((char*)g_h0p[0][dir][1] + off) = lo;
    } else {
        g_h1f[0][dir][b * H + n] = v;
        *(bf16*)((char*)g_h1p[0][dir][0] + off) = hi;
        *(bf16*)((char*)g_h1p[0][dir][1] + off) = lo;
    }
}

// ---------------- gi0 = input @ Wih0^T + bih0, smem-staged split-bf16 mma ----------------
// grid (S, 24, 2), 256 thr = 8 warps (4 mtiles x 2 nhalves of 32). M=64, N=64, K=512.
// smem 73728 -> 3 blocks/SM.  (R7 champion version)
__global__ void __launch_bounds__(256, 3)
gemm_gi0(const float* __restrict__ bf_, const float* __restrict__ bb_) {
    extern __shared__ char sm2[];
    char* Wbuf0 = sm2;                 // 2 planes x [64][72 bf16] = 18432
    char* Wbuf1 = sm2 + 18432;
    char* Xbuf0 = sm2 + 36864;
    char* Xbuf1 = sm2 + 55296;

    int s  = blockIdx.x;
    int nb = blockIdx.y;
    int d  = blockIdx.z;
    const float* bias = d ? bb_ : bf_;

    int tid = threadIdx.x;
    int w = tid >> 5, l = tid & 31;
    int mtile = w & 3, m0 = mtile * 16, nh = w >> 2;

    const char* wsrc[2] = { (const char*)&g_wp[d][0][(size_t)(nb * 64) * D],
                            (const char*)&g_wp[d][1][(size_t)(nb * 64) * D] };
    const char* xsrc[2] = { (const char*)&g_xp[0][0], (const char*)&g_xp[1][0] };

    float acc[4][4];
#pragma unroll
    for (int nt = 0; nt < 4; nt++) { acc[nt][0] = acc[nt][1] = acc[nt][2] = acc[nt][3] = 0.f; }

    auto stage = [&](int c, char* Wb, char* Xb) {
#pragma unroll
        for (int i = 0; i < 4; i++) {
            int idx = i * 256 + tid;              // < 1024
            int pl = idx >> 9, row = (idx >> 3) & 63, seg = idx & 7;
            cp16(Wb + pl * 9216 + row * 144 + seg * 16,
                 wsrc[pl] + (size_t)row * 1024 + c * 128 + seg * 16);
        }
#pragma unroll
        for (int i = 0; i < 4; i++) {
            int idx = i * 256 + tid;              // < 1024
            int pl = idx >> 9, row = (idx >> 3) & 63, seg = idx & 7;
            cp16(Xb + pl * 9216 + row * 144 + seg * 16,
                 xsrc[pl] + (size_t)row * 524288 + (size_t)s * 1024 + c * 128 + seg * 16);
        }
        asm volatile("cp.async.commit_group;");
    };

    stage(0, Wbuf0, Xbuf0);

    for (int c = 0; c < 8; c++) {
        asm volatile("cp.async.wait_group 0;");
        __syncthreads();
        if (c < 7) stage(c + 1, (c & 1) ? Wbuf0 : Wbuf1, (c & 1) ? Xbuf0 : Xbuf1);
        char* Wb = (c & 1) ? Wbuf1 : Wbuf0;
        char* Xb = (c & 1) ? Xbuf1 : Xbuf0;
#pragma unroll
        for (int kl = 0; kl < 4; kl++) {
            u32 ah[4], al[4];
            int aoff = (m0 + (l & 15)) * 144 + kl * 32 + (l >> 4) * 16;
            ldm4(ah, Xb + aoff);
            ldm4(al, Xb + 9216 + aoff);
            const u32* Wh = (const u32*)Wb;
            const u32* Wl = (const u32*)(Wb + 9216);
#pragma unroll
            for (int nt = 0; nt < 4; nt++) {
                int nrow = nh * 32 + nt * 8 + (l >> 2);
                int wi = nrow * 36 + kl * 8 + (l & 3);
                u32 bh0 = Wh[wi], bh1 = Wh[wi + 4];
                u32 bl0 = Wl[wi], bl1 = Wl[wi + 4];
                mma16816(acc[nt], ah, bh0, bh1);
                mma16816(acc[nt], al, bh0, bh1);
                mma16816(acc[nt], ah, bl0, bl1);
            }
        }
    }

#pragma unroll
    for (int nt = 0; nt < 4; nt++) {
        int col = nb * 64 + nh * 32 + nt * 8 + 2 * (l & 3);
        float2 bi = *(const float2*)&bias[col];
        int b0 = m0 + (l >> 2);
        float2 v0 = make_float2(acc[nt][0] + bi.x, acc[nt][1] + bi.y);
        float2 v1 = make_float2(acc[nt][2] + bi.x, acc[nt][3] + bi.y);
        *(float2*)&g_gi0[(((size_t)d * S + s) * B + b0) * G3 + col] = v0;
        *(float2*)&g_gi0[(((size_t)d * S + s) * B + b0 + 8) * G3 + col] = v1;
    }
}

// ---------------- per-dir grid barrier (R7 proven design) ----------------
__device__ __forceinline__ void grid_bar(int dir, unsigned target) {
    __syncthreads();
    if (threadIdx.x == 0) {
        __threadfence();
        unsigned v = atomicAdd(&g_arrive2[dir], 1u) + 1u;
        if (v == target * 64u) {
            asm volatile("st.release.gpu.u32 [%0], %1;" :: "l"(&g_release2[dir]), "r"(target) : "memory");
        } else {
            unsigned r;
            do {
                asm volatile("ld.acquire.gpu.u32 %0, [%1];" : "=r"(r) : "l"(&g_release2[dir]) : "memory");
            } while (r < target);
        }
    }
    __syncthreads();
}

// ---------------- persistent recurrence kernel ----------------
// grid 128 (2 dir x 64 hgroups of 8), 512 thr = 16 warps (mtile x4, ksub x4).
// smem: WS 152064 | G0 19968 | G1 19968 | GI0S 6144 = 198144 B
__global__ void __launch_bounds__(512, 1)
gru_persist(const float* __restrict__ Wih_f, const float* __restrict__ Wih_b,
            const float* __restrict__ Whh_f, const float* __restrict__ Whh_b,
            const float* __restrict__ bih_f, const float* __restrict__ bih_b,
            const float* __restrict__ bhh_f, const float* __restrict__ bhh_b,
            float* __restrict__ out) {
    extern __shared__ char smem[];
    u32*  WS    = (u32*)smem;                    // [(mat*2+plane)*24 + n][264]
    float* G0   = (float*)(smem + 152064);       // partials ksub{0,1}
    float* G1   = (float*)(smem + 172032);       // partials ksub{2,3}
    float* GI0S = (float*)(smem + 192000);       // [64][24]

    const int tid = threadIdx.x;
    const int bid = blockIdx.x;
    const int dir = bid >> 6;
    const int hb  = (bid & 63) * 8;
    const int w = tid >> 5, l = tid & 31;
    const int mtile = w & 3, m0 = mtile * 16, ksub = w >> 2;

    const float* Wih = dir ? Wih_b : Wih_f;
    const float* Whh = dir ? Whh_b : Whh_f;
    const float* bih = dir ? bih_b : bih_f;
    const float* bhh = dir ? bhh_b : bhh_f;
    const float* bhh0 = bhh;
    const float* bi1 = bih + G3;
    const float* bh1 = bhh + G3;

    // ---- one-time weight staging: bf16 hi/lo, (k,k+8)-interleaved u32 pairs ----
    {
        const float* Wmat[3] = { Whh, Wih + (size_t)G3 * D, Whh + (size_t)G3 * H };
#pragma unroll 4
        for (int i = 0; i < 36; i++) {
            int item = tid + 512 * i;            // < 18432
            int m3 = item / 6144;
            int rem = item - m3 * 6144;
            int n = rem >> 8;
            int k2 = rem & 255;
            int grow = (n >> 3) * H + hb + (n & 7);
            float2 v = *(const float2*)(Wmat[m3] + (size_t)grow * 512 + 2 * k2);
            bf16 h0, l0, h1, l1;
            split_bf(v.x, h0, l0); split_bf(v.y, h1, l1);
            int j = k2 & 7;
            int col = ((k2 >> 3) << 3) + ((j & 3) << 1) + (j >> 2);
            WS[((m3 * 2 + 0) * 24 + n) * 264 + col] = pack2(h0, h1);
            WS[((m3 * 2 + 1) * 24 + n) * 264 + col] = pack2(l0, l1);
        }
    }

    const int rowoff = (l >> 2) * 264 + 2 * (l & 3) + ksub * 8;
    const int fbase  = mtile * 128 + l * 4;

    for (int p = 0; p <= S; p++) {
        const u32* Apl[4] = { g_h0p[p & 1][dir][0], g_h0p[p & 1][dir][1],
                              g_h1p[(p + 1) & 1][dir][0], g_h1p[(p + 1) & 1][dir][1] };
        const float* Xf = g_h0f[p & 1][dir];
        const float* Hf = g_h1f[(p + 1) & 1][dir];

        // gi0 prefetch (used in L0 epilogue)
        if (p < S) {
            int tt0 = dir ? (S - 1 - p) : p;
            const float* gi = &g_gi0[((size_t)dir * S + tt0) * B * G3];
            if (tid < 384) {
                int mm = tid / 6, r = tid % 6;
                int gate = r >> 1, half = r & 1;
                cp16(&GI0S[mm * 24 + gate * 8 + half * 4],
                     gi + mm * G3 + gate * H + hb + half * 4);
            }
            asm volatile("cp.async.commit_group;");
        }

        float acc[3][3][4];
#pragma unroll
        for (int m3 = 0; m3 < 3; m3++)
#pragma unroll
            for (int nt = 0; nt < 3; nt++)
                acc[m3][nt][0] = acc[m3][nt][1] = acc[m3][nt][2] = acc[m3][nt][3] = 0.f;

        u32 f0[4][4], f1[4][4];
        {
            int idx = ksub * 512 + fbase;
#pragma unroll
            for (int pl = 0; pl < 4; pl++) {
                uint4 v = __ldcg((const uint4*)(Apl[pl] + idx));
                f0[pl][0] = v.x; f0[pl][1] = v.y; f0[pl][2] = v.z; f0[pl][3] = v.w;
            }
        }

#pragma unroll
        for (int c = 0; c < 8; c++) {
            if (c < 7) {
                int idx = ((c + 1) * 4 + ksub) * 512 + fbase;
                u32 (*Fn)[4] = (c & 1) ? f0 : f1;
#pragma unroll
                for (int pl = 0; pl < 4; pl++) {
                    uint4 v = __ldcg((const uint4*)(Apl[pl] + idx));
                    Fn[pl][0] = v.x; Fn[pl][1] = v.y; Fn[pl][2] = v.z; Fn[pl][3] = v.w;
                }
            }
            u32 (*Af)[4] = (c & 1) ? f1 : f0;
            const int cb = rowoff + c * 32;
#pragma unroll
            for (int m3 = 0; m3 < 3; m3++) {
                const u32* Ahi = (m3 == 2) ? Af[2] : Af[0];
                const u32* Alo = (m3 == 2) ? Af[3] : Af[1];
                const u32* WH = WS + (m3 * 2) * 24 * 264 + cb;
                const u32* WL = WH + 24 * 264;
#pragma unroll
                for (int nt = 0; nt < 3; nt++) {
                    ull wh64 = *(const ull*)(WH + nt * 8 * 264);
                    ull wl64 = *(const ull*)(WL + nt * 8 * 264);
                    u32 bh0 = (u32)wh64, bh1 = (u32)(wh64 >> 32);
                    u32 bl0 = (u32)wl64, bl1 = (u32)(wl64 >> 32);
                    mma16816(acc[m3][nt], Ahi, bh0, bh1);
                    mma16816(acc[m3][nt], Alo, bh0, bh1);
                    mma16816(acc[m3][nt], Ahi, bl0, bl1);
                }
            }
        }

        // ---- pairwise K-split reduction: ksub{0,2} write, ksub{1,3} accumulate ----
        __syncthreads();
        {
            float* Gb = (ksub & 2) ? G1 : G0;
            if ((ksub & 1) == 0) {
#pragma unroll
                for (int m3 = 0; m3 < 3; m3++) {
                    float* G = Gb + m3 * 1664;
#pragma unroll
                    for (int nt = 0; nt < 3; nt++) {
                        int col = nt * 8 + 2 * (l & 3);
                        int r0 = m0 + (l >> 2);
                        *(float2*)&G[r0 * 26 + col] =
                            make_float2(acc[m3][nt][0], acc[m3][nt][1]);
                        *(float2*)&G[(r0 + 8) * 26 + col] =
                            make_float2(acc[m3][nt][2], acc[m3][nt][3]);
                    }
                }
            }
            __syncthreads();
            if (ksub & 1) {
#pragma unroll
                for (int m3 = 0; m3 < 3; m3++) {
                    float* G = Gb + m3 * 1664;
#pragma unroll
                    for (int nt = 0; nt < 3; nt++) {
                        int col = nt * 8 + 2 * (l & 3);
                        int r0 = m0 + (l >> 2);
                        float2* p0 = (float2*)&G[r0 * 26 + col];
                        float2* p1 = (float2*)&G[(r0 + 8) * 26 + col];
                        float2 o0 = *p0, o1 = *p1;
                        *p0 = make_float2(o0.x + acc[m3][nt][0], o0.y + acc[m3][nt][1]);
                        *p1 = make_float2(o1.x + acc[m3][nt][2], o1.y + acc[m3][nt][3]);
                    }
                }
            }
            __syncthreads();
        }
        asm volatile("cp.async.wait_group 0;");

        // ---- L0 epilogue: t = p ----
        if (p < S) {
            float* Xnf = g_h0f[(p + 1) & 1][dir];
            char* Xnh = (char*)g_h0p[(p + 1) & 1][dir][0];
            char* Xnl = (char*)g_h0p[(p + 1) & 1][dir][1];
            int mm = tid & 63;
            int j  = tid >> 6;
            int row = hb + j;
            float hr = G0[mm * 26 + j]      + G1[mm * 26 + j]      + bhh0[row];
            float hz = G0[mm * 26 + 8 + j]  + G1[mm * 26 + 8 + j]  + bhh0[H + row];
            float hn = G0[mm * 26 + 16 + j] + G1[mm * 26 + 16 + j] + bhh0[2 * H + row];
            float rr = sigm(GI0S[mm * 24 + j] + hr);
            float zz = sigm(GI0S[mm * 24 + 8 + j] + hz);
            float nn = tanhf(GI0S[mm * 24 + 16 + j] + rr * hn);
            float hp = __ldcg(&Xf[mm * H + row]);
            float hnew = (1.0f - zz) * nn + zz * hp;
            Xnf[mm * H + row] = hnew;
            bf16 hi, lo; split_bf(hnew, hi, lo);
            int off = frag_byte(mm, row);
            *(bf16*)(Xnh + off) = hi;
            *(bf16*)(Xnl + off) = lo;
        }

        // ---- L1 epilogue: t = p-1 ----
        if (p >= 1) {
            int t1 = p - 1;
            int tt = dir ? (S - 1 - t1) : t1;
            float* Hnf = g_h1f[p & 1][dir];
            char* Hnh = (char*)g_h1p[p & 1][dir][0];
            char* Hnl = (char*)g_h1p[p & 1][dir][1];
            int mm = tid & 63;
            int j  = tid >> 6;
            int row = hb + j;
            float ir  = G0[1664 + mm * 26 + j]      + G1[1664 + mm * 26 + j]      + bi1[row];
            float iz  = G0[1664 + mm * 26 + 8 + j]  + G1[1664 + mm * 26 + 8 + j]  + bi1[H + row];
            float inn = G0[1664 + mm * 26 + 16 + j] + G1[1664 + mm * 26 + 16 + j] + bi1[2 * H + row];
            float hr  = G0[3328 + mm * 26 + j]      + G1[3328 + mm * 26 + j]      + bh1[row];
            float hz  = G0[3328 + mm * 26 + 8 + j]  + G1[3328 + mm * 26 + 8 + j]  + bh1[H + row];
            float hn  = G0[3328 + mm * 26 + 16 + j] + G1[3328 + mm * 26 + 16 + j] + bh1[2 * H + row];
            float rr = sigm(ir + hr);
            float zz = sigm(iz + hz);
            float nn = tanhf(inn + rr * hn);
            float hp = __ldcg(&Hf[mm * H + row]);
            float hnew = (1.0f - zz) * nn + zz * hp;
            Hnf[mm * H + row] = hnew;
            bf16 hi, lo; split_bf(hnew, hi, lo);
            int off = frag_byte(mm, row);
            *(bf16*)(Hnh + off) = hi;
            *(bf16*)(Hnl + off) = lo;
            out[(size_t)mm * (S * 2 * H) + (size_t)tt * (2 * H) + dir * H + row] = hnew;
        }

        grid_bar(dir, (unsigned)(p + 1));
    }

    // ---- final hidden state copy (own dir; parity 0) ----
#pragma unroll
    for (int it = 0; it < 2; it++) {
        int local = (bid & 63) * 1024 + it * 512 + tid;   // < 65536 per dir
        int lyr = local >> 15;
        int rem = local & 32767;
        int b = rem >> 9;
        int n = rem & 511;
        float v = lyr ? __ldcg(&g_h1f[0][dir][b * H + n]) : __ldcg(&g_h0f[0][dir][b * H + n]);
        out[(size_t)B * S * 2 * H + ((size_t)lyr * B + b) * (2 * H) + dir * H + n] = v;
    }
}

// ---------------- launch ----------------
extern "C" void kernel_launch(void* const* d_in, const int* in_sizes, int n_in,
                              void* d_out, int out_size) {
    const float* input  = (const float*)d_in[0];
    const float* enc    = (const float*)d_in[1];
    const float* Wih_f  = (const float*)d_in[2];
    const float* Whh_f  = (const float*)d_in[3];
    const float* bih_f  = (const float*)d_in[4];
    const float* bhh_f  = (const float*)d_in[5];
    const float* Wih_b  = (const float*)d_in[6];
    const float* Whh_b  = (const float*)d_in[7];
    const float* bih_b  = (const float*)d_in[8];
    const float* bhh_b  = (const float*)d_in[9];
    float* out = (float*)d_out;

    const int SMEM_G = 73728;
    const int SMEM_P = 198144;
    static int configured = 0;
    if (!configured) {
        cudaFuncSetAttribute(gemm_gi0, cudaFuncAttributeMaxDynamicSharedMemorySize, SMEM_G);
        cudaFuncSetAttribute(gru_persist, cudaFuncAttributeMaxDynamicSharedMemorySize, SMEM_P);
        configured = 1;
    }

    conv_xw<<<17920, 256>>>(input, Wih_f, Wih_b);
    init_h<<<512, 256>>>(enc);
    gemm_gi0<<<dim3(S, 24, 2), 256, SMEM_G>>>(bih_f, bih_b);
    gru_persist<<<NBLK, 512, SMEM_P>>>(Wih_f, Wih_b, Whh_f, Whh_b,
                                       bih_f, bih_b, bhh_f, bhh_b, out);
}

// round 12
// speedup vs baseline: 1.4673x; 1.0441x over previous
#include <cuda_runtime.h>
#include <cuda_bf16.h>
#include <math.h>

#define S 512
#define B 64
#define H 512
#define D 512
#define G3 1536
#define NBLK 128

typedef unsigned u32;
typedef unsigned long long ull;
typedef __nv_bfloat16 bf16;

// ---------------- device-global scratch (allocation-free rule) ----------------
__device__ float g_gi0[(size_t)2 * S * B * G3];          // fp32 gi0 [dir][t][b][3H]
__device__ bf16  g_xp[2][(size_t)B * S * D];             // input hi/lo planes (planar)
__device__ bf16  g_wp[2][2][(size_t)G3 * D];             // Wih layer0 [dir][plane] (planar)
__device__ float g_h0f[2][2][B * H];                     // [parity][dir]
__device__ float g_h1f[2][2][B * H];
// unified h planes, mma-frag layout: sel = layer*4 + parity*2 + dir; [sel][plane][...]
__device__ u32   g_hp[8][2][16384];
__device__ unsigned g_arrive2[2];
__device__ unsigned g_release2[2];

// ---------------- helpers ----------------
__device__ __forceinline__ void split_bf(float v, bf16& hi, bf16& lo) {
    hi = __float2bfloat16(v);
    lo = __float2bfloat16(v - __bfloat162float(hi));
}
__device__ __forceinline__ u32 pack2(bf16 a, bf16 b) {
    return (u32)__bfloat16_as_ushort(a) | ((u32)__bfloat16_as_ushort(b) << 16);
}
__device__ __forceinline__ float sigm(float x) { return 1.0f / (1.0f + expf(-x)); }

// byte offset of h value (batch b, hidden k) inside a frag-layout plane
__device__ __forceinline__ int frag_byte(int b, int k) {
    int kblk = k >> 4, c = k & 15, mt = b >> 4, r = b & 15;
    int lane = (r & 7) * 4 + ((c & 7) >> 1);
    int reg  = (r >> 3) + 2 * (c >> 3);
    return ((kblk * 512 + mt * 128 + lane * 4 + reg) << 2) + ((c & 1) << 1);
}

__device__ __forceinline__ void mma16816(float* d, const u32* a, u32 b0, u32 b1) {
    asm volatile("mma.sync.aligned.m16n8k16.row.col.f32.bf16.bf16.f32 "
                 "{%0,%1,%2,%3},{%4,%5,%6,%7},{%8,%9},{%0,%1,%2,%3};"
                 : "+f"(d[0]), "+f"(d[1]), "+f"(d[2]), "+f"(d[3])
                 : "r"(a[0]), "r"(a[1]), "r"(a[2]), "r"(a[3]), "r"(b0), "r"(b1));
}
__device__ __forceinline__ void ldm4(u32* r, const void* p) {
    u32 s = (u32)__cvta_generic_to_shared(p);
    asm volatile("ldmatrix.sync.aligned.m8n8.x4.shared.b16 {%0,%1,%2,%3},[%4];"
                 : "=r"(r[0]), "=r"(r[1]), "=r"(r[2]), "=r"(r[3]) : "r"(s));
}
__device__ __forceinline__ void cp16(void* smem_dst, const void* gsrc) {
    u32 s = (u32)__cvta_generic_to_shared(smem_dst);
    asm volatile("cp.async.cg.shared.global [%0], [%1], 16;" :: "r"(s), "l"(gsrc));
}

// ---------------- conv_xw: input + Wih0 -> planar hi/lo bf16 planes ----------------
__global__ void conv_xw(const float* __restrict__ x,
                        const float* __restrict__ wf, const float* __restrict__ wb) {
    if (blockIdx.x < 16384) {
        size_t i = ((size_t)blockIdx.x * 256 + threadIdx.x) * 4;
        float4 v = *(const float4*)&x[i];
        bf16 h0, l0, h1, l1, h2, l2, h3, l3;
        split_bf(v.x, h0, l0); split_bf(v.y, h1, l1);
        split_bf(v.z, h2, l2); split_bf(v.w, h3, l3);
        u32* ph = (u32*)&g_xp[0][i];
        u32* pl = (u32*)&g_xp[1][i];
        ph[0] = pack2(h0, h1); ph[1] = pack2(h2, h3);
        pl[0] = pack2(l0, l1); pl[1] = pack2(l2, l3);
    } else {
        size_t j = ((size_t)(blockIdx.x - 16384) * 256 + threadIdx.x) * 4;
        int d = j >= (size_t)G3 * D;
        size_t off = d ? j - (size_t)G3 * D : j;
        const float* src = d ? wb : wf;
        float4 v = *(const float4*)&src[off];
        bf16 h0, l0, h1, l1, h2, l2, h3, l3;
        split_bf(v.x, h0, l0); split_bf(v.y, h1, l1);
        split_bf(v.z, h2, l2); split_bf(v.w, h3, l3);
        u32* ph = (u32*)&g_wp[d][0][off];
        u32* pl = (u32*)&g_wp[d][1][off];
        ph[0] = pack2(h0, h1); ph[1] = pack2(h2, h3);
        pl[0] = pack2(l0, l1); pl[1] = pack2(l2, l3);
    }
}

// ---------------- init: hidden states (fp32 + frag planes) + barrier reset ----------------
__global__ void init_h(const float* __restrict__ enc) {
    if (blockIdx.x == 0 && threadIdx.x < 2) {
        g_arrive2[threadIdx.x] = 0;
        g_release2[threadIdx.x] = 0;
    }
    int idx = blockIdx.x * blockDim.x + threadIdx.x;   // 131072
    int layer = idx >> 16;
    int rem = idx & 65535;
    int dir = rem >> 15;
    int rem2 = rem & 32767;
    int b = rem2 >> 9;
    int n = rem2 & 511;
    float v = enc[(layer * B + b) * (2 * H) + dir * H + n];
    bf16 hi, lo; split_bf(v, hi, lo);
    int off = frag_byte(b, n);
    int sel = layer * 4 + dir;                 // parity 0
    if (layer == 0) g_h0f[0][dir][b * H + n] = v;
    else            g_h1f[0][dir][b * H + n] = v;
    *(bf16*)((char*)g_hp[sel][0] + off) = hi;
    *(bf16*)((char*)g_hp[sel][1] + off) = lo;
}

// ---------------- gi0 = input @ Wih0^T + bih0, smem-staged split-bf16 mma ----------------
__global__ void __launch_bounds__(256, 3)
gemm_gi0(const float* __restrict__ bf_, const float* __restrict__ bb_) {
    extern __shared__ char sm2[];
    char* Wbuf0 = sm2;
    char* Wbuf1 = sm2 + 18432;
    char* Xbuf0 = sm2 + 36864;
    char* Xbuf1 = sm2 + 55296;

    int s  = blockIdx.x;
    int nb = blockIdx.y;
    int d  = blockIdx.z;
    const float* bias = d ? bb_ : bf_;

    int tid = threadIdx.x;
    int w = tid >> 5, l = tid & 31;
    int mtile = w & 3, m0 = mtile * 16, nh = w >> 2;

    const char* wsrc[2] = { (const char*)&g_wp[d][0][(size_t)(nb * 64) * D],
                            (const char*)&g_wp[d][1][(size_t)(nb * 64) * D] };
    const char* xsrc[2] = { (const char*)&g_xp[0][0], (const char*)&g_xp[1][0] };

    float acc[4][4];
#pragma unroll
    for (int nt = 0; nt < 4; nt++) { acc[nt][0] = acc[nt][1] = acc[nt][2] = acc[nt][3] = 0.f; }

    auto stage = [&](int c, char* Wb, char* Xb) {
#pragma unroll
        for (int i = 0; i < 4; i++) {
            int idx = i * 256 + tid;
            int pl = idx >> 9, row = (idx >> 3) & 63, seg = idx & 7;
            cp16(Wb + pl * 9216 + row * 144 + seg * 16,
                 wsrc[pl] + (size_t)row * 1024 + c * 128 + seg * 16);
        }
#pragma unroll
        for (int i = 0; i < 4; i++) {
            int idx = i * 256 + tid;
            int pl = idx >> 9, row = (idx >> 3) & 63, seg = idx & 7;
            cp16(Xb + pl * 9216 + row * 144 + seg * 16,
                 xsrc[pl] + (size_t)row * 524288 + (size_t)s * 1024 + c * 128 + seg * 16);
        }
        asm volatile("cp.async.commit_group;");
    };

    stage(0, Wbuf0, Xbuf0);

    for (int c = 0; c < 8; c++) {
        asm volatile("cp.async.wait_group 0;");
        __syncthreads();
        if (c < 7) stage(c + 1, (c & 1) ? Wbuf0 : Wbuf1, (c & 1) ? Xbuf0 : Xbuf1);
        char* Wb = (c & 1) ? Wbuf1 : Wbuf0;
        char* Xb = (c & 1) ? Xbuf1 : Xbuf0;
#pragma unroll
        for (int kl = 0; kl < 4; kl++) {
            u32 ah[4], al[4];
            int aoff = (m0 + (l & 15)) * 144 + kl * 32 + (l >> 4) * 16;
            ldm4(ah, Xb + aoff);
            ldm4(al, Xb + 9216 + aoff);
            const u32* Wh = (const u32*)Wb;
            const u32* Wl = (const u32*)(Wb + 9216);
#pragma unroll
            for (int nt = 0; nt < 4; nt++) {
                int nrow = nh * 32 + nt * 8 + (l >> 2);
                int wi = nrow * 36 + kl * 8 + (l & 3);
                u32 bh0 = Wh[wi], bh1 = Wh[wi + 4];
                u32 bl0 = Wl[wi], bl1 = Wl[wi + 4];
                mma16816(acc[nt], ah, bh0, bh1);
                mma16816(acc[nt], al, bh0, bh1);
                mma16816(acc[nt], ah, bl0, bl1);
            }
        }
    }

#pragma unroll
    for (int nt = 0; nt < 4; nt++) {
        int col = nb * 64 + nh * 32 + nt * 8 + 2 * (l & 3);
        float2 bi = *(const float2*)&bias[col];
        int b0 = m0 + (l >> 2);
        float2 v0 = make_float2(acc[nt][0] + bi.x, acc[nt][1] + bi.y);
        float2 v1 = make_float2(acc[nt][2] + bi.x, acc[nt][3] + bi.y);
        *(float2*)&g_gi0[(((size_t)d * S + s) * B + b0) * G3 + col] = v0;
        *(float2*)&g_gi0[(((size_t)d * S + s) * B + b0 + 8) * G3 + col] = v1;
    }
}

// ---------------- per-dir grid barrier (R7 proven design) ----------------
__device__ __forceinline__ void grid_bar(int dir, unsigned target) {
    __syncthreads();
    if (threadIdx.x == 0) {
        __threadfence();
        unsigned v = atomicAdd(&g_arrive2[dir], 1u) + 1u;
        if (v == target * 64u) {
            asm volatile("st.release.gpu.u32 [%0], %1;" :: "l"(&g_release2[dir]), "r"(target) : "memory");
        } else {
            unsigned r;
            do {
                asm volatile("ld.acquire.gpu.u32 %0, [%1];" : "=r"(r) : "l"(&g_release2[dir]) : "memory");
            } while (r < target);
        }
    }
    __syncthreads();
}

// ---------------- persistent recurrence kernel ----------------
// grid 128 (2 dir x 64 hgroups of 8), 512 thr = 16 warps (mtile x4, ksub x4).
// smem: WS 152064 | G0 19968 | G1 19968 | GI0S 6144 = 198144 B
__global__ void __launch_bounds__(512, 1)
gru_persist(const float* __restrict__ Wih_f, const float* __restrict__ Wih_b,
            const float* __restrict__ Whh_f, const float* __restrict__ Whh_b,
            const float* __restrict__ bih_f, const float* __restrict__ bih_b,
            const float* __restrict__ bhh_f, const float* __restrict__ bhh_b,
            float* __restrict__ out) {
    extern __shared__ char smem[];
    u32*  WS    = (u32*)smem;                    // [(mat*2+plane)*24 + n][264]
    float* G0   = (float*)(smem + 152064);       // partials ksub{0,1}
    float* G1   = (float*)(smem + 172032);       // partials ksub{2,3}
    float* GI0S = (float*)(smem + 192000);       // [64][24]

    const int tid = threadIdx.x;
    const int bid = blockIdx.x;
    const int dir = bid >> 6;
    const int hb  = (bid & 63) * 8;
    const int w = tid >> 5, l = tid & 31;
    const int mtile = w & 3, m0 = mtile * 16, ksub = w >> 2;

    const float* Wih = dir ? Wih_b : Wih_f;
    const float* Whh = dir ? Whh_b : Whh_f;
    const float* bih = dir ? bih_b : bih_f;
    const float* bhh = dir ? bhh_b : bhh_f;
    const float* bhh0 = bhh;
    const float* bi1 = bih + G3;
    const float* bh1 = bhh + G3;

    // ---- one-time weight staging: bf16 hi/lo, (k,k+8)-interleaved u32 pairs ----
    {
        const float* Wmat[3] = { Whh, Wih + (size_t)G3 * D, Whh + (size_t)G3 * H };
#pragma unroll 4
        for (int i = 0; i < 36; i++) {
            int item = tid + 512 * i;            // < 18432
            int m3 = item / 6144;
            int rem = item - m3 * 6144;
            int n = rem >> 8;
            int k2 = rem & 255;
            int grow = (n >> 3) * H + hb + (n & 7);
            float2 v = *(const float2*)(Wmat[m3] + (size_t)grow * 512 + 2 * k2);
            bf16 h0, l0, h1, l1;
            split_bf(v.x, h0, l0); split_bf(v.y, h1, l1);
            int j = k2 & 7;
            int col = ((k2 >> 3) << 3) + ((j & 3) << 1) + (j >> 2);
            WS[((m3 * 2 + 0) * 24 + n) * 264 + col] = pack2(h0, h1);
            WS[((m3 * 2 + 1) * 24 + n) * 264 + col] = pack2(l0, l1);
        }
    }

    // ---- register-carried previous-h for this thread's fixed (emm, erow) element ----
    const int emm = tid & 63;
    const int ej  = tid >> 6;
    const int erow = hb + ej;
    float hprev0 = g_h0f[0][dir][emm * H + erow];
    float hprev1 = g_h1f[0][dir][emm * H + erow];
    const int eoff = frag_byte(emm, erow);

    const int rowoff = (l >> 2) * 264 + 2 * (l & 3) + ksub * 8;
    const int fbase  = mtile * 128 + l * 4;

    for (int p = 0; p <= S; p++) {
        const u32* Xb = g_hp[(p & 1) * 2 + dir][0];            // layer0 planes (hi at +0, lo at +16384)
        const u32* Hb = g_hp[4 + ((p + 1) & 1) * 2 + dir][0];  // layer1 planes

        // gi0 prefetch (used in L0 epilogue)
        if (p < S) {
            int tt0 = dir ? (S - 1 - p) : p;
            const float* gi = &g_gi0[((size_t)dir * S + tt0) * B * G3];
            if (tid < 384) {
                int mm = tid / 6, r = tid % 6;
                int gate = r >> 1, half = r & 1;
                cp16(&GI0S[mm * 24 + gate * 8 + half * 4],
                     gi + mm * G3 + gate * H + hb + half * 4);
            }
            asm volatile("cp.async.commit_group;");
        }

        float acc[3][3][4];
#pragma unroll
        for (int m3 = 0; m3 < 3; m3++)
#pragma unroll
            for (int nt = 0; nt < 3; nt++)
                acc[m3][nt][0] = acc[m3][nt][1] = acc[m3][nt][2] = acc[m3][nt][3] = 0.f;

        u32 f0[4][4], f1[4][4];
        {
            int idx = ksub * 512 + fbase;
            uint4 v;
            v = __ldcg((const uint4*)(Xb + idx));
            f0[0][0] = v.x; f0[0][1] = v.y; f0[0][2] = v.z; f0[0][3] = v.w;
            v = __ldcg((const uint4*)(Xb + 16384 + idx));
            f0[1][0] = v.x; f0[1][1] = v.y; f0[1][2] = v.z; f0[1][3] = v.w;
            v = __ldcg((const uint4*)(Hb + idx));
            f0[2][0] = v.x; f0[2][1] = v.y; f0[2][2] = v.z; f0[2][3] = v.w;
            v = __ldcg((const uint4*)(Hb + 16384 + idx));
            f0[3][0] = v.x; f0[3][1] = v.y; f0[3][2] = v.z; f0[3][3] = v.w;
        }

#pragma unroll
        for (int c = 0; c < 8; c++) {
            if (c < 7) {
                int idx = ((c + 1) * 4 + ksub) * 512 + fbase;
                u32 (*Fn)[4] = (c & 1) ? f0 : f1;
                uint4 v;
                v = __ldcg((const uint4*)(Xb + idx));
                Fn[0][0] = v.x; Fn[0][1] = v.y; Fn[0][2] = v.z; Fn[0][3] = v.w;
                v = __ldcg((const uint4*)(Xb + 16384 + idx));
                Fn[1][0] = v.x; Fn[1][1] = v.y; Fn[1][2] = v.z; Fn[1][3] = v.w;
                v = __ldcg((const uint4*)(Hb + idx));
                Fn[2][0] = v.x; Fn[2][1] = v.y; Fn[2][2] = v.z; Fn[2][3] = v.w;
                v = __ldcg((const uint4*)(Hb + 16384 + idx));
                Fn[3][0] = v.x; Fn[3][1] = v.y; Fn[3][2] = v.z; Fn[3][3] = v.w;
            }
            u32 (*Af)[4] = (c & 1) ? f1 : f0;
            const int cb = rowoff + c * 32;
#pragma unroll
            for (int m3 = 0; m3 < 3; m3++) {
                const u32* Ahi = (m3 == 2) ? Af[2] : Af[0];
                const u32* Alo = (m3 == 2) ? Af[3] : Af[1];
                const u32* WH = WS + (m3 * 2) * 24 * 264 + cb;
                const u32* WL = WH + 24 * 264;
#pragma unroll
                for (int nt = 0; nt < 3; nt++) {
                    ull wh64 = *(const ull*)(WH + nt * 8 * 264);
                    ull wl64 = *(const ull*)(WL + nt * 8 * 264);
                    u32 bh0 = (u32)wh64, bh1 = (u32)(wh64 >> 32);
                    u32 bl0 = (u32)wl64, bl1 = (u32)(wl64 >> 32);
                    mma16816(acc[m3][nt], Ahi, bh0, bh1);
                    mma16816(acc[m3][nt], Alo, bh0, bh1);
                    mma16816(acc[m3][nt], Ahi, bl0, bl1);
                }
            }
        }

        // ---- pairwise K-split reduction: ksub{0,2} write, ksub{1,3} accumulate ----
        __syncthreads();
        {
            float* Gb = (ksub & 2) ? G1 : G0;
            if ((ksub & 1) == 0) {
#pragma unroll
                for (int m3 = 0; m3 < 3; m3++) {
                    float* G = Gb + m3 * 1664;
#pragma unroll
                    for (int nt = 0; nt < 3; nt++) {
                        int col = nt * 8 + 2 * (l & 3);
                        int r0 = m0 + (l >> 2);
                        *(float2*)&G[r0 * 26 + col] =
                            make_float2(acc[m3][nt][0], acc[m3][nt][1]);
                        *(float2*)&G[(r0 + 8) * 26 + col] =
                            make_float2(acc[m3][nt][2], acc[m3][nt][3]);
                    }
                }
            }
            __syncthreads();
            if (ksub & 1) {
#pragma unroll
                for (int m3 = 0; m3 < 3; m3++) {
                    float* G = Gb + m3 * 1664;
#pragma unroll
                    for (int nt = 0; nt < 3; nt++) {
                        int col = nt * 8 + 2 * (l & 3);
                        int r0 = m0 + (l >> 2);
                        float2* p0 = (float2*)&G[r0 * 26 + col];
                        float2* p1 = (float2*)&G[(r0 + 8) * 26 + col];
                        float2 o0 = *p0, o1 = *p1;
                        *p0 = make_float2(o0.x + acc[m3][nt][0], o0.y + acc[m3][nt][1]);
                        *p1 = make_float2(o1.x + acc[m3][nt][2], o1.y + acc[m3][nt][3]);
                    }
                }
            }
            __syncthreads();
        }
        asm volatile("cp.async.wait_group 0;");

        // ---- L0 epilogue: t = p ----
        if (p < S) {
            float* Xnf = g_h0f[(p + 1) & 1][dir];
            char* Xn = (char*)g_hp[((p + 1) & 1) * 2 + dir][0];
            float hr = G0[emm * 26 + ej]      + G1[emm * 26 + ej]      + bhh0[erow];
            float hz = G0[emm * 26 + 8 + ej]  + G1[emm * 26 + 8 + ej]  + bhh0[H + erow];
            float hn = G0[emm * 26 + 16 + ej] + G1[emm * 26 + 16 + ej] + bhh0[2 * H + erow];
            float rr = sigm(GI0S[emm * 24 + ej] + hr);
            float zz = sigm(GI0S[emm * 24 + 8 + ej] + hz);
            float nn = tanhf(GI0S[emm * 24 + 16 + ej] + rr * hn);
            float hnew = (1.0f - zz) * nn + zz * hprev0;
            hprev0 = hnew;
            Xnf[emm * H + erow] = hnew;
            bf16 hi, lo; split_bf(hnew, hi, lo);
            *(bf16*)(Xn + eoff) = hi;
            *(bf16*)(Xn + 65536 + eoff) = lo;
        }

        // ---- L1 epilogue: t = p-1 ----
        if (p >= 1) {
            int t1 = p - 1;
            int tt = dir ? (S - 1 - t1) : t1;
            float* Hnf = g_h1f[p & 1][dir];
            char* Hn = (char*)g_hp[4 + (p & 1) * 2 + dir][0];
            float ir  = G0[1664 + emm * 26 + ej]      + G1[1664 + emm * 26 + ej]      + bi1[erow];
            float iz  = G0[1664 + emm * 26 + 8 + ej]  + G1[1664 + emm * 26 + 8 + ej]  + bi1[H + erow];
            float inn = G0[1664 + emm * 26 + 16 + ej] + G1[1664 + emm * 26 + 16 + ej] + bi1[2 * H + erow];
            float hr  = G0[3328 + emm * 26 + ej]      + G1[3328 + emm * 26 + ej]      + bh1[erow];
            float hz  = G0[3328 + emm * 26 + 8 + ej]  + G1[3328 + emm * 26 + 8 + ej]  + bh1[H + erow];
            float hn  = G0[3328 + emm * 26 + 16 + ej] + G1[3328 + emm * 26 + 16 + ej] + bh1[2 * H + erow];
            float rr = sigm(ir + hr);
            float zz = sigm(iz + hz);
            float nn = tanhf(inn + rr * hn);
            float hnew = (1.0f - zz) * nn + zz * hprev1;
            hprev1 = hnew;
            Hnf[emm * H + erow] = hnew;
            bf16 hi, lo; split_bf(hnew, hi, lo);
            *(bf16*)(Hn + eoff) = hi;
            *(bf16*)(Hn + 65536 + eoff) = lo;
            out[(size_t)emm * (S * 2 * H) + (size_t)tt * (2 * H) + dir * H + erow] = hnew;
        }

        grid_bar(dir, (unsigned)(p + 1));
    }

    // ---- final hidden state copy (own dir; parity 0) ----
#pragma unroll
    for (int it = 0; it < 2; it++) {
        int local = (bid & 63) * 1024 + it * 512 + tid;   // < 65536 per dir
        int lyr = local >> 15;
        int rem = local & 32767;
        int b = rem >> 9;
        int n = rem & 511;
        float v = lyr ? __ldcg(&g_h1f[0][dir][b * H + n]) : __ldcg(&g_h0f[0][dir][b * H + n]);
        out[(size_t)B * S * 2 * H + ((size_t)lyr * B + b) * (2 * H) + dir * H + n] = v;
    }
}

// ---------------- launch ----------------
extern "C" void kernel_launch(void* const* d_in, const int* in_sizes, int n_in,
                              void* d_out, int out_size) {
    const float* input  = (const float*)d_in[0];
    const float* enc    = (const float*)d_in[1];
    const float* Wih_f  = (const float*)d_in[2];
    const float* Whh_f  = (const float*)d_in[3];
    const float* bih_f  = (const float*)d_in[4];
    const float* bhh_f  = (const float*)d_in[5];
    const float* Wih_b  = (const float*)d_in[6];
    const float* Whh_b  = (const float*)d_in[7];
    const float* bih_b  = (const float*)d_in[8];
    const float* bhh_b  = (const float*)d_in[9];
    float* out = (float*)d_out;

    const int SMEM_G = 73728;
    const int SMEM_P = 198144;
    static int configured = 0;
    if (!configured) {
        cudaFuncSetAttribute(gemm_gi0, cudaFuncAttributeMaxDynamicSharedMemorySize, SMEM_G);
        cudaFuncSetAttribute(gru_persist, cudaFuncAttributeMaxDynamicSharedMemorySize, SMEM_P);
        configured = 1;
    }

    conv_xw<<<17920, 256>>>(input, Wih_f, Wih_b);
    init_h<<<512, 256>>>(enc);
    gemm_gi0<<<dim3(S, 24, 2), 256, SMEM_G>>>(bih_f, bih_b);
    gru_persist<<<NBLK, 512, SMEM_P>>>(Wih_f, Wih_b, Whh_f, Whh_b,
                                       bih_f, bih_b, bhh_f, bhh_b, out);
}

// round 13
// speedup vs baseline: 1.7086x; 1.1645x over previous
#include <cuda_runtime.h>
#include <cuda_bf16.h>
#include <math.h>

#define S 512
#define B 64
#define H 512
#define D 512
#define G3 1536
#define NBLK 128

typedef unsigned u32;
typedef unsigned long long ull;
typedef __nv_bfloat16 bf16;

// ---------------- device-global scratch (allocation-free rule) ----------------
__device__ float g_gi0[(size_t)2 * S * B * G3];          // fp32 gi0 [dir][t][b][3H]
__device__ bf16  g_xp[2][(size_t)B * S * D];             // input hi/lo planes (planar)
__device__ bf16  g_wp[2][2][(size_t)G3 * D];             // Wih layer0 [dir][plane] (planar)
__device__ float g_h0f[2][2][B * H];                     // [parity][dir]
__device__ float g_h1f[2][2][B * H];
// unified h planes, mma-frag layout: sel = layer*4 + parity*2 + dir; [sel][plane][...]
__device__ u32   g_hp[8][2][16384];
__device__ unsigned g_arrive2[2];
__device__ unsigned g_release2[2];

// ---------------- helpers ----------------
__device__ __forceinline__ void split_bf(float v, bf16& hi, bf16& lo) {
    hi = __float2bfloat16(v);
    lo = __float2bfloat16(v - __bfloat162float(hi));
}
__device__ __forceinline__ u32 pack2(bf16 a, bf16 b) {
    return (u32)__bfloat16_as_ushort(a) | ((u32)__bfloat16_as_ushort(b) << 16);
}
__device__ __forceinline__ float sigm(float x) { return 1.0f / (1.0f + expf(-x)); }

// byte offset of h value (batch b, hidden k) inside a frag-layout plane
__device__ __forceinline__ int frag_byte(int b, int k) {
    int kblk = k >> 4, c = k & 15, mt = b >> 4, r = b & 15;
    int lane = (r & 7) * 4 + ((c & 7) >> 1);
    int reg  = (r >> 3) + 2 * (c >> 3);
    return ((kblk * 512 + mt * 128 + lane * 4 + reg) << 2) + ((c & 1) << 1);
}

__device__ __forceinline__ void mma16816(float* d, const u32* a, u32 b0, u32 b1) {
    asm volatile("mma.sync.aligned.m16n8k16.row.col.f32.bf16.bf16.f32 "
                 "{%0,%1,%2,%3},{%4,%5,%6,%7},{%8,%9},{%0,%1,%2,%3};"
                 : "+f"(d[0]), "+f"(d[1]), "+f"(d[2]), "+f"(d[3])
                 : "r"(a[0]), "r"(a[1]), "r"(a[2]), "r"(a[3]), "r"(b0), "r"(b1));
}
__device__ __forceinline__ void ldm4(u32* r, const void* p) {
    u32 s = (u32)__cvta_generic_to_shared(p);
    asm volatile("ldmatrix.sync.aligned.m8n8.x4.shared.b16 {%0,%1,%2,%3},[%4];"
                 : "=r"(r[0]), "=r"(r[1]), "=r"(r[2]), "=r"(r[3]) : "r"(s));
}
__device__ __forceinline__ void cp16(void* smem_dst, const void* gsrc) {
    u32 s = (u32)__cvta_generic_to_shared(smem_dst);
    asm volatile("cp.async.cg.shared.global [%0], [%1], 16;" :: "r"(s), "l"(gsrc));
}

// ---------------- conv_xw: input + Wih0 -> planar hi/lo bf16 planes ----------------
__global__ void conv_xw(const float* __restrict__ x,
                        const float* __restrict__ wf, const float* __restrict__ wb) {
    if (blockIdx.x < 16384) {
        size_t i = ((size_t)blockIdx.x * 256 + threadIdx.x) * 4;
        float4 v = *(const float4*)&x[i];
        bf16 h0, l0, h1, l1, h2, l2, h3, l3;
        split_bf(v.x, h0, l0); split_bf(v.y, h1, l1);
        split_bf(v.z, h2, l2); split_bf(v.w, h3, l3);
        u32* ph = (u32*)&g_xp[0][i];
        u32* pl = (u32*)&g_xp[1][i];
        ph[0] = pack2(h0, h1); ph[1] = pack2(h2, h3);
        pl[0] = pack2(l0, l1); pl[1] = pack2(l2, l3);
    } else {
        size_t j = ((size_t)(blockIdx.x - 16384) * 256 + threadIdx.x) * 4;
        int d = j >= (size_t)G3 * D;
        size_t off = d ? j - (size_t)G3 * D : j;
        const float* src = d ? wb : wf;
        float4 v = *(const float4*)&src[off];
        bf16 h0, l0, h1, l1, h2, l2, h3, l3;
        split_bf(v.x, h0, l0); split_bf(v.y, h1, l1);
        split_bf(v.z, h2, l2); split_bf(v.w, h3, l3);
        u32* ph = (u32*)&g_wp[d][0][off];
        u32* pl = (u32*)&g_wp[d][1][off];
        ph[0] = pack2(h0, h1); ph[1] = pack2(h2, h3);
        pl[0] = pack2(l0, l1); pl[1] = pack2(l2, l3);
    }
}

// ---------------- init: hidden states (fp32 + frag planes) + barrier reset ----------------
__global__ void init_h(const float* __restrict__ enc) {
    if (blockIdx.x == 0 && threadIdx.x < 2) {
        g_arrive2[threadIdx.x] = 0;
        g_release2[threadIdx.x] = 0;
    }
    int idx = blockIdx.x * blockDim.x + threadIdx.x;   // 131072
    int layer = idx >> 16;
    int rem = idx & 65535;
    int dir = rem >> 15;
    int rem2 = rem & 32767;
    int b = rem2 >> 9;
    int n = rem2 & 511;
    float v = enc[(layer * B + b) * (2 * H) + dir * H + n];
    bf16 hi, lo; split_bf(v, hi, lo);
    int off = frag_byte(b, n);
    int sel = layer * 4 + dir;                 // parity 0
    if (layer == 0) g_h0f[0][dir][b * H + n] = v;
    else            g_h1f[0][dir][b * H + n] = v;
    *(bf16*)((char*)g_hp[sel][0] + off) = hi;
    *(bf16*)((char*)g_hp[sel][1] + off) = lo;
}

// ---------------- gi0 = input @ Wih0^T + bih0, smem-staged split-bf16 mma ----------------
__global__ void __launch_bounds__(256, 3)
gemm_gi0(const float* __restrict__ bf_, const float* __restrict__ bb_) {
    extern __shared__ char sm2[];
    char* Wbuf0 = sm2;
    char* Wbuf1 = sm2 + 18432;
    char* Xbuf0 = sm2 + 36864;
    char* Xbuf1 = sm2 + 55296;

    int s  = blockIdx.x;
    int nb = blockIdx.y;
    int d  = blockIdx.z;
    const float* bias = d ? bb_ : bf_;

    int tid = threadIdx.x;
    int w = tid >> 5, l = tid & 31;
    int mtile = w & 3, m0 = mtile * 16, nh = w >> 2;

    const char* wsrc[2] = { (const char*)&g_wp[d][0][(size_t)(nb * 64) * D],
                            (const char*)&g_wp[d][1][(size_t)(nb * 64) * D] };
    const char* xsrc[2] = { (const char*)&g_xp[0][0], (const char*)&g_xp[1][0] };

    float acc[4][4];
#pragma unroll
    for (int nt = 0; nt < 4; nt++) { acc[nt][0] = acc[nt][1] = acc[nt][2] = acc[nt][3] = 0.f; }

    auto stage = [&](int c, char* Wb, char* Xb) {
#pragma unroll
        for (int i = 0; i < 4; i++) {
            int idx = i * 256 + tid;
            int pl = idx >> 9, row = (idx >> 3) & 63, seg = idx & 7;
            cp16(Wb + pl * 9216 + row * 144 + seg * 16,
                 wsrc[pl] + (size_t)row * 1024 + c * 128 + seg * 16);
        }
#pragma unroll
        for (int i = 0; i < 4; i++) {
            int idx = i * 256 + tid;
            int pl = idx >> 9, row = (idx >> 3) & 63, seg = idx & 7;
            cp16(Xb + pl * 9216 + row * 144 + seg * 16,
                 xsrc[pl] + (size_t)row * 524288 + (size_t)s * 1024 + c * 128 + seg * 16);
        }
        asm volatile("cp.async.commit_group;");
    };

    stage(0, Wbuf0, Xbuf0);

    for (int c = 0; c < 8; c++) {
        asm volatile("cp.async.wait_group 0;");
        __syncthreads();
        if (c < 7) stage(c + 1, (c & 1) ? Wbuf0 : Wbuf1, (c & 1) ? Xbuf0 : Xbuf1);
        char* Wb = (c & 1) ? Wbuf1 : Wbuf0;
        char* Xb = (c & 1) ? Xbuf1 : Xbuf0;
#pragma unroll
        for (int kl = 0; kl < 4; kl++) {
            u32 ah[4], al[4];
            int aoff = (m0 + (l & 15)) * 144 + kl * 32 + (l >> 4) * 16;
            ldm4(ah, Xb + aoff);
            ldm4(al, Xb + 9216 + aoff);
            const u32* Wh = (const u32*)Wb;
            const u32* Wl = (const u32*)(Wb + 9216);
#pragma unroll
            for (int nt = 0; nt < 4; nt++) {
                int nrow = nh * 32 + nt * 8 + (l >> 2);
                int wi = nrow * 36 + kl * 8 + (l & 3);
                u32 bh0 = Wh[wi], bh1 = Wh[wi + 4];
                u32 bl0 = Wl[wi], bl1 = Wl[wi + 4];
                mma16816(acc[nt], ah, bh0, bh1);
                mma16816(acc[nt], al, bh0, bh1);
                mma16816(acc[nt], ah, bl0, bl1);
            }
        }
    }

#pragma unroll
    for (int nt = 0; nt < 4; nt++) {
        int col = nb * 64 + nh * 32 + nt * 8 + 2 * (l & 3);
        float2 bi = *(const float2*)&bias[col];
        int b0 = m0 + (l >> 2);
        float2 v0 = make_float2(acc[nt][0] + bi.x, acc[nt][1] + bi.y);
        float2 v1 = make_float2(acc[nt][2] + bi.x, acc[nt][3] + bi.y);
        *(float2*)&g_gi0[(((size_t)d * S + s) * B + b0) * G3 + col] = v0;
        *(float2*)&g_gi0[(((size_t)d * S + s) * B + b0 + 8) * G3 + col] = v1;
    }
}

// ---------------- per-dir grid barrier (R7 proven design) ----------------
__device__ __forceinline__ void grid_bar(int dir, unsigned target) {
    __syncthreads();
    if (threadIdx.x == 0) {
        __threadfence();
        unsigned v = atomicAdd(&g_arrive2[dir], 1u) + 1u;
        if (v == target * 64u) {
            asm volatile("st.release.gpu.u32 [%0], %1;" :: "l"(&g_release2[dir]), "r"(target) : "memory");
        } else {
            unsigned r;
            do {
                asm volatile("ld.acquire.gpu.u32 %0, [%1];" : "=r"(r) : "l"(&g_release2[dir]) : "memory");
            } while (r < target);
        }
    }
    __syncthreads();
}

// ---------------- persistent recurrence kernel ----------------
// grid 128 (2 dir x 64 hgroups of 8), 512 thr = 16 warps (mtile x4, ksub x4).
// smem: WS 152064 | G0 19968 | G1 19968 | GI0S 6144 = 198144 B
// Epilogue: thread halves run L0/L1 concurrently; each thread owns a row PAIR
// (sharing one frag u32) -> packed u32 plane stores.
__global__ void __launch_bounds__(512, 1)
gru_persist(const float* __restrict__ Wih_f, const float* __restrict__ Wih_b,
            const float* __restrict__ Whh_f, const float* __restrict__ Whh_b,
            const float* __restrict__ bih_f, const float* __restrict__ bih_b,
            const float* __restrict__ bhh_f, const float* __restrict__ bhh_b,
            float* __restrict__ out) {
    extern __shared__ char smem[];
    u32*  WS    = (u32*)smem;                    // [(mat*2+plane)*24 + n][264]
    float* G0   = (float*)(smem + 152064);       // partials ksub{0,1}
    float* G1   = (float*)(smem + 172032);       // partials ksub{2,3}
    float* GI0S = (float*)(smem + 192000);       // [64][24]

    const int tid = threadIdx.x;
    const int bid = blockIdx.x;
    const int dir = bid >> 6;
    const int hb  = (bid & 63) * 8;
    const int w = tid >> 5, l = tid & 31;
    const int mtile = w & 3, m0 = mtile * 16, ksub = w >> 2;

    const float* Wih = dir ? Wih_b : Wih_f;
    const float* Whh = dir ? Whh_b : Whh_f;
    const float* bih = dir ? bih_b : bih_f;
    const float* bhh = dir ? bhh_b : bhh_f;
    const float* bhh0 = bhh;
    const float* bi1 = bih + G3;
    const float* bh1 = bhh + G3;

    // ---- one-time weight staging: bf16 hi/lo, (k,k+8)-interleaved u32 pairs ----
    {
        const float* Wmat[3] = { Whh, Wih + (size_t)G3 * D, Whh + (size_t)G3 * H };
#pragma unroll 4
        for (int i = 0; i < 36; i++) {
            int item = tid + 512 * i;            // < 18432
            int m3 = item / 6144;
            int rem = item - m3 * 6144;
            int n = rem >> 8;
            int k2 = rem & 255;
            int grow = (n >> 3) * H + hb + (n & 7);
            float2 v = *(const float2*)(Wmat[m3] + (size_t)grow * 512 + 2 * k2);
            bf16 h0, l0, h1, l1;
            split_bf(v.x, h0, l0); split_bf(v.y, h1, l1);
            int j = k2 & 7;
            int col = ((k2 >> 3) << 3) + ((j & 3) << 1) + (j >> 2);
            WS[((m3 * 2 + 0) * 24 + n) * 264 + col] = pack2(h0, h1);
            WS[((m3 * 2 + 1) * 24 + n) * 264 + col] = pack2(l0, l1);
        }
    }

    // ---- epilogue ownership: half 0 -> L0, half 1 -> L1; row pair (r0, r0+1) ----
    const int half = tid >> 8;
    const int emm  = tid & 63;
    const int q    = (tid >> 6) & 3;
    const int j0   = 2 * q;
    const int er0  = hb + j0;
    float hpA, hpB;
    if (half == 0) {
        hpA = g_h0f[0][dir][emm * H + er0];
        hpB = g_h0f[0][dir][emm * H + er0 + 1];
    } else {
        hpA = g_h1f[0][dir][emm * H + er0];
        hpB = g_h1f[0][dir][emm * H + er0 + 1];
    }
    const int eidx = frag_byte(emm, er0) >> 2;   // u32 index shared by the row pair

    const int rowoff = (l >> 2) * 264 + 2 * (l & 3) + ksub * 8;
    const int fbase  = mtile * 128 + l * 4;

    for (int p = 0; p <= S; p++) {
        const u32* Xb = g_hp[(p & 1) * 2 + dir][0];            // layer0 planes (lo at +16384)
        const u32* Hb = g_hp[4 + ((p + 1) & 1) * 2 + dir][0];  // layer1 planes

        // gi0 prefetch (used in L0 epilogue)
        if (p < S) {
            int tt0 = dir ? (S - 1 - p) : p;
            const float* gi = &g_gi0[((size_t)dir * S + tt0) * B * G3];
            if (tid < 384) {
                int mm = tid / 6, r = tid % 6;
                int gate = r >> 1, hf = r & 1;
                cp16(&GI0S[mm * 24 + gate * 8 + hf * 4],
                     gi + mm * G3 + gate * H + hb + hf * 4);
            }
            asm volatile("cp.async.commit_group;");
        }

        float acc[3][3][4];
#pragma unroll
        for (int m3 = 0; m3 < 3; m3++)
#pragma unroll
            for (int nt = 0; nt < 3; nt++)
                acc[m3][nt][0] = acc[m3][nt][1] = acc[m3][nt][2] = acc[m3][nt][3] = 0.f;

        u32 f0[4][4], f1[4][4];
        {
            int idx = ksub * 512 + fbase;
            uint4 v;
            v = __ldcg((const uint4*)(Xb + idx));
            f0[0][0] = v.x; f0[0][1] = v.y; f0[0][2] = v.z; f0[0][3] = v.w;
            v = __ldcg((const uint4*)(Xb + 16384 + idx));
            f0[1][0] = v.x; f0[1][1] = v.y; f0[1][2] = v.z; f0[1][3] = v.w;
            v = __ldcg((const uint4*)(Hb + idx));
            f0[2][0] = v.x; f0[2][1] = v.y; f0[2][2] = v.z; f0[2][3] = v.w;
            v = __ldcg((const uint4*)(Hb + 16384 + idx));
            f0[3][0] = v.x; f0[3][1] = v.y; f0[3][2] = v.z; f0[3][3] = v.w;
        }

#pragma unroll
        for (int c = 0; c < 8; c++) {
            if (c < 7) {
                int idx = ((c + 1) * 4 + ksub) * 512 + fbase;
                u32 (*Fn)[4] = (c & 1) ? f0 : f1;
                uint4 v;
                v = __ldcg((const uint4*)(Xb + idx));
                Fn[0][0] = v.x; Fn[0][1] = v.y; Fn[0][2] = v.z; Fn[0][3] = v.w;
                v = __ldcg((const uint4*)(Xb + 16384 + idx));
                Fn[1][0] = v.x; Fn[1][1] = v.y; Fn[1][2] = v.z; Fn[1][3] = v.w;
                v = __ldcg((const uint4*)(Hb + idx));
                Fn[2][0] = v.x; Fn[2][1] = v.y; Fn[2][2] = v.z; Fn[2][3] = v.w;
                v = __ldcg((const uint4*)(Hb + 16384 + idx));
                Fn[3][0] = v.x; Fn[3][1] = v.y; Fn[3][2] = v.z; Fn[3][3] = v.w;
            }
            u32 (*Af)[4] = (c & 1) ? f1 : f0;
            const int cb = rowoff + c * 32;
#pragma unroll
            for (int m3 = 0; m3 < 3; m3++) {
                const u32* Ahi = (m3 == 2) ? Af[2] : Af[0];
                const u32* Alo = (m3 == 2) ? Af[3] : Af[1];
                const u32* WH = WS + (m3 * 2) * 24 * 264 + cb;
                const u32* WL = WH + 24 * 264;
#pragma unroll
                for (int nt = 0; nt < 3; nt++) {
                    ull wh64 = *(const ull*)(WH + nt * 8 * 264);
                    ull wl64 = *(const ull*)(WL + nt * 8 * 264);
                    u32 bh0 = (u32)wh64, bh1 = (u32)(wh64 >> 32);
                    u32 bl0 = (u32)wl64, bl1 = (u32)(wl64 >> 32);
                    mma16816(acc[m3][nt], Ahi, bh0, bh1);
                    mma16816(acc[m3][nt], Alo, bh0, bh1);
                    mma16816(acc[m3][nt], Ahi, bl0, bl1);
                }
            }
        }

        // ---- pairwise K-split reduction: ksub{0,2} write, ksub{1,3} accumulate ----
        __syncthreads();
        {
            float* Gb = (ksub & 2) ? G1 : G0;
            if ((ksub & 1) == 0) {
#pragma unroll
                for (int m3 = 0; m3 < 3; m3++) {
                    float* G = Gb + m3 * 1664;
#pragma unroll
                    for (int nt = 0; nt < 3; nt++) {
                        int col = nt * 8 + 2 * (l & 3);
                        int r0 = m0 + (l >> 2);
                        *(float2*)&G[r0 * 26 + col] =
                            make_float2(acc[m3][nt][0], acc[m3][nt][1]);
                        *(float2*)&G[(r0 + 8) * 26 + col] =
                            make_float2(acc[m3][nt][2], acc[m3][nt][3]);
                    }
                }
            }
            __syncthreads();
            if (ksub & 1) {
#pragma unroll
                for (int m3 = 0; m3 < 3; m3++) {
                    float* G = Gb + m3 * 1664;
#pragma unroll
                    for (int nt = 0; nt < 3; nt++) {
                        int col = nt * 8 + 2 * (l & 3);
                        int r0 = m0 + (l >> 2);
                        float2* p0 = (float2*)&G[r0 * 26 + col];
                        float2* p1 = (float2*)&G[(r0 + 8) * 26 + col];
                        float2 o0 = *p0, o1 = *p1;
                        *p0 = make_float2(o0.x + acc[m3][nt][0], o0.y + acc[m3][nt][1]);
                        *p1 = make_float2(o1.x + acc[m3][nt][2], o1.y + acc[m3][nt][3]);
                    }
                }
            }
            __syncthreads();
        }
        asm volatile("cp.async.wait_group 0;");

        if (half == 0) {
            // ---- L0 epilogue: t = p (row pair er0, er0+1) ----
            if (p < S) {
                u32* Xn = g_hp[((p + 1) & 1) * 2 + dir][0];
                float hnA, hnB;
                {
                    float hr = G0[emm * 26 + j0]      + G1[emm * 26 + j0]      + bhh0[er0];
                    float hz = G0[emm * 26 + 8 + j0]  + G1[emm * 26 + 8 + j0]  + bhh0[H + er0];
                    float hn = G0[emm * 26 + 16 + j0] + G1[emm * 26 + 16 + j0] + bhh0[2 * H + er0];
                    float rr = sigm(GI0S[emm * 24 + j0] + hr);
                    float zz = sigm(GI0S[emm * 24 + 8 + j0] + hz);
                    float nn = tanhf(GI0S[emm * 24 + 16 + j0] + rr * hn);
                    hnA = (1.0f - zz) * nn + zz * hpA;
                }
                {
                    int j1 = j0 + 1, er1 = er0 + 1;
                    float hr = G0[emm * 26 + j1]      + G1[emm * 26 + j1]      + bhh0[er1];
                    float hz = G0[emm * 26 + 8 + j1]  + G1[emm * 26 + 8 + j1]  + bhh0[H + er1];
                    float hn = G0[emm * 26 + 16 + j1] + G1[emm * 26 + 16 + j1] + bhh0[2 * H + er1];
                    float rr = sigm(GI0S[emm * 24 + j1] + hr);
                    float zz = sigm(GI0S[emm * 24 + 8 + j1] + hz);
                    float nn = tanhf(GI0S[emm * 24 + 16 + j1] + rr * hn);
                    hnB = (1.0f - zz) * nn + zz * hpB;
                }
                hpA = hnA; hpB = hnB;
                bf16 hiA, loA, hiB, loB;
                split_bf(hnA, hiA, loA);
                split_bf(hnB, hiB, loB);
                Xn[eidx]         = pack2(hiA, hiB);
                Xn[16384 + eidx] = pack2(loA, loB);
                if (p == S - 1) {
                    g_h0f[0][dir][emm * H + er0]     = hnA;
                    g_h0f[0][dir][emm * H + er0 + 1] = hnB;
                }
            }
        } else {
            // ---- L1 epilogue: t = p-1 ----
            if (p >= 1) {
                int t1 = p - 1;
                int tt = dir ? (S - 1 - t1) : t1;
                u32* Hn = g_hp[4 + (p & 1) * 2 + dir][0];
                float hnA, hnB;
                {
                    float ir  = G0[1664 + emm * 26 + j0]      + G1[1664 + emm * 26 + j0]      + bi1[er0];
                    float iz  = G0[1664 + emm * 26 + 8 + j0]  + G1[1664 + emm * 26 + 8 + j0]  + bi1[H + er0];
                    float inn = G0[1664 + emm * 26 + 16 + j0] + G1[1664 + emm * 26 + 16 + j0] + bi1[2 * H + er0];
                    float hr  = G0[3328 + emm * 26 + j0]      + G1[3328 + emm * 26 + j0]      + bh1[er0];
                    float hz  = G0[3328 + emm * 26 + 8 + j0]  + G1[3328 + emm * 26 + 8 + j0]  + bh1[H + er0];
                    float hn  = G0[3328 + emm * 26 + 16 + j0] + G1[3328 + emm * 26 + 16 + j0] + bh1[2 * H + er0];
                    float rr = sigm(ir + hr);
                    float zz = sigm(iz + hz);
                    float nn = tanhf(inn + rr * hn);
                    hnA = (1.0f - zz) * nn + zz * hpA;
                }
                {
                    int j1 = j0 + 1, er1 = er0 + 1;
                    float ir  = G0[1664 + emm * 26 + j1]      + G1[1664 + emm * 26 + j1]      + bi1[er1];
                    float iz  = G0[1664 + emm * 26 + 8 + j1]  + G1[1664 + emm * 26 + 8 + j1]  + bi1[H + er1];
                    float inn = G0[1664 + emm * 26 + 16 + j1] + G1[1664 + emm * 26 + 16 + j1] + bi1[2 * H + er1];
                    float hr  = G0[3328 + emm * 26 + j1]      + G1[3328 + emm * 26 + j1]      + bh1[er1];
                    float hz  = G0[3328 + emm * 26 + 8 + j1]  + G1[3328 + emm * 26 + 8 + j1]  + bh1[H + er1];
                    float hn  = G0[3328 + emm * 26 + 16 + j1] + G1[3328 + emm * 26 + 16 + j1] + bh1[2 * H + er1];
                    float rr = sigm(ir + hr);
                    float zz = sigm(iz + hz);
                    float nn = tanhf(inn + rr * hn);
                    hnB = (1.0f - zz) * nn + zz * hpB;
                }
                hpA = hnA; hpB = hnB;
                bf16 hiA, loA, hiB, loB;
                split_bf(hnA, hiA, loA);
                split_bf(hnB, hiB, loB);
                Hn[eidx]         = pack2(hiA, hiB);
                Hn[16384 + eidx] = pack2(loA, loB);
                *(float2*)&out[(size_t)emm * (S * 2 * H) + (size_t)tt * (2 * H) + dir * H + er0] =
                    make_float2(hnA, hnB);
                if (p == S) {
                    g_h1f[0][dir][emm * H + er0]     = hnA;
                    g_h1f[0][dir][emm * H + er0 + 1] = hnB;
                }
            }
        }

        grid_bar(dir, (unsigned)(p + 1));
    }

    // ---- final hidden state copy (own dir; parity 0) ----
#pragma unroll
    for (int it = 0; it < 2; it++) {
        int local = (bid & 63) * 1024 + it * 512 + tid;   // < 65536 per dir
        int lyr = local >> 15;
        int rem = local & 32767;
        int b = rem >> 9;
        int n = rem & 511;
        float v = lyr ? __ldcg(&g_h1f[0][dir][b * H + n]) : __ldcg(&g_h0f[0][dir][b * H + n]);
        out[(size_t)B * S * 2 * H + ((size_t)lyr * B + b) * (2 * H) + dir * H + n] = v;
    }
}

// ---------------- launch ----------------
extern "C" void kernel_launch(void* const* d_in, const int* in_sizes, int n_in,
                              void* d_out, int out_size) {
    const float* input  = (const float*)d_in[0];
    const float* enc    = (const float*)d_in[1];
    const float* Wih_f  = (const float*)d_in[2];
    const float* Whh_f  = (const float*)d_in[3];
    const float* bih_f  = (const float*)d_in[4];
    const float* bhh_f  = (const float*)d_in[5];
    const float* Wih_b  = (const float*)d_in[6];
    const float* Whh_b  = (const float*)d_in[7];
    const float* bih_b  = (const float*)d_in[8];
    const float* bhh_b  = (const float*)d_in[9];
    float* out = (float*)d_out;

    const int SMEM_G = 73728;
    const int SMEM_P = 198144;
    static int configured = 0;
    if (!configured) {
        cudaFuncSetAttribute(gemm_gi0, cudaFuncAttributeMaxDynamicSharedMemorySize, SMEM_G);
        cudaFuncSetAttribute(gru_persist, cudaFuncAttributeMaxDynamicSharedMemorySize, SMEM_P);
        configured = 1;
    }

    conv_xw<<<17920, 256>>>(input, Wih_f, Wih_b);
    init_h<<<512, 256>>>(enc);
    gemm_gi0<<<dim3(S, 24, 2), 256, SMEM_G>>>(bih_f, bih_b);
    gru_persist<<<NBLK, 512, SMEM_P>>>(Wih_f, Wih_b, Whh_f, Whh_b,
                                       bih_f, bih_b, bhh_f, bhh_b, out);
}

// round 14
// speedup vs baseline: 1.8221x; 1.0664x over previous
#include <cuda_runtime.h>
#include <cuda_bf16.h>
#include <math.h>

#define S 512
#define B 64
#define H 512
#define D 512
#define G3 1536
#define NBLK 128

typedef unsigned u32;
typedef unsigned long long ull;
typedef __nv_bfloat16 bf16;

// ---------------- device-global scratch (allocation-free rule) ----------------
__device__ float g_gi0[(size_t)2 * S * B * G3];          // fp32 gi0 [dir][t][b][3H]
__device__ bf16  g_xp[2][(size_t)B * S * D];             // input hi/lo planes (planar)
__device__ bf16  g_wp[2][2][(size_t)G3 * D];             // Wih layer0 [dir][plane] (planar)
__device__ float g_h0f[2][2][B * H];                     // [parity][dir]
__device__ float g_h1f[2][2][B * H];
// unified h planes, mma-frag layout: sel = layer*4 + parity*2 + dir; [sel][plane][...]
__device__ u32   g_hp[8][2][16384];
__device__ unsigned g_arrive2[2];

// ---------------- helpers ----------------
__device__ __forceinline__ void split_bf(float v, bf16& hi, bf16& lo) {
    hi = __float2bfloat16(v);
    lo = __float2bfloat16(v - __bfloat162float(hi));
}
__device__ __forceinline__ u32 pack2(bf16 a, bf16 b) {
    return (u32)__bfloat16_as_ushort(a) | ((u32)__bfloat16_as_ushort(b) << 16);
}
__device__ __forceinline__ float sigm(float x) { return 1.0f / (1.0f + expf(-x)); }

// byte offset of h value (batch b, hidden k) inside a frag-layout plane
__device__ __forceinline__ int frag_byte(int b, int k) {
    int kblk = k >> 4, c = k & 15, mt = b >> 4, r = b & 15;
    int lane = (r & 7) * 4 + ((c & 7) >> 1);
    int reg  = (r >> 3) + 2 * (c >> 3);
    return ((kblk * 512 + mt * 128 + lane * 4 + reg) << 2) + ((c & 1) << 1);
}

__device__ __forceinline__ void mma16816(float* d, const u32* a, u32 b0, u32 b1) {
    asm volatile("mma.sync.aligned.m16n8k16.row.col.f32.bf16.bf16.f32 "
                 "{%0,%1,%2,%3},{%4,%5,%6,%7},{%8,%9},{%0,%1,%2,%3};"
                 : "+f"(d[0]), "+f"(d[1]), "+f"(d[2]), "+f"(d[3])
                 : "r"(a[0]), "r"(a[1]), "r"(a[2]), "r"(a[3]), "r"(b0), "r"(b1));
}
__device__ __forceinline__ void ldm4(u32* r, const void* p) {
    u32 s = (u32)__cvta_generic_to_shared(p);
    asm volatile("ldmatrix.sync.aligned.m8n8.x4.shared.b16 {%0,%1,%2,%3},[%4];"
                 : "=r"(r[0]), "=r"(r[1]), "=r"(r[2]), "=r"(r[3]) : "r"(s));
}
__device__ __forceinline__ void cp16(void* smem_dst, const void* gsrc) {
    u32 s = (u32)__cvta_generic_to_shared(smem_dst);
    asm volatile("cp.async.cg.shared.global [%0], [%1], 16;" :: "r"(s), "l"(gsrc));
}

// ---------------- conv_xw: input + Wih0 -> planar hi/lo bf16 planes ----------------
__global__ void conv_xw(const float* __restrict__ x,
                        const float* __restrict__ wf, const float* __restrict__ wb) {
    if (blockIdx.x < 16384) {
        size_t i = ((size_t)blockIdx.x * 256 + threadIdx.x) * 4;
        float4 v = *(const float4*)&x[i];
        bf16 h0, l0, h1, l1, h2, l2, h3, l3;
        split_bf(v.x, h0, l0); split_bf(v.y, h1, l1);
        split_bf(v.z, h2, l2); split_bf(v.w, h3, l3);
        u32* ph = (u32*)&g_xp[0][i];
        u32* pl = (u32*)&g_xp[1][i];
        ph[0] = pack2(h0, h1); ph[1] = pack2(h2, h3);
        pl[0] = pack2(l0, l1); pl[1] = pack2(l2, l3);
    } else {
        size_t j = ((size_t)(blockIdx.x - 16384) * 256 + threadIdx.x) * 4;
        int d = j >= (size_t)G3 * D;
        size_t off = d ? j - (size_t)G3 * D : j;
        const float* src = d ? wb : wf;
        float4 v = *(const float4*)&src[off];
        bf16 h0, l0, h1, l1, h2, l2, h3, l3;
        split_bf(v.x, h0, l0); split_bf(v.y, h1, l1);
        split_bf(v.z, h2, l2); split_bf(v.w, h3, l3);
        u32* ph = (u32*)&g_wp[d][0][off];
        u32* pl = (u32*)&g_wp[d][1][off];
        ph[0] = pack2(h0, h1); ph[1] = pack2(h2, h3);
        pl[0] = pack2(l0, l1); pl[1] = pack2(l2, l3);
    }
}

// ---------------- init: hidden states (fp32 + frag planes) + barrier reset ----------------
__global__ void init_h(const float* __restrict__ enc) {
    if (blockIdx.x == 0 && threadIdx.x < 2) {
        g_arrive2[threadIdx.x] = 0;
    }
    int idx = blockIdx.x * blockDim.x + threadIdx.x;   // 131072
    int layer = idx >> 16;
    int rem = idx & 65535;
    int dir = rem >> 15;
    int rem2 = rem & 32767;
    int b = rem2 >> 9;
    int n = rem2 & 511;
    float v = enc[(layer * B + b) * (2 * H) + dir * H + n];
    bf16 hi, lo; split_bf(v, hi, lo);
    int off = frag_byte(b, n);
    int sel = layer * 4 + dir;                 // parity 0
    if (layer == 0) g_h0f[0][dir][b * H + n] = v;
    else            g_h1f[0][dir][b * H + n] = v;
    *(bf16*)((char*)g_hp[sel][0] + off) = hi;
    *(bf16*)((char*)g_hp[sel][1] + off) = lo;
}

// ---------------- gi0 = input @ Wih0^T + bih0, smem-staged split-bf16 mma ----------------
__global__ void __launch_bounds__(256, 3)
gemm_gi0(const float* __restrict__ bf_, const float* __restrict__ bb_) {
    extern __shared__ char sm2[];
    char* Wbuf0 = sm2;
    char* Wbuf1 = sm2 + 18432;
    char* Xbuf0 = sm2 + 36864;
    char* Xbuf1 = sm2 + 55296;

    int s  = blockIdx.x;
    int nb = blockIdx.y;
    int d  = blockIdx.z;
    const float* bias = d ? bb_ : bf_;

    int tid = threadIdx.x;
    int w = tid >> 5, l = tid & 31;
    int mtile = w & 3, m0 = mtile * 16, nh = w >> 2;

    const char* wsrc[2] = { (const char*)&g_wp[d][0][(size_t)(nb * 64) * D],
                            (const char*)&g_wp[d][1][(size_t)(nb * 64) * D] };
    const char* xsrc[2] = { (const char*)&g_xp[0][0], (const char*)&g_xp[1][0] };

    float acc[4][4];
#pragma unroll
    for (int nt = 0; nt < 4; nt++) { acc[nt][0] = acc[nt][1] = acc[nt][2] = acc[nt][3] = 0.f; }

    auto stage = [&](int c, char* Wb, char* Xb) {
#pragma unroll
        for (int i = 0; i < 4; i++) {
            int idx = i * 256 + tid;
            int pl = idx >> 9, row = (idx >> 3) & 63, seg = idx & 7;
            cp16(Wb + pl * 9216 + row * 144 + seg * 16,
                 wsrc[pl] + (size_t)row * 1024 + c * 128 + seg * 16);
        }
#pragma unroll
        for (int i = 0; i < 4; i++) {
            int idx = i * 256 + tid;
            int pl = idx >> 9, row = (idx >> 3) & 63, seg = idx & 7;
            cp16(Xb + pl * 9216 + row * 144 + seg * 16,
                 xsrc[pl] + (size_t)row * 524288 + (size_t)s * 1024 + c * 128 + seg * 16);
        }
        asm volatile("cp.async.commit_group;");
    };

    stage(0, Wbuf0, Xbuf0);

    for (int c = 0; c < 8; c++) {
        asm volatile("cp.async.wait_group 0;");
        __syncthreads();
        if (c < 7) stage(c + 1, (c & 1) ? Wbuf0 : Wbuf1, (c & 1) ? Xbuf0 : Xbuf1);
        char* Wb = (c & 1) ? Wbuf1 : Wbuf0;
        char* Xb = (c & 1) ? Xbuf1 : Xbuf0;
#pragma unroll
        for (int kl = 0; kl < 4; kl++) {
            u32 ah[4], al[4];
            int aoff = (m0 + (l & 15)) * 144 + kl * 32 + (l >> 4) * 16;
            ldm4(ah, Xb + aoff);
            ldm4(al, Xb + 9216 + aoff);
            const u32* Wh = (const u32*)Wb;
            const u32* Wl = (const u32*)(Wb + 9216);
#pragma unroll
            for (int nt = 0; nt < 4; nt++) {
                int nrow = nh * 32 + nt * 8 + (l >> 2);
                int wi = nrow * 36 + kl * 8 + (l & 3);
                u32 bh0 = Wh[wi], bh1 = Wh[wi + 4];
                u32 bl0 = Wl[wi], bl1 = Wl[wi + 4];
                mma16816(acc[nt], ah, bh0, bh1);
                mma16816(acc[nt], al, bh0, bh1);
                mma16816(acc[nt], ah, bl0, bl1);
            }
        }
    }

#pragma unroll
    for (int nt = 0; nt < 4; nt++) {
        int col = nb * 64 + nh * 32 + nt * 8 + 2 * (l & 3);
        float2 bi = *(const float2*)&bias[col];
        int b0 = m0 + (l >> 2);
        float2 v0 = make_float2(acc[nt][0] + bi.x, acc[nt][1] + bi.y);
        float2 v1 = make_float2(acc[nt][2] + bi.x, acc[nt][3] + bi.y);
        *(float2*)&g_gi0[(((size_t)d * S + s) * B + b0) * G3 + col] = v0;
        *(float2*)&g_gi0[(((size_t)d * S + s) * B + b0 + 8) * G3 + col] = v1;
    }
}

// ---------------- per-dir grid barrier v3: release-red arrive + counter poll ----------------
// bar.sync gives cta-scope happens-before into thread 0; red.release lifts to gpu
// scope (same recipe as cooperative-groups grid.sync). No __threadfence, no separate
// release word, no serialized returning atomics.
__device__ __forceinline__ void grid_bar(int dir, unsigned target) {
    __syncthreads();
    if (threadIdx.x == 0) {
        asm volatile("red.release.gpu.global.add.u32 [%0], 1;"
                     :: "l"(&g_arrive2[dir]) : "memory");
        unsigned r;
        do {
            asm volatile("ld.acquire.gpu.u32 %0, [%1];" : "=r"(r) : "l"(&g_arrive2[dir]) : "memory");
        } while (r < target * 64u);
    }
    __syncthreads();
}

// ---------------- persistent recurrence kernel ----------------
// grid 128 (2 dir x 64 hgroups of 8), 512 thr = 16 warps (mtile x4, ksub x4).
// smem: WS 152064 | G0 19968 | G1 19968 | GI0S 6144 = 198144 B
// Epilogue: thread halves run L0/L1 concurrently; each thread owns a row PAIR
// (sharing one frag u32) -> packed u32 plane stores.
__global__ void __launch_bounds__(512, 1)
gru_persist(const float* __restrict__ Wih_f, const float* __restrict__ Wih_b,
            const float* __restrict__ Whh_f, const float* __restrict__ Whh_b,
            const float* __restrict__ bih_f, const float* __restrict__ bih_b,
            const float* __restrict__ bhh_f, const float* __restrict__ bhh_b,
            float* __restrict__ out) {
    extern __shared__ char smem[];
    u32*  WS    = (u32*)smem;                    // [(mat*2+plane)*24 + n][264]
    float* G0   = (float*)(smem + 152064);       // partials ksub{0,1}
    float* G1   = (float*)(smem + 172032);       // partials ksub{2,3}
    float* GI0S = (float*)(smem + 192000);       // [64][24]

    const int tid = threadIdx.x;
    const int bid = blockIdx.x;
    const int dir = bid >> 6;
    const int hb  = (bid & 63) * 8;
    const int w = tid >> 5, l = tid & 31;
    const int mtile = w & 3, m0 = mtile * 16, ksub = w >> 2;

    const float* Wih = dir ? Wih_b : Wih_f;
    const float* Whh = dir ? Whh_b : Whh_f;
    const float* bih = dir ? bih_b : bih_f;
    const float* bhh = dir ? bhh_b : bhh_f;
    const float* bhh0 = bhh;
    const float* bi1 = bih + G3;
    const float* bh1 = bhh + G3;

    // ---- one-time weight staging: bf16 hi/lo, (k,k+8)-interleaved u32 pairs ----
    {
        const float* Wmat[3] = { Whh, Wih + (size_t)G3 * D, Whh + (size_t)G3 * H };
#pragma unroll 4
        for (int i = 0; i < 36; i++) {
            int item = tid + 512 * i;            // < 18432
            int m3 = item / 6144;
            int rem = item - m3 * 6144;
            int n = rem >> 8;
            int k2 = rem & 255;
            int grow = (n >> 3) * H + hb + (n & 7);
            float2 v = *(const float2*)(Wmat[m3] + (size_t)grow * 512 + 2 * k2);
            bf16 h0, l0, h1, l1;
            split_bf(v.x, h0, l0); split_bf(v.y, h1, l1);
            int j = k2 & 7;
            int col = ((k2 >> 3) << 3) + ((j & 3) << 1) + (j >> 2);
            WS[((m3 * 2 + 0) * 24 + n) * 264 + col] = pack2(h0, h1);
            WS[((m3 * 2 + 1) * 24 + n) * 264 + col] = pack2(l0, l1);
        }
    }

    // ---- epilogue ownership: half 0 -> L0, half 1 -> L1; row pair (r0, r0+1) ----
    const int half = tid >> 8;
    const int emm  = tid & 63;
    const int q    = (tid >> 6) & 3;
    const int j0   = 2 * q;
    const int er0  = hb + j0;
    float hpA, hpB;
    if (half == 0) {
        hpA = g_h0f[0][dir][emm * H + er0];
        hpB = g_h0f[0][dir][emm * H + er0 + 1];
    } else {
        hpA = g_h1f[0][dir][emm * H + er0];
        hpB = g_h1f[0][dir][emm * H + er0 + 1];
    }
    const int eidx = frag_byte(emm, er0) >> 2;   // u32 index shared by the row pair

    const int rowoff = (l >> 2) * 264 + 2 * (l & 3) + ksub * 8;
    const int fbase  = mtile * 128 + l * 4;

    for (int p = 0; p <= S; p++) {
        const u32* Xb = g_hp[(p & 1) * 2 + dir][0];            // layer0 planes (lo at +16384)
        const u32* Hb = g_hp[4 + ((p + 1) & 1) * 2 + dir][0];  // layer1 planes

        // gi0 prefetch (used in L0 epilogue)
        if (p < S) {
            int tt0 = dir ? (S - 1 - p) : p;
            const float* gi = &g_gi0[((size_t)dir * S + tt0) * B * G3];
            if (tid < 384) {
                int mm = tid / 6, r = tid % 6;
                int gate = r >> 1, hf = r & 1;
                cp16(&GI0S[mm * 24 + gate * 8 + hf * 4],
                     gi + mm * G3 + gate * H + hb + hf * 4);
            }
            asm volatile("cp.async.commit_group;");
        }

        float acc[3][3][4];
#pragma unroll
        for (int m3 = 0; m3 < 3; m3++)
#pragma unroll
            for (int nt = 0; nt < 3; nt++)
                acc[m3][nt][0] = acc[m3][nt][1] = acc[m3][nt][2] = acc[m3][nt][3] = 0.f;

        u32 f0[4][4], f1[4][4];
        {
            int idx = ksub * 512 + fbase;
            uint4 v;
            v = __ldcg((const uint4*)(Xb + idx));
            f0[0][0] = v.x; f0[0][1] = v.y; f0[0][2] = v.z; f0[0][3] = v.w;
            v = __ldcg((const uint4*)(Xb + 16384 + idx));
            f0[1][0] = v.x; f0[1][1] = v.y; f0[1][2] = v.z; f0[1][3] = v.w;
            v = __ldcg((const uint4*)(Hb + idx));
            f0[2][0] = v.x; f0[2][1] = v.y; f0[2][2] = v.z; f0[2][3] = v.w;
            v = __ldcg((const uint4*)(Hb + 16384 + idx));
            f0[3][0] = v.x; f0[3][1] = v.y; f0[3][2] = v.z; f0[3][3] = v.w;
        }

#pragma unroll
        for (int c = 0; c < 8; c++) {
            if (c < 7) {
                int idx = ((c + 1) * 4 + ksub) * 512 + fbase;
                u32 (*Fn)[4] = (c & 1) ? f0 : f1;
                uint4 v;
                v = __ldcg((const uint4*)(Xb + idx));
                Fn[0][0] = v.x; Fn[0][1] = v.y; Fn[0][2] = v.z; Fn[0][3] = v.w;
                v = __ldcg((const uint4*)(Xb + 16384 + idx));
                Fn[1][0] = v.x; Fn[1][1] = v.y; Fn[1][2] = v.z; Fn[1][3] = v.w;
                v = __ldcg((const uint4*)(Hb + idx));
                Fn[2][0] = v.x; Fn[2][1] = v.y; Fn[2][2] = v.z; Fn[2][3] = v.w;
                v = __ldcg((const uint4*)(Hb + 16384 + idx));
                Fn[3][0] = v.x; Fn[3][1] = v.y; Fn[3][2] = v.z; Fn[3][3] = v.w;
            }
            u32 (*Af)[4] = (c & 1) ? f1 : f0;
            const int cb = rowoff + c * 32;
#pragma unroll
            for (int m3 = 0; m3 < 3; m3++) {
                const u32* Ahi = (m3 == 2) ? Af[2] : Af[0];
                const u32* Alo = (m3 == 2) ? Af[3] : Af[1];
                const u32* WH = WS + (m3 * 2) * 24 * 264 + cb;
                const u32* WL = WH + 24 * 264;
#pragma unroll
                for (int nt = 0; nt < 3; nt++) {
                    ull wh64 = *(const ull*)(WH + nt * 8 * 264);
                    ull wl64 = *(const ull*)(WL + nt * 8 * 264);
                    u32 bh0 = (u32)wh64, bh1 = (u32)(wh64 >> 32);
                    u32 bl0 = (u32)wl64, bl1 = (u32)(wl64 >> 32);
                    mma16816(acc[m3][nt], Ahi, bh0, bh1);
                    mma16816(acc[m3][nt], Alo, bh0, bh1);
                    mma16816(acc[m3][nt], Ahi, bl0, bl1);
                }
            }
        }

        // ---- pairwise K-split reduction: ksub{0,2} write, ksub{1,3} accumulate ----
        __syncthreads();
        {
            float* Gb = (ksub & 2) ? G1 : G0;
            if ((ksub & 1) == 0) {
#pragma unroll
                for (int m3 = 0; m3 < 3; m3++) {
                    float* G = Gb + m3 * 1664;
#pragma unroll
                    for (int nt = 0; nt < 3; nt++) {
                        int col = nt * 8 + 2 * (l & 3);
                        int r0 = m0 + (l >> 2);
                        *(float2*)&G[r0 * 26 + col] =
                            make_float2(acc[m3][nt][0], acc[m3][nt][1]);
                        *(float2*)&G[(r0 + 8) * 26 + col] =
                            make_float2(acc[m3][nt][2], acc[m3][nt][3]);
                    }
                }
            }
            __syncthreads();
            if (ksub & 1) {
#pragma unroll
                for (int m3 = 0; m3 < 3; m3++) {
                    float* G = Gb + m3 * 1664;
#pragma unroll
                    for (int nt = 0; nt < 3; nt++) {
                        int col = nt * 8 + 2 * (l & 3);
                        int r0 = m0 + (l >> 2);
                        float2* p0 = (float2*)&G[r0 * 26 + col];
                        float2* p1 = (float2*)&G[(r0 + 8) * 26 + col];
                        float2 o0 = *p0, o1 = *p1;
                        *p0 = make_float2(o0.x + acc[m3][nt][0], o0.y + acc[m3][nt][1]);
                        *p1 = make_float2(o1.x + acc[m3][nt][2], o1.y + acc[m3][nt][3]);
                    }
                }
            }
            __syncthreads();
        }
        asm volatile("cp.async.wait_group 0;");

        if (half == 0) {
            // ---- L0 epilogue: t = p (row pair er0, er0+1) ----
            if (p < S) {
                u32* Xn = g_hp[((p + 1) & 1) * 2 + dir][0];
                float hnA, hnB;
                {
                    float hr = G0[emm * 26 + j0]      + G1[emm * 26 + j0]      + bhh0[er0];
                    float hz = G0[emm * 26 + 8 + j0]  + G1[emm * 26 + 8 + j0]  + bhh0[H + er0];
                    float hn = G0[emm * 26 + 16 + j0] + G1[emm * 26 + 16 + j0] + bhh0[2 * H + er0];
                    float rr = sigm(GI0S[emm * 24 + j0] + hr);
                    float zz = sigm(GI0S[emm * 24 + 8 + j0] + hz);
                    float nn = tanhf(GI0S[emm * 24 + 16 + j0] + rr * hn);
                    hnA = (1.0f - zz) * nn + zz * hpA;
                }
                {
                    int j1 = j0 + 1, er1 = er0 + 1;
                    float hr = G0[emm * 26 + j1]      + G1[emm * 26 + j1]      + bhh0[er1];
                    float hz = G0[emm * 26 + 8 + j1]  + G1[emm * 26 + 8 + j1]  + bhh0[H + er1];
                    float hn = G0[emm * 26 + 16 + j1] + G1[emm * 26 + 16 + j1] + bhh0[2 * H + er1];
                    float rr = sigm(GI0S[emm * 24 + j1] + hr);
                    float zz = sigm(GI0S[emm * 24 + 8 + j1] + hz);
                    float nn = tanhf(GI0S[emm * 24 + 16 + j1] + rr * hn);
                    hnB = (1.0f - zz) * nn + zz * hpB;
                }
                hpA = hnA; hpB = hnB;
                bf16 hiA, loA, hiB, loB;
                split_bf(hnA, hiA, loA);
                split_bf(hnB, hiB, loB);
                Xn[eidx]         = pack2(hiA, hiB);
                Xn[16384 + eidx] = pack2(loA, loB);
                if (p == S - 1) {
                    g_h0f[0][dir][emm * H + er0]     = hnA;
                    g_h0f[0][dir][emm * H + er0 + 1] = hnB;
                }
            }
        } else {
            // ---- L1 epilogue: t = p-1 ----
            if (p >= 1) {
                int t1 = p - 1;
                int tt = dir ? (S - 1 - t1) : t1;
                u32* Hn = g_hp[4 + (p & 1) * 2 + dir][0];
                float hnA, hnB;
                {
                    float ir  = G0[1664 + emm * 26 + j0]      + G1[1664 + emm * 26 + j0]      + bi1[er0];
                    float iz  = G0[1664 + emm * 26 + 8 + j0]  + G1[1664 + emm * 26 + 8 + j0]  + bi1[H + er0];
                    float inn = G0[1664 + emm * 26 + 16 + j0] + G1[1664 + emm * 26 + 16 + j0] + bi1[2 * H + er0];
                    float hr  = G0[3328 + emm * 26 + j0]      + G1[3328 + emm * 26 + j0]      + bh1[er0];
                    float hz  = G0[3328 + emm * 26 + 8 + j0]  + G1[3328 + emm * 26 + 8 + j0]  + bh1[H + er0];
                    float hn  = G0[3328 + emm * 26 + 16 + j0] + G1[3328 + emm * 26 + 16 + j0] + bh1[2 * H + er0];
                    float rr = sigm(ir + hr);
                    float zz = sigm(iz + hz);
                    float nn = tanhf(inn + rr * hn);
                    hnA = (1.0f - zz) * nn + zz * hpA;
                }
                {
                    int j1 = j0 + 1, er1 = er0 + 1;
                    float ir  = G0[1664 + emm * 26 + j1]      + G1[1664 + emm * 26 + j1]      + bi1[er1];
                    float iz  = G0[1664 + emm * 26 + 8 + j1]  + G1[1664 + emm * 26 + 8 + j1]  + bi1[H + er1];
                    float inn = G0[1664 + emm * 26 + 16 + j1] + G1[1664 + emm * 26 + 16 + j1] + bi1[2 * H + er1];
                    float hr  = G0[3328 + emm * 26 + j1]      + G1[3328 + emm * 26 + j1]      + bh1[er1];
                    float hz  = G0[3328 + emm * 26 + 8 + j1]  + G1[3328 + emm * 26 + 8 + j1]  + bh1[H + er1];
                    float hn  = G0[3328 + emm * 26 + 16 + j1] + G1[3328 + emm * 26 + 16 + j1] + bh1[2 * H + er1];
                    float rr = sigm(ir + hr);
                    float zz = sigm(iz + hz);
                    float nn = tanhf(inn + rr * hn);
                    hnB = (1.0f - zz) * nn + zz * hpB;
                }
                hpA = hnA; hpB = hnB;
                bf16 hiA, loA, hiB, loB;
                split_bf(hnA, hiA, loA);
                split_bf(hnB, hiB, loB);
                Hn[eidx]         = pack2(hiA, hiB);
                Hn[16384 + eidx] = pack2(loA, loB);
                *(float2*)&out[(size_t)emm * (S * 2 * H) + (size_t)tt * (2 * H) + dir * H + er0] =
                    make_float2(hnA, hnB);
                if (p == S) {
                    g_h1f[0][dir][emm * H + er0]     = hnA;
                    g_h1f[0][dir][emm * H + er0 + 1] = hnB;
                }
            }
        }

        grid_bar(dir, (unsigned)(p + 1));
    }

    // ---- final hidden state copy (own dir; parity 0) ----
#pragma unroll
    for (int it = 0; it < 2; it++) {
        int local = (bid & 63) * 1024 + it * 512 + tid;   // < 65536 per dir
        int lyr = local >> 15;
        int rem = local & 32767;
        int b = rem >> 9;
        int n = rem & 511;
        float v = lyr ? __ldcg(&g_h1f[0][dir][b * H + n]) : __ldcg(&g_h0f[0][dir][b * H + n]);
        out[(size_t)B * S * 2 * H + ((size_t)lyr * B + b) * (2 * H) + dir * H + n] = v;
    }
}

// ---------------- launch ----------------
extern "C" void kernel_launch(void* const* d_in, const int* in_sizes, int n_in,
                              void* d_out, int out_size) {
    const float* input  = (const float*)d_in[0];
    const float* enc    = (const float*)d_in[1];
    const float* Wih_f  = (const float*)d_in[2];
    const float* Whh_f  = (const float*)d_in[3];
    const float* bih_f  = (const float*)d_in[4];
    const float* bhh_f  = (const float*)d_in[5];
    const float* Wih_b  = (const float*)d_in[6];
    const float* Whh_b  = (const float*)d_in[7];
    const float* bih_b  = (const float*)d_in[8];
    const float* bhh_b  = (const float*)d_in[9];
    float* out = (float*)d_out;

    const int SMEM_G = 73728;
    const int SMEM_P = 198144;
    static int configured = 0;
    if (!configured) {
        cudaFuncSetAttribute(gemm_gi0, cudaFuncAttributeMaxDynamicSharedMemorySize, SMEM_G);
        cudaFuncSetAttribute(gru_persist, cudaFuncAttributeMaxDynamicSharedMemorySize, SMEM_P);
        configured = 1;
    }

    conv_xw<<<17920, 256>>>(input, Wih_f, Wih_b);
    init_h<<<512, 256>>>(enc);
    gemm_gi0<<<dim3(S, 24, 2), 256, SMEM_G>>>(bih_f, bih_b);
    gru_persist<<<NBLK, 512, SMEM_P>>>(Wih_f, Wih_b, Whh_f, Whh_b,
                                       bih_f, bih_b, bhh_f, bhh_b, out);
}

// round 15
// speedup vs baseline: 1.8416x; 1.0107x over previous
#include <cuda_runtime.h>
#include <cuda_bf16.h>
#include <math.h>

#define S 512
#define B 64
#define H 512
#define D 512
#define G3 1536
#define NBLK 128

typedef unsigned u32;
typedef unsigned long long ull;
typedef __nv_bfloat16 bf16;

// ---------------- device-global scratch (allocation-free rule) ----------------
__device__ float g_gi0[(size_t)2 * S * B * G3];          // fp32 gi0 [dir][t][b][3H]
__device__ bf16  g_xp[2][(size_t)B * S * D];             // input hi/lo planes (planar)
__device__ bf16  g_wp[2][2][(size_t)G3 * D];             // Wih layer0 [dir][plane] (planar)
__device__ float g_h0f[2][2][B * H];                     // [parity][dir]
__device__ float g_h1f[2][2][B * H];
// unified h planes, mma-frag layout: sel = layer*4 + parity*2 + dir; [sel][plane][...]
__device__ u32   g_hp[8][2][16384];
__device__ unsigned g_arrive2[2];

// ---------------- helpers ----------------
__device__ __forceinline__ void split_bf(float v, bf16& hi, bf16& lo) {
    hi = __float2bfloat16(v);
    lo = __float2bfloat16(v - __bfloat162float(hi));
}
__device__ __forceinline__ u32 pack2(bf16 a, bf16 b) {
    return (u32)__bfloat16_as_ushort(a) | ((u32)__bfloat16_as_ushort(b) << 16);
}
__device__ __forceinline__ float sigm(float x) { return 1.0f / (1.0f + expf(-x)); }

// byte offset of h value (batch b, hidden k) inside a frag-layout plane
__device__ __forceinline__ int frag_byte(int b, int k) {
    int kblk = k >> 4, c = k & 15, mt = b >> 4, r = b & 15;
    int lane = (r & 7) * 4 + ((c & 7) >> 1);
    int reg  = (r >> 3) + 2 * (c >> 3);
    return ((kblk * 512 + mt * 128 + lane * 4 + reg) << 2) + ((c & 1) << 1);
}

__device__ __forceinline__ void mma16816(float* d, const u32* a, u32 b0, u32 b1) {
    asm volatile("mma.sync.aligned.m16n8k16.row.col.f32.bf16.bf16.f32 "
                 "{%0,%1,%2,%3},{%4,%5,%6,%7},{%8,%9},{%0,%1,%2,%3};"
                 : "+f"(d[0]), "+f"(d[1]), "+f"(d[2]), "+f"(d[3])
                 : "r"(a[0]), "r"(a[1]), "r"(a[2]), "r"(a[3]), "r"(b0), "r"(b1));
}
__device__ __forceinline__ void ldm4(u32* r, const void* p) {
    u32 s = (u32)__cvta_generic_to_shared(p);
    asm volatile("ldmatrix.sync.aligned.m8n8.x4.shared.b16 {%0,%1,%2,%3},[%4];"
                 : "=r"(r[0]), "=r"(r[1]), "=r"(r[2]), "=r"(r[3]) : "r"(s));
}
__device__ __forceinline__ void cp16(void* smem_dst, const void* gsrc) {
    u32 s = (u32)__cvta_generic_to_shared(smem_dst);
    asm volatile("cp.async.cg.shared.global [%0], [%1], 16;" :: "r"(s), "l"(gsrc));
}

// ---------------- conv_xw: input + Wih0 -> planar hi/lo bf16 planes ----------------
__global__ void conv_xw(const float* __restrict__ x,
                        const float* __restrict__ wf, const float* __restrict__ wb) {
    if (blockIdx.x < 16384) {
        size_t i = ((size_t)blockIdx.x * 256 + threadIdx.x) * 4;
        float4 v = *(const float4*)&x[i];
        bf16 h0, l0, h1, l1, h2, l2, h3, l3;
        split_bf(v.x, h0, l0); split_bf(v.y, h1, l1);
        split_bf(v.z, h2, l2); split_bf(v.w, h3, l3);
        u32* ph = (u32*)&g_xp[0][i];
        u32* pl = (u32*)&g_xp[1][i];
        ph[0] = pack2(h0, h1); ph[1] = pack2(h2, h3);
        pl[0] = pack2(l0, l1); pl[1] = pack2(l2, l3);
    } else {
        size_t j = ((size_t)(blockIdx.x - 16384) * 256 + threadIdx.x) * 4;
        int d = j >= (size_t)G3 * D;
        size_t off = d ? j - (size_t)G3 * D : j;
        const float* src = d ? wb : wf;
        float4 v = *(const float4*)&src[off];
        bf16 h0, l0, h1, l1, h2, l2, h3, l3;
        split_bf(v.x, h0, l0); split_bf(v.y, h1, l1);
        split_bf(v.z, h2, l2); split_bf(v.w, h3, l3);
        u32* ph = (u32*)&g_wp[d][0][off];
        u32* pl = (u32*)&g_wp[d][1][off];
        ph[0] = pack2(h0, h1); ph[1] = pack2(h2, h3);
        pl[0] = pack2(l0, l1); pl[1] = pack2(l2, l3);
    }
}

// ---------------- init: hidden states (fp32 + frag planes) + barrier reset ----------------
__global__ void init_h(const float* __restrict__ enc) {
    if (blockIdx.x == 0 && threadIdx.x < 2) {
        g_arrive2[threadIdx.x] = 0;
    }
    int idx = blockIdx.x * blockDim.x + threadIdx.x;   // 131072
    int layer = idx >> 16;
    int rem = idx & 65535;
    int dir = rem >> 15;
    int rem2 = rem & 32767;
    int b = rem2 >> 9;
    int n = rem2 & 511;
    float v = enc[(layer * B + b) * (2 * H) + dir * H + n];
    bf16 hi, lo; split_bf(v, hi, lo);
    int off = frag_byte(b, n);
    int sel = layer * 4 + dir;                 // parity 0
    if (layer == 0) g_h0f[0][dir][b * H + n] = v;
    else            g_h1f[0][dir][b * H + n] = v;
    *(bf16*)((char*)g_hp[sel][0] + off) = hi;
    *(bf16*)((char*)g_hp[sel][1] + off) = lo;
}

// ---------------- gi0 = input @ Wih0^T + bih0, smem-staged split-bf16 mma ----------------
__global__ void __launch_bounds__(256, 3)
gemm_gi0(const float* __restrict__ bf_, const float* __restrict__ bb_) {
    extern __shared__ char sm2[];
    char* Wbuf0 = sm2;
    char* Wbuf1 = sm2 + 18432;
    char* Xbuf0 = sm2 + 36864;
    char* Xbuf1 = sm2 + 55296;

    int s  = blockIdx.x;
    int nb = blockIdx.y;
    int d  = blockIdx.z;
    const float* bias = d ? bb_ : bf_;

    int tid = threadIdx.x;
    int w = tid >> 5, l = tid & 31;
    int mtile = w & 3, m0 = mtile * 16, nh = w >> 2;

    const char* wsrc[2] = { (const char*)&g_wp[d][0][(size_t)(nb * 64) * D],
                            (const char*)&g_wp[d][1][(size_t)(nb * 64) * D] };
    const char* xsrc[2] = { (const char*)&g_xp[0][0], (const char*)&g_xp[1][0] };

    float acc[4][4];
#pragma unroll
    for (int nt = 0; nt < 4; nt++) { acc[nt][0] = acc[nt][1] = acc[nt][2] = acc[nt][3] = 0.f; }

    auto stage = [&](int c, char* Wb, char* Xb) {
#pragma unroll
        for (int i = 0; i < 4; i++) {
            int idx = i * 256 + tid;
            int pl = idx >> 9, row = (idx >> 3) & 63, seg = idx & 7;
            cp16(Wb + pl * 9216 + row * 144 + seg * 16,
                 wsrc[pl] + (size_t)row * 1024 + c * 128 + seg * 16);
        }
#pragma unroll
        for (int i = 0; i < 4; i++) {
            int idx = i * 256 + tid;
            int pl = idx >> 9, row = (idx >> 3) & 63, seg = idx & 7;
            cp16(Xb + pl * 9216 + row * 144 + seg * 16,
                 xsrc[pl] + (size_t)row * 524288 + (size_t)s * 1024 + c * 128 + seg * 16);
        }
        asm volatile("cp.async.commit_group;");
    };

    stage(0, Wbuf0, Xbuf0);

    for (int c = 0; c < 8; c++) {
        asm volatile("cp.async.wait_group 0;");
        __syncthreads();
        if (c < 7) stage(c + 1, (c & 1) ? Wbuf0 : Wbuf1, (c & 1) ? Xbuf0 : Xbuf1);
        char* Wb = (c & 1) ? Wbuf1 : Wbuf0;
        char* Xb = (c & 1) ? Xbuf1 : Xbuf0;
#pragma unroll
        for (int kl = 0; kl < 4; kl++) {
            u32 ah[4], al[4];
            int aoff = (m0 + (l & 15)) * 144 + kl * 32 + (l >> 4) * 16;
            ldm4(ah, Xb + aoff);
            ldm4(al, Xb + 9216 + aoff);
            const u32* Wh = (const u32*)Wb;
            const u32* Wl = (const u32*)(Wb + 9216);
#pragma unroll
            for (int nt = 0; nt < 4; nt++) {
                int nrow = nh * 32 + nt * 8 + (l >> 2);
                int wi = nrow * 36 + kl * 8 + (l & 3);
                u32 bh0 = Wh[wi], bh1 = Wh[wi + 4];
                u32 bl0 = Wl[wi], bl1 = Wl[wi + 4];
                mma16816(acc[nt], ah, bh0, bh1);
                mma16816(acc[nt], al, bh0, bh1);
                mma16816(acc[nt], ah, bl0, bl1);
            }
        }
    }

#pragma unroll
    for (int nt = 0; nt < 4; nt++) {
        int col = nb * 64 + nh * 32 + nt * 8 + 2 * (l & 3);
        float2 bi = *(const float2*)&bias[col];
        int b0 = m0 + (l >> 2);
        float2 v0 = make_float2(acc[nt][0] + bi.x, acc[nt][1] + bi.y);
        float2 v1 = make_float2(acc[nt][2] + bi.x, acc[nt][3] + bi.y);
        *(float2*)&g_gi0[(((size_t)d * S + s) * B + b0) * G3 + col] = v0;
        *(float2*)&g_gi0[(((size_t)d * S + s) * B + b0 + 8) * G3 + col] = v1;
    }
}

// ---------------- per-dir grid barrier v3: release-red arrive + counter poll ----------------
__device__ __forceinline__ void grid_bar(int dir, unsigned target) {
    __syncthreads();
    if (threadIdx.x == 0) {
        asm volatile("red.release.gpu.global.add.u32 [%0], 1;"
                     :: "l"(&g_arrive2[dir]) : "memory");
        unsigned r;
        do {
            asm volatile("ld.acquire.gpu.u32 %0, [%1];" : "=r"(r) : "l"(&g_arrive2[dir]) : "memory");
        } while (r < target * 64u);
    }
    __syncthreads();
}

// ---------------- persistent recurrence kernel ----------------
// grid 128 (2 dir x 64 hgroups of 8), 512 thr = 16 warps (mtile x4, ksub x4).
// smem: WS 152064 | G0 19968 | G1 19968 | GI0S 6144 = 198144 B
// Epilogue: thread halves run L0/L1 concurrently; packed row-pair plane stores.
__global__ void __launch_bounds__(512, 1)
gru_persist(const float* __restrict__ Wih_f, const float* __restrict__ Wih_b,
            const float* __restrict__ Whh_f, const float* __restrict__ Whh_b,
            const float* __restrict__ bih_f, const float* __restrict__ bih_b,
            const float* __restrict__ bhh_f, const float* __restrict__ bhh_b,
            float* __restrict__ out) {
    extern __shared__ char smem[];
    u32*  WS    = (u32*)smem;                    // [(mat*2+plane)*24 + n][264]
    float* G0   = (float*)(smem + 152064);       // partials ksub{0,1}
    float* G1   = (float*)(smem + 172032);       // partials ksub{2,3}
    float* GI0S = (float*)(smem + 192000);       // [64][24]

    const int tid = threadIdx.x;
    const int bid = blockIdx.x;
    const int dir = bid >> 6;
    const int hb  = (bid & 63) * 8;
    const int w = tid >> 5, l = tid & 31;
    const int mtile = w & 3, m0 = mtile * 16, ksub = w >> 2;

    const float* Wih = dir ? Wih_b : Wih_f;
    const float* Whh = dir ? Whh_b : Whh_f;
    const float* bih = dir ? bih_b : bih_f;
    const float* bhh = dir ? bhh_b : bhh_f;
    const float* bhh0 = bhh;
    const float* bi1 = bih + G3;
    const float* bh1 = bhh + G3;

    // ---- one-time weight staging: bf16 hi/lo, (k,k+8)-interleaved u32 pairs ----
    {
        const float* Wmat[3] = { Whh, Wih + (size_t)G3 * D, Whh + (size_t)G3 * H };
#pragma unroll 4
        for (int i = 0; i < 36; i++) {
            int item = tid + 512 * i;            // < 18432
            int m3 = item / 6144;
            int rem = item - m3 * 6144;
            int n = rem >> 8;
            int k2 = rem & 255;
            int grow = (n >> 3) * H + hb + (n & 7);
            float2 v = *(const float2*)(Wmat[m3] + (size_t)grow * 512 + 2 * k2);
            bf16 h0, l0, h1, l1;
            split_bf(v.x, h0, l0); split_bf(v.y, h1, l1);
            int j = k2 & 7;
            int col = ((k2 >> 3) << 3) + ((j & 3) << 1) + (j >> 2);
            WS[((m3 * 2 + 0) * 24 + n) * 264 + col] = pack2(h0, h1);
            WS[((m3 * 2 + 1) * 24 + n) * 264 + col] = pack2(l0, l1);
        }
    }

    // ---- epilogue ownership: half 0 -> L0, half 1 -> L1; row pair (r0, r0+1) ----
    const int half = tid >> 8;
    const int emm  = tid & 63;
    const int q    = (tid >> 6) & 3;
    const int j0   = 2 * q;
    const int er0  = hb + j0;
    float hpA, hpB;
    if (half == 0) {
        hpA = g_h0f[0][dir][emm * H + er0];
        hpB = g_h0f[0][dir][emm * H + er0 + 1];
    } else {
        hpA = g_h1f[0][dir][emm * H + er0];
        hpB = g_h1f[0][dir][emm * H + er0 + 1];
    }
    const int eidx = frag_byte(emm, er0) >> 2;   // u32 index shared by the row pair

    const int rowoff = (l >> 2) * 264 + 2 * (l & 3) + ksub * 8;
    const int fbase  = mtile * 128 + l * 4;

    for (int p = 0; p <= S; p++) {
        const u32* Xb = g_hp[(p & 1) * 2 + dir][0];            // layer0 planes (lo at +16384)
        const u32* Hb = g_hp[4 + ((p + 1) & 1) * 2 + dir][0];  // layer1 planes

        // gi0 prefetch (used in L0 epilogue)
        if (p < S) {
            int tt0 = dir ? (S - 1 - p) : p;
            const float* gi = &g_gi0[((size_t)dir * S + tt0) * B * G3];
            if (tid < 384) {
                int mm = tid / 6, r = tid % 6;
                int gate = r >> 1, hf = r & 1;
                cp16(&GI0S[mm * 24 + gate * 8 + hf * 4],
                     gi + mm * G3 + gate * H + hb + hf * 4);
            }
            asm volatile("cp.async.commit_group;");
        }

        float acc[3][3][4];
#pragma unroll
        for (int m3 = 0; m3 < 3; m3++)
#pragma unroll
            for (int nt = 0; nt < 3; nt++)
                acc[m3][nt][0] = acc[m3][nt][1] = acc[m3][nt][2] = acc[m3][nt][3] = 0.f;

        u32 f0[4][4], f1[4][4];
        {
            int idx = ksub * 512 + fbase;
            uint4 v;
            v = __ldcg((const uint4*)(Xb + idx));
            f0[0][0] = v.x; f0[0][1] = v.y; f0[0][2] = v.z; f0[0][3] = v.w;
            v = __ldcg((const uint4*)(Xb + 16384 + idx));
            f0[1][0] = v.x; f0[1][1] = v.y; f0[1][2] = v.z; f0[1][3] = v.w;
            v = __ldcg((const uint4*)(Hb + idx));
            f0[2][0] = v.x; f0[2][1] = v.y; f0[2][2] = v.z; f0[2][3] = v.w;
            v = __ldcg((const uint4*)(Hb + 16384 + idx));
            f0[3][0] = v.x; f0[3][1] = v.y; f0[3][2] = v.z; f0[3][3] = v.w;
        }

#pragma unroll
        for (int c = 0; c < 8; c++) {
            if (c < 7) {
                int idx = ((c + 1) * 4 + ksub) * 512 + fbase;
                u32 (*Fn)[4] = (c & 1) ? f0 : f1;
                uint4 v;
                v = __ldcg((const uint4*)(Xb + idx));
                Fn[0][0] = v.x; Fn[0][1] = v.y; Fn[0][2] = v.z; Fn[0][3] = v.w;
                v = __ldcg((const uint4*)(Xb + 16384 + idx));
                Fn[1][0] = v.x; Fn[1][1] = v.y; Fn[1][2] = v.z; Fn[1][3] = v.w;
                v = __ldcg((const uint4*)(Hb + idx));
                Fn[2][0] = v.x; Fn[2][1] = v.y; Fn[2][2] = v.z; Fn[2][3] = v.w;
                v = __ldcg((const uint4*)(Hb + 16384 + idx));
                Fn[3][0] = v.x; Fn[3][1] = v.y; Fn[3][2] = v.z; Fn[3][3] = v.w;
            }
            u32 (*Af)[4] = (c & 1) ? f1 : f0;
            const int cb = rowoff + c * 32;
#pragma unroll
            for (int m3 = 0; m3 < 3; m3++) {
                const u32* Ahi = (m3 == 2) ? Af[2] : Af[0];
                const u32* Alo = (m3 == 2) ? Af[3] : Af[1];
                const u32* WH = WS + (m3 * 2) * 24 * 264 + cb;
                const u32* WL = WH + 24 * 264;
#pragma unroll
                for (int nt = 0; nt < 3; nt++) {
                    ull wh64 = *(const ull*)(WH + nt * 8 * 264);
                    ull wl64 = *(const ull*)(WL + nt * 8 * 264);
                    u32 bh0 = (u32)wh64, bh1 = (u32)(wh64 >> 32);
                    u32 bl0 = (u32)wl64, bl1 = (u32)(wl64 >> 32);
                    mma16816(acc[m3][nt], Ahi, bh0, bh1);
                    mma16816(acc[m3][nt], Alo, bh0, bh1);
                    mma16816(acc[m3][nt], Ahi, bl0, bl1);
                }
            }
        }

        // gi0 cp.async settled before the reduction barriers (issuer-wait -> barrier -> read)
        asm volatile("cp.async.wait_group 0;");

        // ---- pairwise K-split reduction: ksub{0,2} write, ksub{1,3} accumulate ----
        // (no leading sync needed: previous phase's G readers are ordered by grid_bar)
        {
            float* Gb = (ksub & 2) ? G1 : G0;
            if ((ksub & 1) == 0) {
#pragma unroll
                for (int m3 = 0; m3 < 3; m3++) {
                    float* G = Gb + m3 * 1664;
#pragma unroll
                    for (int nt = 0; nt < 3; nt++) {
                        int col = nt * 8 + 2 * (l & 3);
                        int r0 = m0 + (l >> 2);
                        *(float2*)&G[r0 * 26 + col] =
                            make_float2(acc[m3][nt][0], acc[m3][nt][1]);
                        *(float2*)&G[(r0 + 8) * 26 + col] =
                            make_float2(acc[m3][nt][2], acc[m3][nt][3]);
                    }
                }
            }
            __syncthreads();
            if (ksub & 1) {
#pragma unroll
                for (int m3 = 0; m3 < 3; m3++) {
                    float* G = Gb + m3 * 1664;
#pragma unroll
                    for (int nt = 0; nt < 3; nt++) {
                        int col = nt * 8 + 2 * (l & 3);
                        int r0 = m0 + (l >> 2);
                        float2* p0 = (float2*)&G[r0 * 26 + col];
                        float2* p1 = (float2*)&G[(r0 + 8) * 26 + col];
                        float2 o0 = *p0, o1 = *p1;
                        *p0 = make_float2(o0.x + acc[m3][nt][0], o0.y + acc[m3][nt][1]);
                        *p1 = make_float2(o1.x + acc[m3][nt][2], o1.y + acc[m3][nt][3]);
                    }
                }
            }
            __syncthreads();
        }

        if (half == 0) {
            // ---- L0 epilogue: t = p (row pair er0, er0+1) ----
            if (p < S) {
                u32* Xn = g_hp[((p + 1) & 1) * 2 + dir][0];
                float hnA, hnB;
                {
                    float hr = G0[emm * 26 + j0]      + G1[emm * 26 + j0]      + bhh0[er0];
                    float hz = G0[emm * 26 + 8 + j0]  + G1[emm * 26 + 8 + j0]  + bhh0[H + er0];
                    float hn = G0[emm * 26 + 16 + j0] + G1[emm * 26 + 16 + j0] + bhh0[2 * H + er0];
                    float rr = sigm(GI0S[emm * 24 + j0] + hr);
                    float zz = sigm(GI0S[emm * 24 + 8 + j0] + hz);
                    float nn = tanhf(GI0S[emm * 24 + 16 + j0] + rr * hn);
                    hnA = (1.0f - zz) * nn + zz * hpA;
                }
                {
                    int j1 = j0 + 1, er1 = er0 + 1;
                    float hr = G0[emm * 26 + j1]      + G1[emm * 26 + j1]      + bhh0[er1];
                    float hz = G0[emm * 26 + 8 + j1]  + G1[emm * 26 + 8 + j1]  + bhh0[H + er1];
                    float hn = G0[emm * 26 + 16 + j1] + G1[emm * 26 + 16 + j1] + bhh0[2 * H + er1];
                    float rr = sigm(GI0S[emm * 24 + j1] + hr);
                    float zz = sigm(GI0S[emm * 24 + 8 + j1] + hz);
                    float nn = tanhf(GI0S[emm * 24 + 16 + j1] + rr * hn);
                    hnB = (1.0f - zz) * nn + zz * hpB;
                }
                hpA = hnA; hpB = hnB;
                bf16 hiA, loA, hiB, loB;
                split_bf(hnA, hiA, loA);
                split_bf(hnB, hiB, loB);
                Xn[eidx]         = pack2(hiA, hiB);
                Xn[16384 + eidx] = pack2(loA, loB);
                if (p == S - 1) {
                    g_h0f[0][dir][emm * H + er0]     = hnA;
                    g_h0f[0][dir][emm * H + er0 + 1] = hnB;
                }
            }
        } else {
            // ---- L1 epilogue: t = p-1 ----
            if (p >= 1) {
                int t1 = p - 1;
                int tt = dir ? (S - 1 - t1) : t1;
                u32* Hn = g_hp[4 + (p & 1) * 2 + dir][0];
                float hnA, hnB;
                {
                    float ir  = G0[1664 + emm * 26 + j0]      + G1[1664 + emm * 26 + j0]      + bi1[er0];
                    float iz  = G0[1664 + emm * 26 + 8 + j0]  + G1[1664 + emm * 26 + 8 + j0]  + bi1[H + er0];
                    float inn = G0[1664 + emm * 26 + 16 + j0] + G1[1664 + emm * 26 + 16 + j0] + bi1[2 * H + er0];
                    float hr  = G0[3328 + emm * 26 + j0]      + G1[3328 + emm * 26 + j0]      + bh1[er0];
                    float hz  = G0[3328 + emm * 26 + 8 + j0]  + G1[3328 + emm * 26 + 8 + j0]  + bh1[H + er0];
                    float hn  = G0[3328 + emm * 26 + 16 + j0] + G1[3328 + emm * 26 + 16 + j0] + bh1[2 * H + er0];
                    float rr = sigm(ir + hr);
                    float zz = sigm(iz + hz);
                    float nn = tanhf(inn + rr * hn);
                    hnA = (1.0f - zz) * nn + zz * hpA;
                }
                {
                    int j1 = j0 + 1, er1 = er0 + 1;
                    float ir  = G0[1664 + emm * 26 + j1]      + G1[1664 + emm * 26 + j1]      + bi1[er1];
                    float iz  = G0[1664 + emm * 26 + 8 + j1]  + G1[1664 + emm * 26 + 8 + j1]  + bi1[H + er1];
                    float inn = G0[1664 + emm * 26 + 16 + j1] + G1[1664 + emm * 26 + 16 + j1] + bi1[2 * H + er1];
                    float hr  = G0[3328 + emm * 26 + j1]      + G1[3328 + emm * 26 + j1]      + bh1[er1];
                    float hz  = G0[3328 + emm * 26 + 8 + j1]  + G1[3328 + emm * 26 + 8 + j1]  + bh1[H + er1];
                    float hn  = G0[3328 + emm * 26 + 16 + j1] + G1[3328 + emm * 26 + 16 + j1] + bh1[2 * H + er1];
                    float rr = sigm(ir + hr);
                    float zz = sigm(iz + hz);
                    float nn = tanhf(inn + rr * hn);
                    hnB = (1.0f - zz) * nn + zz * hpB;
                }
                hpA = hnA; hpB = hnB;
                bf16 hiA, loA, hiB, loB;
                split_bf(hnA, hiA, loA);
                split_bf(hnB, hiB, loB);
                Hn[eidx]         = pack2(hiA, hiB);
                Hn[16384 + eidx] = pack2(loA, loB);
                *(float2*)&out[(size_t)emm * (S * 2 * H) + (size_t)tt * (2 * H) + dir * H + er0] =
                    make_float2(hnA, hnB);
                if (p == S) {
                    g_h1f[0][dir][emm * H + er0]     = hnA;
                    g_h1f[0][dir][emm * H + er0 + 1] = hnB;
                }
            }
        }

        grid_bar(dir, (unsigned)(p + 1));
    }

    // ---- final hidden state copy (own dir; parity 0) ----
#pragma unroll
    for (int it = 0; it < 2; it++) {
        int local = (bid & 63) * 1024 + it * 512 + tid;   // < 65536 per dir
        int lyr = local >> 15;
        int rem = local & 32767;
        int b = rem >> 9;
        int n = rem & 511;
        float v = lyr ? __ldcg(&g_h1f[0][dir][b * H + n]) : __ldcg(&g_h0f[0][dir][b * H + n]);
        out[(size_t)B * S * 2 * H + ((size_t)lyr * B + b) * (2 * H) + dir * H + n] = v;
    }
}

// ---------------- launch ----------------
extern "C" void kernel_launch(void* const* d_in, const int* in_sizes, int n_in,
                              void* d_out, int out_size) {
    const float* input  = (const float*)d_in[0];
    const float* enc    = (const float*)d_in[1];
    const float* Wih_f  = (const float*)d_in[2];
    const float* Whh_f  = (const float*)d_in[3];
    const float* bih_f  = (const float*)d_in[4];
    const float* bhh_f  = (const float*)d_in[5];
    const float* Wih_b  = (const float*)d_in[6];
    const float* Whh_b  = (const float*)d_in[7];
    const float* bih_b  = (const float*)d_in[8];
    const float* bhh_b  = (const float*)d_in[9];
    float* out = (float*)d_out;

    const int SMEM_G = 73728;
    const int SMEM_P = 198144;
    static int configured = 0;
    if (!configured) {
        cudaFuncSetAttribute(gemm_gi0, cudaFuncAttributeMaxDynamicSharedMemorySize, SMEM_G);
        cudaFuncSetAttribute(gru_persist, cudaFuncAttributeMaxDynamicSharedMemorySize, SMEM_P);
        configured = 1;
    }

    conv_xw<<<17920, 256>>>(input, Wih_f, Wih_b);
    init_h<<<512, 256>>>(enc);
    gemm_gi0<<<dim3(S, 24, 2), 256, SMEM_G>>>(bih_f, bih_b);
    gru_persist<<<NBLK, 512, SMEM_P>>>(Wih_f, Wih_b, Whh_f, Whh_b,
                                       bih_f, bih_b, bhh_f, bhh_b, out);
}

// round 16
// speedup vs baseline: 2.2737x; 1.2346x over previous
#include <cuda_runtime.h>
#include <cuda_fp16.h>
#include <math.h>

#define S 512
#define B 64
#define H 512
#define D 512
#define G3 1536
#define NBLK 128

typedef unsigned u32;
typedef unsigned long long ull;
typedef __half f16;

// ---------------- device-global scratch (allocation-free rule) ----------------
__device__ float g_gi0[(size_t)2 * S * B * G3];          // fp32 gi0 [dir][t][b][3H]
__device__ f16   g_xp[2][(size_t)B * S * D];             // input hi/lo planes (planar fp16)
__device__ f16   g_wp[2][(size_t)G3 * D];                // Wih layer0 [dir] single fp16 plane
__device__ float g_h0f[2][2][B * H];                     // [parity][dir]
__device__ float g_h1f[2][2][B * H];
// unified h planes (fp16 hi/lo), mma-frag layout: sel = layer*4 + parity*2 + dir
__device__ u32   g_hp[8][2][16384];
__device__ unsigned g_arrive2[2];

// ---------------- helpers ----------------
__device__ __forceinline__ void split_h(float v, f16& hi, f16& lo) {
    hi = __float2half(v);
    lo = __float2half(v - __half2float(hi));
}
__device__ __forceinline__ u32 pack2h(f16 a, f16 b) {
    return (u32)__half_as_ushort(a) | ((u32)__half_as_ushort(b) << 16);
}
__device__ __forceinline__ float sigm(float x) { return 1.0f / (1.0f + expf(-x)); }

// byte offset of h value (batch b, hidden k) inside a frag-layout plane
__device__ __forceinline__ int frag_byte(int b, int k) {
    int kblk = k >> 4, c = k & 15, mt = b >> 4, r = b & 15;
    int lane = (r & 7) * 4 + ((c & 7) >> 1);
    int reg  = (r >> 3) + 2 * (c >> 3);
    return ((kblk * 512 + mt * 128 + lane * 4 + reg) << 2) + ((c & 1) << 1);
}

__device__ __forceinline__ void mma16816(float* d, const u32* a, u32 b0, u32 b1) {
    asm volatile("mma.sync.aligned.m16n8k16.row.col.f32.f16.f16.f32 "
                 "{%0,%1,%2,%3},{%4,%5,%6,%7},{%8,%9},{%0,%1,%2,%3};"
                 : "+f"(d[0]), "+f"(d[1]), "+f"(d[2]), "+f"(d[3])
                 : "r"(a[0]), "r"(a[1]), "r"(a[2]), "r"(a[3]), "r"(b0), "r"(b1));
}
__device__ __forceinline__ void ldm4(u32* r, const void* p) {
    u32 s = (u32)__cvta_generic_to_shared(p);
    asm volatile("ldmatrix.sync.aligned.m8n8.x4.shared.b16 {%0,%1,%2,%3},[%4];"
                 : "=r"(r[0]), "=r"(r[1]), "=r"(r[2]), "=r"(r[3]) : "r"(s));
}
__device__ __forceinline__ void cp16(void* smem_dst, const void* gsrc) {
    u32 s = (u32)__cvta_generic_to_shared(smem_dst);
    asm volatile("cp.async.cg.shared.global [%0], [%1], 16;" :: "r"(s), "l"(gsrc));
}

// ---------------- conv_xw: input -> fp16 hi/lo planes; Wih0 -> single fp16 plane ----------------
__global__ void conv_xw(const float* __restrict__ x,
                        const float* __restrict__ wf, const float* __restrict__ wb) {
    if (blockIdx.x < 16384) {
        size_t i = ((size_t)blockIdx.x * 256 + threadIdx.x) * 4;
        float4 v = *(const float4*)&x[i];
        f16 h0, l0, h1, l1, h2, l2, h3, l3;
        split_h(v.x, h0, l0); split_h(v.y, h1, l1);
        split_h(v.z, h2, l2); split_h(v.w, h3, l3);
        u32* ph = (u32*)&g_xp[0][i];
        u32* pl = (u32*)&g_xp[1][i];
        ph[0] = pack2h(h0, h1); ph[1] = pack2h(h2, h3);
        pl[0] = pack2h(l0, l1); pl[1] = pack2h(l2, l3);
    } else {
        size_t j = ((size_t)(blockIdx.x - 16384) * 256 + threadIdx.x) * 4;
        int d = j >= (size_t)G3 * D;
        size_t off = d ? j - (size_t)G3 * D : j;
        const float* src = d ? wb : wf;
        float4 v = *(const float4*)&src[off];
        u32* ph = (u32*)&g_wp[d][off];
        ph[0] = pack2h(__float2half(v.x), __float2half(v.y));
        ph[1] = pack2h(__float2half(v.z), __float2half(v.w));
    }
}

// ---------------- init: hidden states (fp32 + frag planes) + barrier reset ----------------
__global__ void init_h(const float* __restrict__ enc) {
    if (blockIdx.x == 0 && threadIdx.x < 2) {
        g_arrive2[threadIdx.x] = 0;
    }
    int idx = blockIdx.x * blockDim.x + threadIdx.x;   // 131072
    int layer = idx >> 16;
    int rem = idx & 65535;
    int dir = rem >> 15;
    int rem2 = rem & 32767;
    int b = rem2 >> 9;
    int n = rem2 & 511;
    float v = enc[(layer * B + b) * (2 * H) + dir * H + n];
    f16 hi, lo; split_h(v, hi, lo);
    int off = frag_byte(b, n);
    int sel = layer * 4 + dir;                 // parity 0
    if (layer == 0) g_h0f[0][dir][b * H + n] = v;
    else            g_h1f[0][dir][b * H + n] = v;
    *(f16*)((char*)g_hp[sel][0] + off) = hi;
    *(f16*)((char*)g_hp[sel][1] + off) = lo;
}

// ---------------- gi0 = input @ Wih0^T + bih0, smem-staged fp16 2-product mma ----------------
// grid (S, 24, 2), 256 thr. smem 55296 -> 4 blocks/SM.
__global__ void __launch_bounds__(256, 4)
gemm_gi0(const float* __restrict__ bf_, const float* __restrict__ bb_) {
    extern __shared__ char sm2[];
    char* Wbuf0 = sm2;                 // 1 plane x [64][72 f16] = 9216
    char* Wbuf1 = sm2 + 9216;
    char* Xbuf0 = sm2 + 18432;         // 2 planes x [64][72 f16] = 18432
    char* Xbuf1 = sm2 + 36864;

    int s  = blockIdx.x;
    int nb = blockIdx.y;
    int d  = blockIdx.z;
    const float* bias = d ? bb_ : bf_;

    int tid = threadIdx.x;
    int w = tid >> 5, l = tid & 31;
    int mtile = w & 3, m0 = mtile * 16, nh = w >> 2;

    const char* wsrc = (const char*)&g_wp[d][(size_t)(nb * 64) * D];
    const char* xsrc[2] = { (const char*)&g_xp[0][0], (const char*)&g_xp[1][0] };

    float acc[4][4];
#pragma unroll
    for (int nt = 0; nt < 4; nt++) { acc[nt][0] = acc[nt][1] = acc[nt][2] = acc[nt][3] = 0.f; }

    auto stage = [&](int c, char* Wb, char* Xb) {
#pragma unroll
        for (int i = 0; i < 2; i++) {
            int idx = i * 256 + tid;              // < 512
            int row = idx >> 3, seg = idx & 7;
            cp16(Wb + row * 144 + seg * 16,
                 wsrc + (size_t)row * 1024 + c * 128 + seg * 16);
        }
#pragma unroll
        for (int i = 0; i < 4; i++) {
            int idx = i * 256 + tid;              // < 1024
            int pl = idx >> 9, row = (idx >> 3) & 63, seg = idx & 7;
            cp16(Xb + pl * 9216 + row * 144 + seg * 16,
                 xsrc[pl] + (size_t)row * 524288 + (size_t)s * 1024 + c * 128 + seg * 16);
        }
        asm volatile("cp.async.commit_group;");
    };

    stage(0, Wbuf0, Xbuf0);

    for (int c = 0; c < 8; c++) {
        asm volatile("cp.async.wait_group 0;");
        __syncthreads();
        if (c < 7) stage(c + 1, (c & 1) ? Wbuf0 : Wbuf1, (c & 1) ? Xbuf0 : Xbuf1);
        char* Wb = (c & 1) ? Wbuf1 : Wbuf0;
        char* Xb = (c & 1) ? Xbuf1 : Xbuf0;
#pragma unroll
        for (int kl = 0; kl < 4; kl++) {
            u32 ah[4], al[4];
            int aoff = (m0 + (l & 15)) * 144 + kl * 32 + (l >> 4) * 16;
            ldm4(ah, Xb + aoff);
            ldm4(al, Xb + 9216 + aoff);
            const u32* Wh = (const u32*)Wb;
#pragma unroll
            for (int nt = 0; nt < 4; nt++) {
                int nrow = nh * 32 + nt * 8 + (l >> 2);
                int wi = nrow * 36 + kl * 8 + (l & 3);
                u32 bh0 = Wh[wi], bh1 = Wh[wi + 4];
                mma16816(acc[nt], ah, bh0, bh1);
                mma16816(acc[nt], al, bh0, bh1);
            }
        }
    }

#pragma unroll
    for (int nt = 0; nt < 4; nt++) {
        int col = nb * 64 + nh * 32 + nt * 8 + 2 * (l & 3);
        float2 bi = *(const float2*)&bias[col];
        int b0 = m0 + (l >> 2);
        float2 v0 = make_float2(acc[nt][0] + bi.x, acc[nt][1] + bi.y);
        float2 v1 = make_float2(acc[nt][2] + bi.x, acc[nt][3] + bi.y);
        *(float2*)&g_gi0[(((size_t)d * S + s) * B + b0) * G3 + col] = v0;
        *(float2*)&g_gi0[(((size_t)d * S + s) * B + b0 + 8) * G3 + col] = v1;
    }
}

// ---------------- per-dir grid barrier v3: release-red arrive + counter poll ----------------
__device__ __forceinline__ void grid_bar(int dir, unsigned target) {
    __syncthreads();
    if (threadIdx.x == 0) {
        asm volatile("red.release.gpu.global.add.u32 [%0], 1;"
                     :: "l"(&g_arrive2[dir]) : "memory");
        unsigned r;
        do {
            asm volatile("ld.acquire.gpu.u32 %0, [%1];" : "=r"(r) : "l"(&g_arrive2[dir]) : "memory");
        } while (r < target * 64u);
    }
    __syncthreads();
}

// ---------------- persistent recurrence kernel (fp16 2-product) ----------------
// grid 128 (2 dir x 64 hgroups of 8), 512 thr = 16 warps (mtile x4, ksub x4).
// smem: WS 76032 | G0 19968 | G1 19968 | GI0S 6144 = 122112 B
__global__ void __launch_bounds__(512, 1)
gru_persist(const float* __restrict__ Wih_f, const float* __restrict__ Wih_b,
            const float* __restrict__ Whh_f, const float* __restrict__ Whh_b,
            const float* __restrict__ bih_f, const float* __restrict__ bih_b,
            const float* __restrict__ bhh_f, const float* __restrict__ bhh_b,
            float* __restrict__ out) {
    extern __shared__ char smem[];
    u32*  WS    = (u32*)smem;                    // [mat*24 + n][264] single fp16 plane
    float* G0   = (float*)(smem + 76032);        // partials ksub{0,1}
    float* G1   = (float*)(smem + 96000);        // partials ksub{2,3}
    float* GI0S = (float*)(smem + 115968);       // [64][24]

    const int tid = threadIdx.x;
    const int bid = blockIdx.x;
    const int dir = bid >> 6;
    const int hb  = (bid & 63) * 8;
    const int w = tid >> 5, l = tid & 31;
    const int mtile = w & 3, m0 = mtile * 16, ksub = w >> 2;

    const float* Wih = dir ? Wih_b : Wih_f;
    const float* Whh = dir ? Whh_b : Whh_f;
    const float* bih = dir ? bih_b : bih_f;
    const float* bhh = dir ? bhh_b : bhh_f;
    const float* bhh0 = bhh;
    const float* bi1 = bih + G3;
    const float* bh1 = bhh + G3;

    // ---- one-time weight staging: single fp16 plane, (k,k+8)-interleaved u32 pairs ----
    {
        const float* Wmat[3] = { Whh, Wih + (size_t)G3 * D, Whh + (size_t)G3 * H };
#pragma unroll 4
        for (int i = 0; i < 36; i++) {
            int item = tid + 512 * i;            // < 18432
            int m3 = item / 6144;
            int rem = item - m3 * 6144;
            int n = rem >> 8;
            int k2 = rem & 255;
            int grow = (n >> 3) * H + hb + (n & 7);
            float2 v = *(const float2*)(Wmat[m3] + (size_t)grow * 512 + 2 * k2);
            int j = k2 & 7;
            int col = ((k2 >> 3) << 3) + ((j & 3) << 1) + (j >> 2);
            WS[(m3 * 24 + n) * 264 + col] = pack2h(__float2half(v.x), __float2half(v.y));
        }
    }

    // ---- epilogue ownership: half 0 -> L0, half 1 -> L1; row pair (r0, r0+1) ----
    const int half = tid >> 8;
    const int emm  = tid & 63;
    const int q    = (tid >> 6) & 3;
    const int j0   = 2 * q;
    const int er0  = hb + j0;
    float hpA, hpB;
    if (half == 0) {
        hpA = g_h0f[0][dir][emm * H + er0];
        hpB = g_h0f[0][dir][emm * H + er0 + 1];
    } else {
        hpA = g_h1f[0][dir][emm * H + er0];
        hpB = g_h1f[0][dir][emm * H + er0 + 1];
    }
    const int eidx = frag_byte(emm, er0) >> 2;   // u32 index shared by the row pair

    const int rowoff = (l >> 2) * 264 + 2 * (l & 3) + ksub * 8;
    const int fbase  = mtile * 128 + l * 4;

    for (int p = 0; p <= S; p++) {
        const u32* Xb = g_hp[(p & 1) * 2 + dir][0];            // layer0 planes (lo at +16384)
        const u32* Hb = g_hp[4 + ((p + 1) & 1) * 2 + dir][0];  // layer1 planes

        // gi0 prefetch (used in L0 epilogue)
        if (p < S) {
            int tt0 = dir ? (S - 1 - p) : p;
            const float* gi = &g_gi0[((size_t)dir * S + tt0) * B * G3];
            if (tid < 384) {
                int mm = tid / 6, r = tid % 6;
                int gate = r >> 1, hf = r & 1;
                cp16(&GI0S[mm * 24 + gate * 8 + hf * 4],
                     gi + mm * G3 + gate * H + hb + hf * 4);
            }
            asm volatile("cp.async.commit_group;");
        }

        float acc[3][3][4];
#pragma unroll
        for (int m3 = 0; m3 < 3; m3++)
#pragma unroll
            for (int nt = 0; nt < 3; nt++)
                acc[m3][nt][0] = acc[m3][nt][1] = acc[m3][nt][2] = acc[m3][nt][3] = 0.f;

        u32 f0[4][4], f1[4][4];
        {
            int idx = ksub * 512 + fbase;
            uint4 v;
            v = __ldcg((const uint4*)(Xb + idx));
            f0[0][0] = v.x; f0[0][1] = v.y; f0[0][2] = v.z; f0[0][3] = v.w;
            v = __ldcg((const uint4*)(Xb + 16384 + idx));
            f0[1][0] = v.x; f0[1][1] = v.y; f0[1][2] = v.z; f0[1][3] = v.w;
            v = __ldcg((const uint4*)(Hb + idx));
            f0[2][0] = v.x; f0[2][1] = v.y; f0[2][2] = v.z; f0[2][3] = v.w;
            v = __ldcg((const uint4*)(Hb + 16384 + idx));
            f0[3][0] = v.x; f0[3][1] = v.y; f0[3][2] = v.z; f0[3][3] = v.w;
        }

#pragma unroll
        for (int c = 0; c < 8; c++) {
            if (c < 7) {
                int idx = ((c + 1) * 4 + ksub) * 512 + fbase;
                u32 (*Fn)[4] = (c & 1) ? f0 : f1;
                uint4 v;
                v = __ldcg((const uint4*)(Xb + idx));
                Fn[0][0] = v.x; Fn[0][1] = v.y; Fn[0][2] = v.z; Fn[0][3] = v.w;
                v = __ldcg((const uint4*)(Xb + 16384 + idx));
                Fn[1][0] = v.x; Fn[1][1] = v.y; Fn[1][2] = v.z; Fn[1][3] = v.w;
                v = __ldcg((const uint4*)(Hb + idx));
                Fn[2][0] = v.x; Fn[2][1] = v.y; Fn[2][2] = v.z; Fn[2][3] = v.w;
                v = __ldcg((const uint4*)(Hb + 16384 + idx));
                Fn[3][0] = v.x; Fn[3][1] = v.y; Fn[3][2] = v.z; Fn[3][3] = v.w;
            }
            u32 (*Af)[4] = (c & 1) ? f1 : f0;
            const int cb = rowoff + c * 32;
#pragma unroll
            for (int m3 = 0; m3 < 3; m3++) {
                const u32* Ahi = (m3 == 2) ? Af[2] : Af[0];
                const u32* Alo = (m3 == 2) ? Af[3] : Af[1];
                const u32* WH = WS + m3 * 24 * 264 + cb;
#pragma unroll
                for (int nt = 0; nt < 3; nt++) {
                    ull wh64 = *(const ull*)(WH + nt * 8 * 264);
                    u32 bh0 = (u32)wh64, bh1 = (u32)(wh64 >> 32);
                    mma16816(acc[m3][nt], Ahi, bh0, bh1);
                    mma16816(acc[m3][nt], Alo, bh0, bh1);
                }
            }
        }

        // gi0 cp.async settled before the reduction barriers
        asm volatile("cp.async.wait_group 0;");

        // ---- pairwise K-split reduction: ksub{0,2} write, ksub{1,3} accumulate ----
        {
            float* Gb = (ksub & 2) ? G1 : G0;
            if ((ksub & 1) == 0) {
#pragma unroll
                for (int m3 = 0; m3 < 3; m3++) {
                    float* G = Gb + m3 * 1664;
#pragma unroll
                    for (int nt = 0; nt < 3; nt++) {
                        int col = nt * 8 + 2 * (l & 3);
                        int r0 = m0 + (l >> 2);
                        *(float2*)&G[r0 * 26 + col] =
                            make_float2(acc[m3][nt][0], acc[m3][nt][1]);
                        *(float2*)&G[(r0 + 8) * 26 + col] =
                            make_float2(acc[m3][nt][2], acc[m3][nt][3]);
                    }
                }
            }
            __syncthreads();
            if (ksub & 1) {
#pragma unroll
                for (int m3 = 0; m3 < 3; m3++) {
                    float* G = Gb + m3 * 1664;
#pragma unroll
                    for (int nt = 0; nt < 3; nt++) {
                        int col = nt * 8 + 2 * (l & 3);
                        int r0 = m0 + (l >> 2);
                        float2* p0 = (float2*)&G[r0 * 26 + col];
                        float2* p1 = (float2*)&G[(r0 + 8) * 26 + col];
                        float2 o0 = *p0, o1 = *p1;
                        *p0 = make_float2(o0.x + acc[m3][nt][0], o0.y + acc[m3][nt][1]);
                        *p1 = make_float2(o1.x + acc[m3][nt][2], o1.y + acc[m3][nt][3]);
                    }
                }
            }
            __syncthreads();
        }

        if (half == 0) {
            // ---- L0 epilogue: t = p (row pair er0, er0+1) ----
            if (p < S) {
                u32* Xn = g_hp[((p + 1) & 1) * 2 + dir][0];
                float hnA, hnB;
                {
                    float hr = G0[emm * 26 + j0]      + G1[emm * 26 + j0]      + bhh0[er0];
                    float hz = G0[emm * 26 + 8 + j0]  + G1[emm * 26 + 8 + j0]  + bhh0[H + er0];
                    float hn = G0[emm * 26 + 16 + j0] + G1[emm * 26 + 16 + j0] + bhh0[2 * H + er0];
                    float rr = sigm(GI0S[emm * 24 + j0] + hr);
                    float zz = sigm(GI0S[emm * 24 + 8 + j0] + hz);
                    float nn = tanhf(GI0S[emm * 24 + 16 + j0] + rr * hn);
                    hnA = (1.0f - zz) * nn + zz * hpA;
                }
                {
                    int j1 = j0 + 1, er1 = er0 + 1;
                    float hr = G0[emm * 26 + j1]      + G1[emm * 26 + j1]      + bhh0[er1];
                    float hz = G0[emm * 26 + 8 + j1]  + G1[emm * 26 + 8 + j1]  + bhh0[H + er1];
                    float hn = G0[emm * 26 + 16 + j1] + G1[emm * 26 + 16 + j1] + bhh0[2 * H + er1];
                    float rr = sigm(GI0S[emm * 24 + j1] + hr);
                    float zz = sigm(GI0S[emm * 24 + 8 + j1] + hz);
                    float nn = tanhf(GI0S[emm * 24 + 16 + j1] + rr * hn);
                    hnB = (1.0f - zz) * nn + zz * hpB;
                }
                hpA = hnA; hpB = hnB;
                f16 hiA, loA, hiB, loB;
                split_h(hnA, hiA, loA);
                split_h(hnB, hiB, loB);
                Xn[eidx]         = pack2h(hiA, hiB);
                Xn[16384 + eidx] = pack2h(loA, loB);
                if (p == S - 1) {
                    g_h0f[0][dir][emm * H + er0]     = hnA;
                    g_h0f[0][dir][emm * H + er0 + 1] = hnB;
                }
            }
        } else {
            // ---- L1 epilogue: t = p-1 ----
            if (p >= 1) {
                int t1 = p - 1;
                int tt = dir ? (S - 1 - t1) : t1;
                u32* Hn = g_hp[4 + (p & 1) * 2 + dir][0];
                float hnA, hnB;
                {
                    float ir  = G0[1664 + emm * 26 + j0]      + G1[1664 + emm * 26 + j0]      + bi1[er0];
                    float iz  = G0[1664 + emm * 26 + 8 + j0]  + G1[1664 + emm * 26 + 8 + j0]  + bi1[H + er0];
                    float inn = G0[1664 + emm * 26 + 16 + j0] + G1[1664 + emm * 26 + 16 + j0] + bi1[2 * H + er0];
                    float hr  = G0[3328 + emm * 26 + j0]      + G1[3328 + emm * 26 + j0]      + bh1[er0];
                    float hz  = G0[3328 + emm * 26 + 8 + j0]  + G1[3328 + emm * 26 + 8 + j0]  + bh1[H + er0];
                    float hn  = G0[3328 + emm * 26 + 16 + j0] + G1[3328 + emm * 26 + 16 + j0] + bh1[2 * H + er0];
                    float rr = sigm(ir + hr);
                    float zz = sigm(iz + hz);
                    float nn = tanhf(inn + rr * hn);
                    hnA = (1.0f - zz) * nn + zz * hpA;
                }
                {
                    int j1 = j0 + 1, er1 = er0 + 1;
                    float ir  = G0[1664 + emm * 26 + j1]      + G1[1664 + emm * 26 + j1]      + bi1[er1];
                    float iz  = G0[1664 + emm * 26 + 8 + j1]  + G1[1664 + emm * 26 + 8 + j1]  + bi1[H + er1];
                    float inn = G0[1664 + emm * 26 + 16 + j1] + G1[1664 + emm * 26 + 16 + j1] + bi1[2 * H + er1];
                    float hr  = G0[3328 + emm * 26 + j1]      + G1[3328 + emm * 26 + j1]      + bh1[er1];
                    float hz  = G0[3328 + emm * 26 + 8 + j1]  + G1[3328 + emm * 26 + 8 + j1]  + bh1[H + er1];
                    float hn  = G0[3328 + emm * 26 + 16 + j1] + G1[3328 + emm * 26 + 16 + j1] + bh1[2 * H + er1];
                    float rr = sigm(ir + hr);
                    float zz = sigm(iz + hz);
                    float nn = tanhf(inn + rr * hn);
                    hnB = (1.0f - zz) * nn + zz * hpB;
                }
                hpA = hnA; hpB = hnB;
                f16 hiA, loA, hiB, loB;
                split_h(hnA, hiA, loA);
                split_h(hnB, hiB, loB);
                Hn[eidx]         = pack2h(hiA, hiB);
                Hn[16384 + eidx] = pack2h(loA, loB);
                *(float2*)&out[(size_t)emm * (S * 2 * H) + (size_t)tt * (2 * H) + dir * H + er0] =
                    make_float2(hnA, hnB);
                if (p == S) {
                    g_h1f[0][dir][emm * H + er0]     = hnA;
                    g_h1f[0][dir][emm * H + er0 + 1] = hnB;
                }
            }
        }

        grid_bar(dir, (unsigned)(p + 1));
    }

    // ---- final hidden state copy (own dir; parity 0) ----
#pragma unroll
    for (int it = 0; it < 2; it++) {
        int local = (bid & 63) * 1024 + it * 512 + tid;   // < 65536 per dir
        int lyr = local >> 15;
        int rem = local & 32767;
        int b = rem >> 9;
        int n = rem & 511;
        float v = lyr ? __ldcg(&g_h1f[0][dir][b * H + n]) : __ldcg(&g_h0f[0][dir][b * H + n]);
        out[(size_t)B * S * 2 * H + ((size_t)lyr * B + b) * (2 * H) + dir * H + n] = v;
    }
}

// ---------------- launch ----------------
extern "C" void kernel_launch(void* const* d_in, const int* in_sizes, int n_in,
                              void* d_out, int out_size) {
    const float* input  = (const float*)d_in[0];
    const float* enc    = (const float*)d_in[1];
    const float* Wih_f  = (const float*)d_in[2];
    const float* Whh_f  = (const float*)d_in[3];
    const float* bih_f  = (const float*)d_in[4];
    const float* bhh_f  = (const float*)d_in[5];
    const float* Wih_b  = (const float*)d_in[6];
    const float* Whh_b  = (const float*)d_in[7];
    const float* bih_b  = (const float*)d_in[8];
    const float* bhh_b  = (const float*)d_in[9];
    float* out = (float*)d_out;

    const int SMEM_G = 55296;
    const int SMEM_P = 122112;
    static int configured = 0;
    if (!configured) {
        cudaFuncSetAttribute(gemm_gi0, cudaFuncAttributeMaxDynamicSharedMemorySize, SMEM_G);
        cudaFuncSetAttribute(gru_persist, cudaFuncAttributeMaxDynamicSharedMemorySize, SMEM_P);
        configured = 1;
    }

    conv_xw<<<17920, 256>>>(input, Wih_f, Wih_b);
    init_h<<<512, 256>>>(enc);
    gemm_gi0<<<dim3(S, 24, 2), 256, SMEM_G>>>(bih_f, bih_b);
    gru_persist<<<NBLK, 512, SMEM_P>>>(Wih_f, Wih_b, Whh_f, Whh_b,
                                       bih_f, bih_b, bhh_f, bhh_b, out);
}

// round 17
// speedup vs baseline: 2.6458x; 1.1636x over previous
#include <cuda_runtime.h>
#include <cuda_fp16.h>
#include <math.h>

#define S 512
#define B 64
#define H 512
#define D 512
#define G3 1536
#define NBLK 128

typedef unsigned u32;
typedef unsigned long long ull;
typedef __half f16;

// ---------------- device-global scratch (allocation-free rule) ----------------
__device__ float g_gi0[(size_t)2 * S * B * G3];          // fp32 gi0 [dir][t][b][3H]
__device__ f16   g_xp[2][(size_t)B * S * D];             // input hi/lo planes (planar fp16)
__device__ f16   g_wp[2][(size_t)G3 * D];                // Wih layer0 [dir] single fp16 plane
__device__ float g_h0f[2][2][B * H];                     // [parity][dir]
__device__ float g_h1f[2][2][B * H];
// unified h planes (fp16 single-plane), mma-frag layout: sel = layer*4 + parity*2 + dir
__device__ u32   g_hp[8][16384];
__device__ unsigned g_arrive2[2];

// ---------------- helpers ----------------
__device__ __forceinline__ void split_h(float v, f16& hi, f16& lo) {
    hi = __float2half(v);
    lo = __float2half(v - __half2float(hi));
}
__device__ __forceinline__ u32 pack2h(f16 a, f16 b) {
    return (u32)__half_as_ushort(a) | ((u32)__half_as_ushort(b) << 16);
}
__device__ __forceinline__ float sigm(float x) { return 1.0f / (1.0f + expf(-x)); }

// byte offset of h value (batch b, hidden k) inside a frag-layout plane
__device__ __forceinline__ int frag_byte(int b, int k) {
    int kblk = k >> 4, c = k & 15, mt = b >> 4, r = b & 15;
    int lane = (r & 7) * 4 + ((c & 7) >> 1);
    int reg  = (r >> 3) + 2 * (c >> 3);
    return ((kblk * 512 + mt * 128 + lane * 4 + reg) << 2) + ((c & 1) << 1);
}

__device__ __forceinline__ void mma16816(float* d, const u32* a, u32 b0, u32 b1) {
    asm volatile("mma.sync.aligned.m16n8k16.row.col.f32.f16.f16.f32 "
                 "{%0,%1,%2,%3},{%4,%5,%6,%7},{%8,%9},{%0,%1,%2,%3};"
                 : "+f"(d[0]), "+f"(d[1]), "+f"(d[2]), "+f"(d[3])
                 : "r"(a[0]), "r"(a[1]), "r"(a[2]), "r"(a[3]), "r"(b0), "r"(b1));
}
__device__ __forceinline__ void ldm4(u32* r, const void* p) {
    u32 s = (u32)__cvta_generic_to_shared(p);
    asm volatile("ldmatrix.sync.aligned.m8n8.x4.shared.b16 {%0,%1,%2,%3},[%4];"
                 : "=r"(r[0]), "=r"(r[1]), "=r"(r[2]), "=r"(r[3]) : "r"(s));
}
__device__ __forceinline__ void cp16(void* smem_dst, const void* gsrc) {
    u32 s = (u32)__cvta_generic_to_shared(smem_dst);
    asm volatile("cp.async.cg.shared.global [%0], [%1], 16;" :: "r"(s), "l"(gsrc));
}

// ---------------- conv_xw: input -> fp16 hi/lo planes; Wih0 -> single fp16 plane ----------------
__global__ void conv_xw(const float* __restrict__ x,
                        const float* __restrict__ wf, const float* __restrict__ wb) {
    if (blockIdx.x < 16384) {
        size_t i = ((size_t)blockIdx.x * 256 + threadIdx.x) * 4;
        float4 v = *(const float4*)&x[i];
        f16 h0, l0, h1, l1, h2, l2, h3, l3;
        split_h(v.x, h0, l0); split_h(v.y, h1, l1);
        split_h(v.z, h2, l2); split_h(v.w, h3, l3);
        u32* ph = (u32*)&g_xp[0][i];
        u32* pl = (u32*)&g_xp[1][i];
        ph[0] = pack2h(h0, h1); ph[1] = pack2h(h2, h3);
        pl[0] = pack2h(l0, l1); pl[1] = pack2h(l2, l3);
    } else {
        size_t j = ((size_t)(blockIdx.x - 16384) * 256 + threadIdx.x) * 4;
        int d = j >= (size_t)G3 * D;
        size_t off = d ? j - (size_t)G3 * D : j;
        const float* src = d ? wb : wf;
        float4 v = *(const float4*)&src[off];
        u32* ph = (u32*)&g_wp[d][off];
        ph[0] = pack2h(__float2half(v.x), __float2half(v.y));
        ph[1] = pack2h(__float2half(v.z), __float2half(v.w));
    }
}

// ---------------- init: hidden states (fp32 + frag plane) + barrier reset ----------------
__global__ void init_h(const float* __restrict__ enc) {
    if (blockIdx.x == 0 && threadIdx.x < 2) {
        g_arrive2[threadIdx.x] = 0;
    }
    int idx = blockIdx.x * blockDim.x + threadIdx.x;   // 131072
    int layer = idx >> 16;
    int rem = idx & 65535;
    int dir = rem >> 15;
    int rem2 = rem & 32767;
    int b = rem2 >> 9;
    int n = rem2 & 511;
    float v = enc[(layer * B + b) * (2 * H) + dir * H + n];
    int off = frag_byte(b, n);
    int sel = layer * 4 + dir;                 // parity 0
    if (layer == 0) g_h0f[0][dir][b * H + n] = v;
    else            g_h1f[0][dir][b * H + n] = v;
    *(f16*)((char*)g_hp[sel] + off) = __float2half(v);
}

// ---------------- gi0 = input @ Wih0^T + bih0, smem-staged fp16 2-product mma ----------------
// grid (S, 24, 2), 256 thr. smem 55296 -> 4 blocks/SM.
__global__ void __launch_bounds__(256, 4)
gemm_gi0(const float* __restrict__ bf_, const float* __restrict__ bb_) {
    extern __shared__ char sm2[];
    char* Wbuf0 = sm2;                 // 1 plane x [64][72 f16] = 9216
    char* Wbuf1 = sm2 + 9216;
    char* Xbuf0 = sm2 + 18432;         // 2 planes x [64][72 f16] = 18432
    char* Xbuf1 = sm2 + 36864;

    int s  = blockIdx.x;
    int nb = blockIdx.y;
    int d  = blockIdx.z;
    const float* bias = d ? bb_ : bf_;

    int tid = threadIdx.x;
    int w = tid >> 5, l = tid & 31;
    int mtile = w & 3, m0 = mtile * 16, nh = w >> 2;

    const char* wsrc = (const char*)&g_wp[d][(size_t)(nb * 64) * D];
    const char* xsrc[2] = { (const char*)&g_xp[0][0], (const char*)&g_xp[1][0] };

    float acc[4][4];
#pragma unroll
    for (int nt = 0; nt < 4; nt++) { acc[nt][0] = acc[nt][1] = acc[nt][2] = acc[nt][3] = 0.f; }

    auto stage = [&](int c, char* Wb, char* Xb) {
#pragma unroll
        for (int i = 0; i < 2; i++) {
            int idx = i * 256 + tid;              // < 512
            int row = idx >> 3, seg = idx & 7;
            cp16(Wb + row * 144 + seg * 16,
                 wsrc + (size_t)row * 1024 + c * 128 + seg * 16);
        }
#pragma unroll
        for (int i = 0; i < 4; i++) {
            int idx = i * 256 + tid;              // < 1024
            int pl = idx >> 9, row = (idx >> 3) & 63, seg = idx & 7;
            cp16(Xb + pl * 9216 + row * 144 + seg * 16,
                 xsrc[pl] + (size_t)row * 524288 + (size_t)s * 1024 + c * 128 + seg * 16);
        }
        asm volatile("cp.async.commit_group;");
    };

    stage(0, Wbuf0, Xbuf0);

    for (int c = 0; c < 8; c++) {
        asm volatile("cp.async.wait_group 0;");
        __syncthreads();
        if (c < 7) stage(c + 1, (c & 1) ? Wbuf0 : Wbuf1, (c & 1) ? Xbuf0 : Xbuf1);
        char* Wb = (c & 1) ? Wbuf1 : Wbuf0;
        char* Xb = (c & 1) ? Xbuf1 : Xbuf0;
#pragma unroll
        for (int kl = 0; kl < 4; kl++) {
            u32 ah[4], al[4];
            int aoff = (m0 + (l & 15)) * 144 + kl * 32 + (l >> 4) * 16;
            ldm4(ah, Xb + aoff);
            ldm4(al, Xb + 9216 + aoff);
            const u32* Wh = (const u32*)Wb;
#pragma unroll
            for (int nt = 0; nt < 4; nt++) {
                int nrow = nh * 32 + nt * 8 + (l >> 2);
                int wi = nrow * 36 + kl * 8 + (l & 3);
                u32 bh0 = Wh[wi], bh1 = Wh[wi + 4];
                mma16816(acc[nt], ah, bh0, bh1);
                mma16816(acc[nt], al, bh0, bh1);
            }
        }
    }

#pragma unroll
    for (int nt = 0; nt < 4; nt++) {
        int col = nb * 64 + nh * 32 + nt * 8 + 2 * (l & 3);
        float2 bi = *(const float2*)&bias[col];
        int b0 = m0 + (l >> 2);
        float2 v0 = make_float2(acc[nt][0] + bi.x, acc[nt][1] + bi.y);
        float2 v1 = make_float2(acc[nt][2] + bi.x, acc[nt][3] + bi.y);
        *(float2*)&g_gi0[(((size_t)d * S + s) * B + b0) * G3 + col] = v0;
        *(float2*)&g_gi0[(((size_t)d * S + s) * B + b0 + 8) * G3 + col] = v1;
    }
}

// ---------------- per-dir grid barrier v3: release-red arrive + counter poll ----------------
__device__ __forceinline__ void grid_bar(int dir, unsigned target) {
    __syncthreads();
    if (threadIdx.x == 0) {
        asm volatile("red.release.gpu.global.add.u32 [%0], 1;"
                     :: "l"(&g_arrive2[dir]) : "memory");
        unsigned r;
        do {
            asm volatile("ld.acquire.gpu.u32 %0, [%1];" : "=r"(r) : "l"(&g_arrive2[dir]) : "memory");
        } while (r < target * 64u);
    }
    __syncthreads();
}

// ---------------- persistent recurrence kernel (fp16, single-plane activations) ----------------
// grid 128 (2 dir x 64 hgroups of 8), 512 thr = 16 warps (mtile x4, ksub x4).
// smem: WS 76032 | G0 19968 | G1 19968 | GI0S 6144 = 122112 B
__global__ void __launch_bounds__(512, 1)
gru_persist(const float* __restrict__ Wih_f, const float* __restrict__ Wih_b,
            const float* __restrict__ Whh_f, const float* __restrict__ Whh_b,
            const float* __restrict__ bih_f, const float* __restrict__ bih_b,
            const float* __restrict__ bhh_f, const float* __restrict__ bhh_b,
            float* __restrict__ out) {
    extern __shared__ char smem[];
    u32*  WS    = (u32*)smem;                    // [mat*24 + n][264] single fp16 plane
    float* G0   = (float*)(smem + 76032);        // partials ksub{0,1}
    float* G1   = (float*)(smem + 96000);        // partials ksub{2,3}
    float* GI0S = (float*)(smem + 115968);       // [64][24]

    const int tid = threadIdx.x;
    const int bid = blockIdx.x;
    const int dir = bid >> 6;
    const int hb  = (bid & 63) * 8;
    const int w = tid >> 5, l = tid & 31;
    const int mtile = w & 3, m0 = mtile * 16, ksub = w >> 2;

    const float* Wih = dir ? Wih_b : Wih_f;
    const float* Whh = dir ? Whh_b : Whh_f;
    const float* bih = dir ? bih_b : bih_f;
    const float* bhh = dir ? bhh_b : bhh_f;
    const float* bhh0 = bhh;
    const float* bi1 = bih + G3;
    const float* bh1 = bhh + G3;

    // ---- one-time weight staging: single fp16 plane, (k,k+8)-interleaved u32 pairs ----
    {
        const float* Wmat[3] = { Whh, Wih + (size_t)G3 * D, Whh + (size_t)G3 * H };
#pragma unroll 4
        for (int i = 0; i < 36; i++) {
            int item = tid + 512 * i;            // < 18432
            int m3 = item / 6144;
            int rem = item - m3 * 6144;
            int n = rem >> 8;
            int k2 = rem & 255;
            int grow = (n >> 3) * H + hb + (n & 7);
            float2 v = *(const float2*)(Wmat[m3] + (size_t)grow * 512 + 2 * k2);
            int j = k2 & 7;
            int col = ((k2 >> 3) << 3) + ((j & 3) << 1) + (j >> 2);
            WS[(m3 * 24 + n) * 264 + col] = pack2h(__float2half(v.x), __float2half(v.y));
        }
    }

    // ---- epilogue ownership: half 0 -> L0, half 1 -> L1; row pair (r0, r0+1) ----
    const int half = tid >> 8;
    const int emm  = tid & 63;
    const int q    = (tid >> 6) & 3;
    const int j0   = 2 * q;
    const int er0  = hb + j0;
    float hpA, hpB;
    if (half == 0) {
        hpA = g_h0f[0][dir][emm * H + er0];
        hpB = g_h0f[0][dir][emm * H + er0 + 1];
    } else {
        hpA = g_h1f[0][dir][emm * H + er0];
        hpB = g_h1f[0][dir][emm * H + er0 + 1];
    }
    const int eidx = frag_byte(emm, er0) >> 2;   // u32 index shared by the row pair

    const int rowoff = (l >> 2) * 264 + 2 * (l & 3) + ksub * 8;
    const int fbase  = mtile * 128 + l * 4;

    for (int p = 0; p <= S; p++) {
        const u32* Xb = g_hp[(p & 1) * 2 + dir];            // layer0 plane
        const u32* Hb = g_hp[4 + ((p + 1) & 1) * 2 + dir];  // layer1 plane

        // gi0 prefetch (used in L0 epilogue)
        if (p < S) {
            int tt0 = dir ? (S - 1 - p) : p;
            const float* gi = &g_gi0[((size_t)dir * S + tt0) * B * G3];
            if (tid < 384) {
                int mm = tid / 6, r = tid % 6;
                int gate = r >> 1, hf = r & 1;
                cp16(&GI0S[mm * 24 + gate * 8 + hf * 4],
                     gi + mm * G3 + gate * H + hb + hf * 4);
            }
            asm volatile("cp.async.commit_group;");
        }

        float acc[3][3][4];
#pragma unroll
        for (int m3 = 0; m3 < 3; m3++)
#pragma unroll
            for (int nt = 0; nt < 3; nt++)
                acc[m3][nt][0] = acc[m3][nt][1] = acc[m3][nt][2] = acc[m3][nt][3] = 0.f;

        u32 f0[2][4], f1[2][4];
        {
            int idx = ksub * 512 + fbase;
            uint4 v;
            v = __ldcg((const uint4*)(Xb + idx));
            f0[0][0] = v.x; f0[0][1] = v.y; f0[0][2] = v.z; f0[0][3] = v.w;
            v = __ldcg((const uint4*)(Hb + idx));
            f0[1][0] = v.x; f0[1][1] = v.y; f0[1][2] = v.z; f0[1][3] = v.w;
        }

#pragma unroll
        for (int c = 0; c < 8; c++) {
            if (c < 7) {
                int idx = ((c + 1) * 4 + ksub) * 512 + fbase;
                u32 (*Fn)[4] = (c & 1) ? f0 : f1;
                uint4 v;
                v = __ldcg((const uint4*)(Xb + idx));
                Fn[0][0] = v.x; Fn[0][1] = v.y; Fn[0][2] = v.z; Fn[0][3] = v.w;
                v = __ldcg((const uint4*)(Hb + idx));
                Fn[1][0] = v.x; Fn[1][1] = v.y; Fn[1][2] = v.z; Fn[1][3] = v.w;
            }
            u32 (*Af)[4] = (c & 1) ? f1 : f0;
            const int cb = rowoff + c * 32;
#pragma unroll
            for (int m3 = 0; m3 < 3; m3++) {
                const u32* A = (m3 == 2) ? Af[1] : Af[0];
                const u32* WH = WS + m3 * 24 * 264 + cb;
#pragma unroll
                for (int nt = 0; nt < 3; nt++) {
                    ull wh64 = *(const ull*)(WH + nt * 8 * 264);
                    u32 bh0 = (u32)wh64, bh1 = (u32)(wh64 >> 32);
                    mma16816(acc[m3][nt], A, bh0, bh1);
                }
            }
        }

        // gi0 cp.async settled before the reduction barriers
        asm volatile("cp.async.wait_group 0;");

        // ---- pairwise K-split reduction: ksub{0,2} write, ksub{1,3} accumulate ----
        {
            float* Gb = (ksub & 2) ? G1 : G0;
            if ((ksub & 1) == 0) {
#pragma unroll
                for (int m3 = 0; m3 < 3; m3++) {
                    float* G = Gb + m3 * 1664;
#pragma unroll
                    for (int nt = 0; nt < 3; nt++) {
                        int col = nt * 8 + 2 * (l & 3);
                        int r0 = m0 + (l >> 2);
                        *(float2*)&G[r0 * 26 + col] =
                            make_float2(acc[m3][nt][0], acc[m3][nt][1]);
                        *(float2*)&G[(r0 + 8) * 26 + col] =
                            make_float2(acc[m3][nt][2], acc[m3][nt][3]);
                    }
                }
            }
            __syncthreads();
            if (ksub & 1) {
#pragma unroll
                for (int m3 = 0; m3 < 3; m3++) {
                    float* G = Gb + m3 * 1664;
#pragma unroll
                    for (int nt = 0; nt < 3; nt++) {
                        int col = nt * 8 + 2 * (l & 3);
                        int r0 = m0 + (l >> 2);
                        float2* p0 = (float2*)&G[r0 * 26 + col];
                        float2* p1 = (float2*)&G[(r0 + 8) * 26 + col];
                        float2 o0 = *p0, o1 = *p1;
                        *p0 = make_float2(o0.x + acc[m3][nt][0], o0.y + acc[m3][nt][1]);
                        *p1 = make_float2(o1.x + acc[m3][nt][2], o1.y + acc[m3][nt][3]);
                    }
                }
            }
            __syncthreads();
        }

        if (half == 0) {
            // ---- L0 epilogue: t = p (row pair er0, er0+1) ----
            if (p < S) {
                u32* Xn = g_hp[((p + 1) & 1) * 2 + dir];
                float hnA, hnB;
                {
                    float hr = G0[emm * 26 + j0]      + G1[emm * 26 + j0]      + bhh0[er0];
                    float hz = G0[emm * 26 + 8 + j0]  + G1[emm * 26 + 8 + j0]  + bhh0[H + er0];
                    float hn = G0[emm * 26 + 16 + j0] + G1[emm * 26 + 16 + j0] + bhh0[2 * H + er0];
                    float rr = sigm(GI0S[emm * 24 + j0] + hr);
                    float zz = sigm(GI0S[emm * 24 + 8 + j0] + hz);
                    float nn = tanhf(GI0S[emm * 24 + 16 + j0] + rr * hn);
                    hnA = (1.0f - zz) * nn + zz * hpA;
                }
                {
                    int j1 = j0 + 1, er1 = er0 + 1;
                    float hr = G0[emm * 26 + j1]      + G1[emm * 26 + j1]      + bhh0[er1];
                    float hz = G0[emm * 26 + 8 + j1]  + G1[emm * 26 + 8 + j1]  + bhh0[H + er1];
                    float hn = G0[emm * 26 + 16 + j1] + G1[emm * 26 + 16 + j1] + bhh0[2 * H + er1];
                    float rr = sigm(GI0S[emm * 24 + j1] + hr);
                    float zz = sigm(GI0S[emm * 24 + 8 + j1] + hz);
                    float nn = tanhf(GI0S[emm * 24 + 16 + j1] + rr * hn);
                    hnB = (1.0f - zz) * nn + zz * hpB;
                }
                hpA = hnA; hpB = hnB;
                Xn[eidx] = pack2h(__float2half(hnA), __float2half(hnB));
                if (p == S - 1) {
                    g_h0f[0][dir][emm * H + er0]     = hnA;
                    g_h0f[0][dir][emm * H + er0 + 1] = hnB;
                }
            }
        } else {
            // ---- L1 epilogue: t = p-1 ----
            if (p >= 1) {
                int t1 = p - 1;
                int tt = dir ? (S - 1 - t1) : t1;
                u32* Hn = g_hp[4 + (p & 1) * 2 + dir];
                float hnA, hnB;
                {
                    float ir  = G0[1664 + emm * 26 + j0]      + G1[1664 + emm * 26 + j0]      + bi1[er0];
                    float iz  = G0[1664 + emm * 26 + 8 + j0]  + G1[1664 + emm * 26 + 8 + j0]  + bi1[H + er0];
                    float inn = G0[1664 + emm * 26 + 16 + j0] + G1[1664 + emm * 26 + 16 + j0] + bi1[2 * H + er0];
                    float hr  = G0[3328 + emm * 26 + j0]      + G1[3328 + emm * 26 + j0]      + bh1[er0];
                    float hz  = G0[3328 + emm * 26 + 8 + j0]  + G1[3328 + emm * 26 + 8 + j0]  + bh1[H + er0];
                    float hn  = G0[3328 + emm * 26 + 16 + j0] + G1[3328 + emm * 26 + 16 + j0] + bh1[2 * H + er0];
                    float rr = sigm(ir + hr);
                    float zz = sigm(iz + hz);
                    float nn = tanhf(inn + rr * hn);
                    hnA = (1.0f - zz) * nn + zz * hpA;
                }
                {
                    int j1 = j0 + 1, er1 = er0 + 1;
                    float ir  = G0[1664 + emm * 26 + j1]      + G1[1664 + emm * 26 + j1]      + bi1[er1];
                    float iz  = G0[1664 + emm * 26 + 8 + j1]  + G1[1664 + emm * 26 + 8 + j1]  + bi1[H + er1];
                    float inn = G0[1664 + emm * 26 + 16 + j1] + G1[1664 + emm * 26 + 16 + j1] + bi1[2 * H + er1];
                    float hr  = G0[3328 + emm * 26 + j1]      + G1[3328 + emm * 26 + j1]      + bh1[er1];
                    float hz  = G0[3328 + emm * 26 + 8 + j1]  + G1[3328 + emm * 26 + 8 + j1]  + bh1[H + er1];
                    float hn  = G0[3328 + emm * 26 + 16 + j1] + G1[3328 + emm * 26 + 16 + j1] + bh1[2 * H + er1];
                    float rr = sigm(ir + hr);
                    float zz = sigm(iz + hz);
                    float nn = tanhf(inn + rr * hn);
                    hnB = (1.0f - zz) * nn + zz * hpB;
                }
                hpA = hnA; hpB = hnB;
                Hn[eidx] = pack2h(__float2half(hnA), __float2half(hnB));
                *(float2*)&out[(size_t)emm * (S * 2 * H) + (size_t)tt * (2 * H) + dir * H + er0] =
                    make_float2(hnA, hnB);
                if (p == S) {
                    g_h1f[0][dir][emm * H + er0]     = hnA;
                    g_h1f[0][dir][emm * H + er0 + 1] = hnB;
                }
            }
        }

        grid_bar(dir, (unsigned)(p + 1));
    }

    // ---- final hidden state copy (own dir; parity 0) ----
#pragma unroll
    for (int it = 0; it < 2; it++) {
        int local = (bid & 63) * 1024 + it * 512 + tid;   // < 65536 per dir
        int lyr = local >> 15;
        int rem = local & 32767;
        int b = rem >> 9;
        int n = rem & 511;
        float v = lyr ? __ldcg(&g_h1f[0][dir][b * H + n]) : __ldcg(&g_h0f[0][dir][b * H + n]);
        out[(size_t)B * S * 2 * H + ((size_t)lyr * B + b) * (2 * H) + dir * H + n] = v;
    }
}

// ---------------- launch ----------------
extern "C" void kernel_launch(void* const* d_in, const int* in_sizes, int n_in,
                              void* d_out, int out_size) {
    const float* input  = (const float*)d_in[0];
    const float* enc    = (const float*)d_in[1];
    const float* Wih_f  = (const float*)d_in[2];
    const float* Whh_f  = (const float*)d_in[3];
    const float* bih_f  = (const float*)d_in[4];
    const float* bhh_f  = (const float*)d_in[5];
    const float* Wih_b  = (const float*)d_in[6];
    const float* Whh_b  = (const float*)d_in[7];
    const float* bih_b  = (const float*)d_in[8];
    const float* bhh_b  = (const float*)d_in[9];
    float* out = (float*)d_out;

    const int SMEM_G = 55296;
    const int SMEM_P = 122112;
    static int configured = 0;
    if (!configured) {
        cudaFuncSetAttribute(gemm_gi0, cudaFuncAttributeMaxDynamicSharedMemorySize, SMEM_G);
        cudaFuncSetAttribute(gru_persist, cudaFuncAttributeMaxDynamicSharedMemorySize, SMEM_P);
        configured = 1;
    }

    conv_xw<<<17920, 256>>>(input, Wih_f, Wih_b);
    init_h<<<512, 256>>>(enc);
    gemm_gi0<<<dim3(S, 24, 2), 256, SMEM_G>>>(bih_f, bih_b);
    gru_persist<<<NBLK, 512, SMEM_P>>>(Wih_f, Wih_b, Whh_f, Whh_b,
                                       bih_f, bih_b, bhh_f, bhh_b, out);
}